// round 1
// baseline (speedup 1.0000x reference)
#include <cuda_runtime.h>
#include <math.h>

#define BSZ   4
#define NSEQ  4096
#define DIM   1024
#define TOPK  8
#define MROWS (BSZ * NSEQ)

// ---------------- scratch (__device__ globals; no allocation allowed) -------
__device__ float g_q[(size_t)MROWS * DIM];
__device__ float g_k[(size_t)MROWS * DIM];
__device__ float g_v[(size_t)MROWS * DIM];
__device__ float g_attn[(size_t)MROWS * DIM];
__device__ float g_probs[(size_t)MROWS * TOPK];
__device__ int   g_topidx[(size_t)MROWS * TOPK];

// ---------------- GEMM: C[M,1024] = A[M,1024] @ W[1024,1024] + bias ---------
// 128x128 block tile, BK=8, 256 threads, 8x8 per thread.
__global__ __launch_bounds__(256) void gemm_bias_kernel(
    const float* __restrict__ A, const float* __restrict__ W,
    const float* __restrict__ bias, float* __restrict__ C) {
    __shared__ float As[8][128];
    __shared__ float Bs[8][128];

    const int tid = threadIdx.x;
    const int tx = tid & 15;       // 0..15 -> N
    const int ty = tid >> 4;       // 0..15 -> M
    const int row0 = blockIdx.y * 128;
    const int col0 = blockIdx.x * 128;

    float acc[8][8];
#pragma unroll
    for (int i = 0; i < 8; i++)
#pragma unroll
        for (int j = 0; j < 8; j++) acc[i][j] = 0.f;

    const int a_row = tid >> 1;          // 0..127
    const int a_col = (tid & 1) * 4;     // 0 or 4
    const int b_row = tid >> 5;          // 0..7
    const int b_col = (tid & 31) * 4;    // 0..124

    const float* Aptr = A + (size_t)(row0 + a_row) * DIM + a_col;
    const float* Bptr = W + (size_t)b_row * DIM + col0 + b_col;

    for (int k0 = 0; k0 < DIM; k0 += 8) {
        float4 av = *(const float4*)(Aptr + k0);
        As[a_col + 0][a_row] = av.x;
        As[a_col + 1][a_row] = av.y;
        As[a_col + 2][a_row] = av.z;
        As[a_col + 3][a_row] = av.w;
        *(float4*)&Bs[b_row][b_col] = *(const float4*)(Bptr + (size_t)k0 * DIM);
        __syncthreads();
#pragma unroll
        for (int kk = 0; kk < 8; kk++) {
            float4 ra0 = *(const float4*)&As[kk][ty * 8];
            float4 ra1 = *(const float4*)&As[kk][ty * 8 + 4];
            float4 rb0 = *(const float4*)&Bs[kk][tx * 8];
            float4 rb1 = *(const float4*)&Bs[kk][tx * 8 + 4];
            float ra[8] = {ra0.x, ra0.y, ra0.z, ra0.w, ra1.x, ra1.y, ra1.z, ra1.w};
            float rb[8] = {rb0.x, rb0.y, rb0.z, rb0.w, rb1.x, rb1.y, rb1.z, rb1.w};
#pragma unroll
            for (int i = 0; i < 8; i++)
#pragma unroll
                for (int j = 0; j < 8; j++) acc[i][j] += ra[i] * rb[j];
        }
        __syncthreads();
    }

#pragma unroll
    for (int i = 0; i < 8; i++) {
        const int r = row0 + ty * 8 + i;
        float* Crow = C + (size_t)r * DIM + col0 + tx * 8;
#pragma unroll
        for (int j = 0; j < 8; j += 4) {
            float4 o;
            o.x = acc[i][j + 0] + bias[col0 + tx * 8 + j + 0];
            o.y = acc[i][j + 1] + bias[col0 + tx * 8 + j + 1];
            o.z = acc[i][j + 2] + bias[col0 + tx * 8 + j + 2];
            o.w = acc[i][j + 3] + bias[col0 + tx * 8 + j + 3];
            *(float4*)(Crow + j) = o;
        }
    }
}

// ---------------- causal scores + streaming top-8 + softmax -----------------
// Block handles query tiles qt = pair and 63-pair (65 key tiles total -> balanced).
// 64x64 score tile, D chunks of 16, 256 threads (16x16, 4x4 per thread).
__global__ __launch_bounds__(256) void scores_topk_kernel(
    const float* __restrict__ q, const float* __restrict__ k,
    float* __restrict__ probs, int* __restrict__ idxs) {
    __shared__ float qs[16][68];
    __shared__ float ks[16][68];
    __shared__ float sc[64][65];
    __shared__ float tval[64][TOPK];
    __shared__ int   tidx[64][TOPK];

    const int tid = threadIdx.x;
    const int tx = tid & 15;
    const int ty = tid >> 4;
    const int b = blockIdx.y;
    const int pair = blockIdx.x;  // 0..31

    const float* qb = q + (size_t)b * NSEQ * DIM;
    const float* kb = k + (size_t)b * NSEQ * DIM;

    const int lr = tid >> 2;         // 0..63
    const int lc = (tid & 3) * 4;    // 0,4,8,12

    for (int s = 0; s < 2; s++) {
        const int qt = (s == 0) ? pair : (63 - pair);
        const int q0 = qt * 64;

        for (int i = tid; i < 64 * TOPK; i += 256) {
            tval[i >> 3][i & 7] = -INFINITY;
            tidx[i >> 3][i & 7] = 0;
        }
        __syncthreads();

        for (int kt = 0; kt <= qt; kt++) {
            const int k0 = kt * 64;
            float acc[4][4];
#pragma unroll
            for (int i = 0; i < 4; i++)
#pragma unroll
                for (int j = 0; j < 4; j++) acc[i][j] = 0.f;

            for (int dc = 0; dc < DIM; dc += 16) {
                float4 qv = *(const float4*)(qb + (size_t)(q0 + lr) * DIM + dc + lc);
                float4 kv = *(const float4*)(kb + (size_t)(k0 + lr) * DIM + dc + lc);
                qs[lc + 0][lr] = qv.x; qs[lc + 1][lr] = qv.y;
                qs[lc + 2][lr] = qv.z; qs[lc + 3][lr] = qv.w;
                ks[lc + 0][lr] = kv.x; ks[lc + 1][lr] = kv.y;
                ks[lc + 2][lr] = kv.z; ks[lc + 3][lr] = kv.w;
                __syncthreads();
#pragma unroll
                for (int dd = 0; dd < 16; dd++) {
                    float4 rq = *(const float4*)&qs[dd][ty * 4];
                    float4 rk = *(const float4*)&ks[dd][tx * 4];
                    float aq[4] = {rq.x, rq.y, rq.z, rq.w};
                    float ak[4] = {rk.x, rk.y, rk.z, rk.w};
#pragma unroll
                    for (int i = 0; i < 4; i++)
#pragma unroll
                        for (int j = 0; j < 4; j++) acc[i][j] += aq[i] * ak[j];
                }
                __syncthreads();
            }
            // scale + causal mask + stage tile
#pragma unroll
            for (int i = 0; i < 4; i++) {
                const int rr = ty * 4 + i;
#pragma unroll
                for (int j = 0; j < 4; j++) {
                    const int cc = tx * 4 + j;
                    float v = acc[i][j] * 0.03125f;  // 1/sqrt(1024)
                    if (k0 + cc > q0 + rr) v = -INFINITY;
                    sc[rr][cc] = v;
                }
            }
            __syncthreads();
            // running top-8 merge: one thread per row
            if (tid < 64) {
                float tv[TOPK]; int ti[TOPK];
#pragma unroll
                for (int j = 0; j < TOPK; j++) { tv[j] = tval[tid][j]; ti[j] = tidx[tid][j]; }
                float vmin = tv[0]; int mpos = 0;
#pragma unroll
                for (int j = 1; j < TOPK; j++) if (tv[j] < vmin) { vmin = tv[j]; mpos = j; }
                for (int c = 0; c < 64; c++) {
                    const float vv = sc[tid][c];
                    if (vv > vmin) {
                        tv[mpos] = vv; ti[mpos] = k0 + c;
                        vmin = tv[0]; mpos = 0;
#pragma unroll
                        for (int j = 1; j < TOPK; j++) if (tv[j] < vmin) { vmin = tv[j]; mpos = j; }
                    }
                }
#pragma unroll
                for (int j = 0; j < TOPK; j++) { tval[tid][j] = tv[j]; tidx[tid][j] = ti[j]; }
            }
            __syncthreads();
        }

        // softmax over top-8 (rows with <8 valid keys keep -inf -> weight 0)
        if (tid < 64) {
            float tv[TOPK]; int ti[TOPK];
#pragma unroll
            for (int j = 0; j < TOPK; j++) { tv[j] = tval[tid][j]; ti[j] = tidx[tid][j]; }
            float m = tv[0];
#pragma unroll
            for (int j = 1; j < TOPK; j++) m = fmaxf(m, tv[j]);
            float e[TOPK]; float ssum = 0.f;
#pragma unroll
            for (int j = 0; j < TOPK; j++) { e[j] = expf(tv[j] - m); ssum += e[j]; }
            const float inv = 1.f / ssum;
            const size_t base = ((size_t)b * NSEQ + q0 + tid) * TOPK;
#pragma unroll
            for (int j = 0; j < TOPK; j++) { probs[base + j] = e[j] * inv; idxs[base + j] = ti[j]; }
        }
        __syncthreads();
    }
}

// ---------------- sparse AV gather: out[n,:] = sum_j p_j * v[idx_j,:] -------
__global__ __launch_bounds__(128) void gather_kernel(
    const float* __restrict__ v, const float* __restrict__ probs,
    const int* __restrict__ idxs, float* __restrict__ out) {
    const int row = blockIdx.x;
    const int b = row >> 12;  // /4096
    const int tid = threadIdx.x;
    __shared__ float p[TOPK];
    __shared__ int   id[TOPK];
    if (tid < TOPK) {
        p[tid]  = probs[(size_t)row * TOPK + tid];
        id[tid] = idxs[(size_t)row * TOPK + tid];
    }
    __syncthreads();
    const float* vb = v + (size_t)b * NSEQ * DIM;
    const int c = tid * 8;
    float4 a0 = {0.f, 0.f, 0.f, 0.f}, a1 = {0.f, 0.f, 0.f, 0.f};
#pragma unroll
    for (int j = 0; j < TOPK; j++) {
        const float4* vr = (const float4*)(vb + (size_t)id[j] * DIM + c);
        const float pj = p[j];
        float4 v0 = vr[0], v1 = vr[1];
        a0.x += pj * v0.x; a0.y += pj * v0.y; a0.z += pj * v0.z; a0.w += pj * v0.w;
        a1.x += pj * v1.x; a1.y += pj * v1.y; a1.z += pj * v1.z; a1.w += pj * v1.w;
    }
    float4* orow = (float4*)(out + (size_t)row * DIM + c);
    orow[0] = a0; orow[1] = a1;
}

// ---------------- launch -----------------------------------------------------
extern "C" void kernel_launch(void* const* d_in, const int* in_sizes, int n_in,
                              void* d_out, int out_size) {
    const float* S  = (const float*)d_in[0];
    const float* Wq = (const float*)d_in[1];
    const float* bq = (const float*)d_in[2];
    const float* Wk = (const float*)d_in[3];
    const float* bk = (const float*)d_in[4];
    const float* Wv = (const float*)d_in[5];
    const float* bv = (const float*)d_in[6];
    const float* Wo = (const float*)d_in[7];
    const float* bo = (const float*)d_in[8];
    float* out = (float*)d_out;

    float *qp, *kp, *vp, *ap, *pp;
    int* ip;
    cudaGetSymbolAddress((void**)&qp, g_q);
    cudaGetSymbolAddress((void**)&kp, g_k);
    cudaGetSymbolAddress((void**)&vp, g_v);
    cudaGetSymbolAddress((void**)&ap, g_attn);
    cudaGetSymbolAddress((void**)&pp, g_probs);
    cudaGetSymbolAddress((void**)&ip, g_topidx);

    dim3 gemm_grid(DIM / 128, MROWS / 128);  // (8, 128)
    gemm_bias_kernel<<<gemm_grid, 256>>>(S, Wq, bq, qp);
    gemm_bias_kernel<<<gemm_grid, 256>>>(S, Wk, bk, kp);
    gemm_bias_kernel<<<gemm_grid, 256>>>(S, Wv, bv, vp);
    scores_topk_kernel<<<dim3(32, BSZ), 256>>>(qp, kp, pp, ip);
    gather_kernel<<<MROWS, 128>>>(vp, pp, ip, ap);
    gemm_bias_kernel<<<gemm_grid, 256>>>(ap, Wo, bo, out);
}

// round 2
// speedup vs baseline: 1.3436x; 1.3436x over previous
#include <cuda_runtime.h>
#include <math.h>

#define BSZ   4
#define NSEQ  4096
#define DIM   1024
#define TOPK  8
#define MROWS (BSZ * NSEQ)

typedef unsigned long long ULL;

// ---------------- scratch (__device__ globals; no allocation allowed) -------
__device__ float g_q[(size_t)MROWS * DIM];
__device__ float g_k[(size_t)MROWS * DIM];
__device__ float g_v[(size_t)MROWS * DIM];
__device__ float g_attn[(size_t)MROWS * DIM];
__device__ float g_probs[(size_t)MROWS * TOPK];
__device__ int   g_topidx[(size_t)MROWS * TOPK];
// partial top-8 per (row, key-half)
__device__ float g_pval[(size_t)MROWS * 2 * TOPK];
__device__ int   g_pidx[(size_t)MROWS * 2 * TOPK];

// ---------------- packed f32x2 helpers ---------------------------------------
__device__ __forceinline__ ULL dup2(float a) {
    ULL r;
    asm("mov.b64 %0, {%1, %1};" : "=l"(r) : "f"(a));
    return r;
}
__device__ __forceinline__ void fma2(ULL& d, ULL a, ULL b) {
    asm("fma.rn.f32x2 %0, %1, %2, %0;" : "+l"(d) : "l"(a), "l"(b));
}
__device__ __forceinline__ float2 unpack2(ULL x) {
    float2 r;
    asm("mov.b64 {%0, %1}, %2;" : "=f"(r.x), "=f"(r.y) : "l"(x));
    return r;
}

// ---------------- GEMM: C[M,1024] = A[M,1024] @ W[1024,1024] + bias ---------
// 128x128 tile, BK=8, 256 threads, 8x8 per thread via fma.rn.f32x2.
// Double-buffered smem + register prefetch, one __syncthreads per k-chunk.
__global__ __launch_bounds__(256, 2) void gemm_bias_kernel(
    const float* __restrict__ A, const float* __restrict__ W,
    const float* __restrict__ bias, float* __restrict__ C) {
    __shared__ float As[2][8][128];
    __shared__ float Bs[2][8][128];

    const int tid = threadIdx.x;
    const int tx = tid & 15;       // N
    const int ty = tid >> 4;       // M
    const int row0 = blockIdx.y * 128;
    const int col0 = blockIdx.x * 128;

    ULL acc2[8][4];
#pragma unroll
    for (int i = 0; i < 8; i++)
#pragma unroll
        for (int j = 0; j < 4; j++) acc2[i][j] = 0ull;

    const int a_row = tid >> 1;
    const int a_col = (tid & 1) * 4;
    const int b_row = tid >> 5;
    const int b_col = (tid & 31) * 4;

    const float* Aptr = A + (size_t)(row0 + a_row) * DIM + a_col;
    const float* Bptr = W + (size_t)b_row * DIM + col0 + b_col;

    float4 av = *(const float4*)(Aptr);
    float4 bv = *(const float4*)(Bptr);

    int p = 0;
    for (int k0 = 0; k0 < DIM; k0 += 8) {
        As[p][a_col + 0][a_row] = av.x;
        As[p][a_col + 1][a_row] = av.y;
        As[p][a_col + 2][a_row] = av.z;
        As[p][a_col + 3][a_row] = av.w;
        *(float4*)&Bs[p][b_row][b_col] = bv;
        __syncthreads();
        if (k0 + 8 < DIM) {
            av = *(const float4*)(Aptr + k0 + 8);
            bv = *(const float4*)(Bptr + (size_t)(k0 + 8) * DIM);
        }
#pragma unroll
        for (int kk = 0; kk < 8; kk++) {
            float4 ra0 = *(const float4*)&As[p][kk][ty * 8];
            float4 ra1 = *(const float4*)&As[p][kk][ty * 8 + 4];
            ULL b0 = *(const ULL*)&Bs[p][kk][tx * 8 + 0];
            ULL b1 = *(const ULL*)&Bs[p][kk][tx * 8 + 2];
            ULL b2 = *(const ULL*)&Bs[p][kk][tx * 8 + 4];
            ULL b3 = *(const ULL*)&Bs[p][kk][tx * 8 + 6];
            ULL a0 = dup2(ra0.x), a1 = dup2(ra0.y), a2 = dup2(ra0.z), a3 = dup2(ra0.w);
            ULL a4 = dup2(ra1.x), a5 = dup2(ra1.y), a6 = dup2(ra1.z), a7 = dup2(ra1.w);
            ULL ar[8] = {a0, a1, a2, a3, a4, a5, a6, a7};
            ULL br[4] = {b0, b1, b2, b3};
#pragma unroll
            for (int i = 0; i < 8; i++)
#pragma unroll
                for (int j = 0; j < 4; j++) fma2(acc2[i][j], ar[i], br[j]);
        }
        p ^= 1;
    }

#pragma unroll
    for (int i = 0; i < 8; i++) {
        const int r = row0 + ty * 8 + i;
        float* Crow = C + (size_t)r * DIM + col0 + tx * 8;
#pragma unroll
        for (int jp = 0; jp < 4; jp += 2) {
            float2 p0 = unpack2(acc2[i][jp]);
            float2 p1 = unpack2(acc2[i][jp + 1]);
            const int cb = col0 + tx * 8 + jp * 2;
            float4 o;
            o.x = p0.x + bias[cb + 0];
            o.y = p0.y + bias[cb + 1];
            o.z = p1.x + bias[cb + 2];
            o.w = p1.y + bias[cb + 3];
            *(float4*)(Crow + jp * 2) = o;
        }
    }
}

// ---------------- causal scores + streaming partial top-8 -------------------
// Block = (pair, key-half, batch). Handles qt = pair and 63-pair; within each,
// key tiles kt = half, half+2, ... <= qt. Writes partial top-8 to global.
__global__ __launch_bounds__(256, 2) void scores_topk_kernel(
    const float* __restrict__ q, const float* __restrict__ k,
    float* __restrict__ pval, int* __restrict__ pidx) {
    __shared__ float qs[16][68];
    __shared__ float ks[16][68];
    __shared__ float sc[64][65];
    __shared__ float tval[64][TOPK];
    __shared__ int   tidx[64][TOPK];

    const int tid = threadIdx.x;
    const int tx = tid & 15;
    const int ty = tid >> 4;
    const int b = blockIdx.z;
    const int half = blockIdx.y;
    const int pair = blockIdx.x;  // 0..31

    const float* qb = q + (size_t)b * NSEQ * DIM;
    const float* kb = k + (size_t)b * NSEQ * DIM;

    const int lr = tid >> 2;
    const int lc = (tid & 3) * 4;

    for (int s = 0; s < 2; s++) {
        const int qt = (s == 0) ? pair : (63 - pair);
        const int q0 = qt * 64;

        for (int i = tid; i < 64 * TOPK; i += 256) {
            tval[i >> 3][i & 7] = -INFINITY;
            tidx[i >> 3][i & 7] = 0;
        }
        __syncthreads();

        for (int kt = half; kt <= qt; kt += 2) {
            const int k0 = kt * 64;
            ULL acc2[4][2];
#pragma unroll
            for (int i = 0; i < 4; i++) { acc2[i][0] = 0ull; acc2[i][1] = 0ull; }

            for (int dc = 0; dc < DIM; dc += 16) {
                float4 qv = *(const float4*)(qb + (size_t)(q0 + lr) * DIM + dc + lc);
                float4 kv = *(const float4*)(kb + (size_t)(k0 + lr) * DIM + dc + lc);
                qs[lc + 0][lr] = qv.x; qs[lc + 1][lr] = qv.y;
                qs[lc + 2][lr] = qv.z; qs[lc + 3][lr] = qv.w;
                ks[lc + 0][lr] = kv.x; ks[lc + 1][lr] = kv.y;
                ks[lc + 2][lr] = kv.z; ks[lc + 3][lr] = kv.w;
                __syncthreads();
#pragma unroll
                for (int dd = 0; dd < 16; dd++) {
                    float4 rq = *(const float4*)&qs[dd][ty * 4];
                    ULL b0 = *(const ULL*)&ks[dd][tx * 4 + 0];
                    ULL b1 = *(const ULL*)&ks[dd][tx * 4 + 2];
                    ULL a0 = dup2(rq.x), a1 = dup2(rq.y), a2 = dup2(rq.z), a3 = dup2(rq.w);
                    fma2(acc2[0][0], a0, b0); fma2(acc2[0][1], a0, b1);
                    fma2(acc2[1][0], a1, b0); fma2(acc2[1][1], a1, b1);
                    fma2(acc2[2][0], a2, b0); fma2(acc2[2][1], a2, b1);
                    fma2(acc2[3][0], a3, b0); fma2(acc2[3][1], a3, b1);
                }
                __syncthreads();
            }
            // scale + causal mask + stage tile
#pragma unroll
            for (int i = 0; i < 4; i++) {
                const int rr = ty * 4 + i;
#pragma unroll
                for (int jp = 0; jp < 2; jp++) {
                    float2 pr = unpack2(acc2[i][jp]);
                    const int cc = tx * 4 + jp * 2;
                    float v0 = pr.x * 0.03125f;
                    float v1 = pr.y * 0.03125f;
                    if (k0 + cc + 0 > q0 + rr) v0 = -INFINITY;
                    if (k0 + cc + 1 > q0 + rr) v1 = -INFINITY;
                    sc[rr][cc + 0] = v0;
                    sc[rr][cc + 1] = v1;
                }
            }
            __syncthreads();
            // running top-8 merge: one thread per row
            if (tid < 64) {
                float tv[TOPK]; int ti[TOPK];
#pragma unroll
                for (int j = 0; j < TOPK; j++) { tv[j] = tval[tid][j]; ti[j] = tidx[tid][j]; }
                float vmin = tv[0]; int mpos = 0;
#pragma unroll
                for (int j = 1; j < TOPK; j++) if (tv[j] < vmin) { vmin = tv[j]; mpos = j; }
                for (int c = 0; c < 64; c++) {
                    const float vv = sc[tid][c];
                    if (vv > vmin) {
                        tv[mpos] = vv; ti[mpos] = k0 + c;
                        vmin = tv[0]; mpos = 0;
#pragma unroll
                        for (int j = 1; j < TOPK; j++) if (tv[j] < vmin) { vmin = tv[j]; mpos = j; }
                    }
                }
#pragma unroll
                for (int j = 0; j < TOPK; j++) { tval[tid][j] = tv[j]; tidx[tid][j] = ti[j]; }
            }
            __syncthreads();
        }

        // write partial top-8
        if (tid < 64) {
            const int row = b * NSEQ + q0 + tid;
            const size_t base = ((size_t)row * 2 + half) * TOPK;
#pragma unroll
            for (int j = 0; j < TOPK; j++) {
                pval[base + j] = tval[tid][j];
                pidx[base + j] = tidx[tid][j];
            }
        }
        __syncthreads();
    }
}

// ---------------- merge two partial top-8 lists + softmax -------------------
__global__ __launch_bounds__(256) void merge_softmax_kernel(
    const float* __restrict__ pv, const int* __restrict__ pi,
    float* __restrict__ probs, int* __restrict__ idxs) {
    const int row = blockIdx.x * 256 + threadIdx.x;
    if (row >= MROWS) return;
    float v[16]; int id[16];
#pragma unroll
    for (int j = 0; j < 16; j++) {
        v[j] = pv[(size_t)row * 16 + j];
        id[j] = pi[(size_t)row * 16 + j];
    }
    float tv[TOPK]; int ti[TOPK];
#pragma unroll
    for (int t = 0; t < TOPK; t++) {
        int m = 0; float best = v[0];
#pragma unroll
        for (int j = 1; j < 16; j++) if (v[j] > best) { best = v[j]; m = j; }
        tv[t] = best; ti[t] = id[m]; v[m] = -INFINITY;
    }
    float mx = tv[0];
#pragma unroll
    for (int j = 1; j < TOPK; j++) mx = fmaxf(mx, tv[j]);
    float e[TOPK]; float ssum = 0.f;
#pragma unroll
    for (int j = 0; j < TOPK; j++) { e[j] = expf(tv[j] - mx); ssum += e[j]; }
    const float inv = 1.f / ssum;
    const size_t base = (size_t)row * TOPK;
#pragma unroll
    for (int j = 0; j < TOPK; j++) { probs[base + j] = e[j] * inv; idxs[base + j] = ti[j]; }
}

// ---------------- sparse AV gather ------------------------------------------
__global__ __launch_bounds__(128) void gather_kernel(
    const float* __restrict__ v, const float* __restrict__ probs,
    const int* __restrict__ idxs, float* __restrict__ out) {
    const int row = blockIdx.x;
    const int b = row >> 12;
    const int tid = threadIdx.x;
    __shared__ float p[TOPK];
    __shared__ int   id[TOPK];
    if (tid < TOPK) {
        p[tid]  = probs[(size_t)row * TOPK + tid];
        id[tid] = idxs[(size_t)row * TOPK + tid];
    }
    __syncthreads();
    const float* vb = v + (size_t)b * NSEQ * DIM;
    const int c = tid * 8;
    float4 a0 = {0.f, 0.f, 0.f, 0.f}, a1 = {0.f, 0.f, 0.f, 0.f};
#pragma unroll
    for (int j = 0; j < TOPK; j++) {
        const float4* vr = (const float4*)(vb + (size_t)id[j] * DIM + c);
        const float pj = p[j];
        float4 v0 = vr[0], v1 = vr[1];
        a0.x += pj * v0.x; a0.y += pj * v0.y; a0.z += pj * v0.z; a0.w += pj * v0.w;
        a1.x += pj * v1.x; a1.y += pj * v1.y; a1.z += pj * v1.z; a1.w += pj * v1.w;
    }
    float4* orow = (float4*)(out + (size_t)row * DIM + c);
    orow[0] = a0; orow[1] = a1;
}

// ---------------- launch -----------------------------------------------------
extern "C" void kernel_launch(void* const* d_in, const int* in_sizes, int n_in,
                              void* d_out, int out_size) {
    const float* S  = (const float*)d_in[0];
    const float* Wq = (const float*)d_in[1];
    const float* bq = (const float*)d_in[2];
    const float* Wk = (const float*)d_in[3];
    const float* bk = (const float*)d_in[4];
    const float* Wv = (const float*)d_in[5];
    const float* bv = (const float*)d_in[6];
    const float* Wo = (const float*)d_in[7];
    const float* bo = (const float*)d_in[8];
    float* out = (float*)d_out;

    float *qp, *kp, *vp, *ap, *pp, *pvp;
    int *ip, *pip;
    cudaGetSymbolAddress((void**)&qp, g_q);
    cudaGetSymbolAddress((void**)&kp, g_k);
    cudaGetSymbolAddress((void**)&vp, g_v);
    cudaGetSymbolAddress((void**)&ap, g_attn);
    cudaGetSymbolAddress((void**)&pp, g_probs);
    cudaGetSymbolAddress((void**)&ip, g_topidx);
    cudaGetSymbolAddress((void**)&pvp, g_pval);
    cudaGetSymbolAddress((void**)&pip, g_pidx);

    dim3 gemm_grid(DIM / 128, MROWS / 128);  // (8, 128)
    gemm_bias_kernel<<<gemm_grid, 256>>>(S, Wq, bq, qp);
    gemm_bias_kernel<<<gemm_grid, 256>>>(S, Wk, bk, kp);
    gemm_bias_kernel<<<gemm_grid, 256>>>(S, Wv, bv, vp);
    scores_topk_kernel<<<dim3(32, 2, BSZ), 256>>>(qp, kp, pvp, pip);
    merge_softmax_kernel<<<(MROWS + 255) / 256, 256>>>(pvp, pip, pp, ip);
    gather_kernel<<<MROWS, 128>>>(vp, pp, ip, ap);
    gemm_bias_kernel<<<gemm_grid, 256>>>(ap, Wo, bo, out);
}

// round 3
// speedup vs baseline: 1.5405x; 1.1465x over previous
#include <cuda_runtime.h>
#include <math.h>

#define BSZ   4
#define NSEQ  4096
#define DIM   1024
#define TOPK  8
#define MROWS (BSZ * NSEQ)
#define NQT   32          // 128-row query tiles per batch
#define NQUART 4          // key-tile split factor

typedef unsigned long long ULL;

// ---------------- scratch (__device__ globals; no allocation allowed) -------
__device__ float g_q[(size_t)MROWS * DIM];
__device__ float g_k[(size_t)MROWS * DIM];
__device__ float g_v[(size_t)MROWS * DIM];
__device__ float g_attn[(size_t)MROWS * DIM];
__device__ float g_probs[(size_t)MROWS * TOPK];
__device__ int   g_topidx[(size_t)MROWS * TOPK];
// partial top-8 per (row, key-quarter)
__device__ float g_pval[(size_t)MROWS * NQUART * TOPK];
__device__ int   g_pidx[(size_t)MROWS * NQUART * TOPK];

// ---------------- packed f32x2 helpers ---------------------------------------
__device__ __forceinline__ ULL dup2(float a) {
    ULL r;
    asm("mov.b64 %0, {%1, %1};" : "=l"(r) : "f"(a));
    return r;
}
__device__ __forceinline__ ULL pack2(float x, float y) {
    ULL r;
    asm("mov.b64 %0, {%1, %2};" : "=l"(r) : "f"(x), "f"(y));
    return r;
}
__device__ __forceinline__ void fma2(ULL& d, ULL a, ULL b) {
    asm("fma.rn.f32x2 %0, %1, %2, %0;" : "+l"(d) : "l"(a), "l"(b));
}
__device__ __forceinline__ float2 unpack2(ULL x) {
    float2 r;
    asm("mov.b64 {%0, %1}, %2;" : "=f"(r.x), "=f"(r.y) : "l"(x));
    return r;
}

// ---------------- GEMM: C[M,1024] = A[M,1024] @ W[1024,1024] + bias ---------
__global__ __launch_bounds__(256, 2) void gemm_bias_kernel(
    const float* __restrict__ A, const float* __restrict__ W,
    const float* __restrict__ bias, float* __restrict__ C) {
    __shared__ float As[2][8][128];
    __shared__ float Bs[2][8][128];

    const int tid = threadIdx.x;
    const int tx = tid & 15;
    const int ty = tid >> 4;
    const int row0 = blockIdx.y * 128;
    const int col0 = blockIdx.x * 128;

    ULL acc2[8][4];
#pragma unroll
    for (int i = 0; i < 8; i++)
#pragma unroll
        for (int j = 0; j < 4; j++) acc2[i][j] = 0ull;

    const int a_row = tid >> 1;
    const int a_col = (tid & 1) * 4;
    const int b_row = tid >> 5;
    const int b_col = (tid & 31) * 4;

    const float* Aptr = A + (size_t)(row0 + a_row) * DIM + a_col;
    const float* Bptr = W + (size_t)b_row * DIM + col0 + b_col;

    float4 av = *(const float4*)(Aptr);
    float4 bv = *(const float4*)(Bptr);

    int p = 0;
    for (int k0 = 0; k0 < DIM; k0 += 8) {
        As[p][a_col + 0][a_row] = av.x;
        As[p][a_col + 1][a_row] = av.y;
        As[p][a_col + 2][a_row] = av.z;
        As[p][a_col + 3][a_row] = av.w;
        *(float4*)&Bs[p][b_row][b_col] = bv;
        __syncthreads();
        if (k0 + 8 < DIM) {
            av = *(const float4*)(Aptr + k0 + 8);
            bv = *(const float4*)(Bptr + (size_t)(k0 + 8) * DIM);
        }
#pragma unroll
        for (int kk = 0; kk < 8; kk++) {
            float4 ra0 = *(const float4*)&As[p][kk][ty * 8];
            float4 ra1 = *(const float4*)&As[p][kk][ty * 8 + 4];
            float4 rb0 = *(const float4*)&Bs[p][kk][tx * 8];
            float4 rb1 = *(const float4*)&Bs[p][kk][tx * 8 + 4];
            ULL b0 = pack2(rb0.x, rb0.y), b1 = pack2(rb0.z, rb0.w);
            ULL b2 = pack2(rb1.x, rb1.y), b3 = pack2(rb1.z, rb1.w);
            ULL a0 = dup2(ra0.x), a1 = dup2(ra0.y), a2 = dup2(ra0.z), a3 = dup2(ra0.w);
            ULL a4 = dup2(ra1.x), a5 = dup2(ra1.y), a6 = dup2(ra1.z), a7 = dup2(ra1.w);
            fma2(acc2[0][0], a0, b0); fma2(acc2[0][1], a0, b1); fma2(acc2[0][2], a0, b2); fma2(acc2[0][3], a0, b3);
            fma2(acc2[1][0], a1, b0); fma2(acc2[1][1], a1, b1); fma2(acc2[1][2], a1, b2); fma2(acc2[1][3], a1, b3);
            fma2(acc2[2][0], a2, b0); fma2(acc2[2][1], a2, b1); fma2(acc2[2][2], a2, b2); fma2(acc2[2][3], a2, b3);
            fma2(acc2[3][0], a3, b0); fma2(acc2[3][1], a3, b1); fma2(acc2[3][2], a3, b2); fma2(acc2[3][3], a3, b3);
            fma2(acc2[4][0], a4, b0); fma2(acc2[4][1], a4, b1); fma2(acc2[4][2], a4, b2); fma2(acc2[4][3], a4, b3);
            fma2(acc2[5][0], a5, b0); fma2(acc2[5][1], a5, b1); fma2(acc2[5][2], a5, b2); fma2(acc2[5][3], a5, b3);
            fma2(acc2[6][0], a6, b0); fma2(acc2[6][1], a6, b1); fma2(acc2[6][2], a6, b2); fma2(acc2[6][3], a6, b3);
            fma2(acc2[7][0], a7, b0); fma2(acc2[7][1], a7, b1); fma2(acc2[7][2], a7, b2); fma2(acc2[7][3], a7, b3);
        }
        p ^= 1;
    }

#pragma unroll
    for (int i = 0; i < 8; i++) {
        const int r = row0 + ty * 8 + i;
        float* Crow = C + (size_t)r * DIM + col0 + tx * 8;
#pragma unroll
        for (int jp = 0; jp < 4; jp += 2) {
            float2 p0 = unpack2(acc2[i][jp]);
            float2 p1 = unpack2(acc2[i][jp + 1]);
            const int cb = col0 + tx * 8 + jp * 2;
            float4 o;
            o.x = p0.x + bias[cb + 0];
            o.y = p0.y + bias[cb + 1];
            o.z = p1.x + bias[cb + 2];
            o.w = p1.y + bias[cb + 3];
            *(float4*)(Crow + jp * 2) = o;
        }
    }
}

// ---------------- causal scores + streaming partial top-8 -------------------
// 128x128 score tile, 8x8 per thread (GEMM-balanced). Block = (pair, quarter, b).
// qt = pair and 31-pair; kt = quarter, quarter+4, ... <= qt.
// Dynamic smem layout (floats):
//   As[2][8][128] (2048) | Bs[2][8][128] (2048) | sc[128][65] (8320)
//   | tval[128][8] (1024) | tidx[128][8] (1024 ints)
__global__ __launch_bounds__(256, 2) void scores_topk_kernel(
    const float* __restrict__ q, const float* __restrict__ k,
    float* __restrict__ pval, int* __restrict__ pidx) {
    extern __shared__ float sm[];
    float* As = sm;              // [2][8][128]
    float* Bs = sm + 2048;       // [2][8][128]
    float* sc = sm + 4096;       // [128][65]
    float* tval = sm + 12416;    // [128][8]
    int* tidx = (int*)(sm + 13440);

    const int tid = threadIdx.x;
    const int tx = tid & 15;
    const int ty = tid >> 4;
    const int b = blockIdx.z;
    const int quarter = blockIdx.y;
    const int pair = blockIdx.x;  // 0..15

    const float* qb = q + (size_t)b * NSEQ * DIM;
    const float* kb = k + (size_t)b * NSEQ * DIM;

    const int a_row = tid >> 1;       // 0..127
    const int a_col = (tid & 1) * 4;  // 0 or 4

    for (int s = 0; s < 2; s++) {
        const int qt = (s == 0) ? pair : (31 - pair);
        const int q0 = qt * 128;

        for (int i = tid; i < 128 * TOPK; i += 256) {
            tval[i] = -INFINITY;
            tidx[i] = 0;
        }
        __syncthreads();

        for (int kt = quarter; kt <= qt; kt += NQUART) {
            const int k0 = kt * 128;
            ULL acc2[8][4];
#pragma unroll
            for (int i = 0; i < 8; i++)
#pragma unroll
                for (int j = 0; j < 4; j++) acc2[i][j] = 0ull;

            const float* Aptr = qb + (size_t)(q0 + a_row) * DIM + a_col;
            const float* Bptr = kb + (size_t)(k0 + a_row) * DIM + a_col;
            float4 av = *(const float4*)(Aptr);
            float4 bv = *(const float4*)(Bptr);

            int p = 0;
            for (int dc = 0; dc < DIM; dc += 8) {
                As[(p * 8 + a_col + 0) * 128 + a_row] = av.x;
                As[(p * 8 + a_col + 1) * 128 + a_row] = av.y;
                As[(p * 8 + a_col + 2) * 128 + a_row] = av.z;
                As[(p * 8 + a_col + 3) * 128 + a_row] = av.w;
                Bs[(p * 8 + a_col + 0) * 128 + a_row] = bv.x;
                Bs[(p * 8 + a_col + 1) * 128 + a_row] = bv.y;
                Bs[(p * 8 + a_col + 2) * 128 + a_row] = bv.z;
                Bs[(p * 8 + a_col + 3) * 128 + a_row] = bv.w;
                __syncthreads();
                if (dc + 8 < DIM) {
                    av = *(const float4*)(Aptr + dc + 8);
                    bv = *(const float4*)(Bptr + dc + 8);
                }
#pragma unroll
                for (int dd = 0; dd < 8; dd++) {
                    float4 ra0 = *(const float4*)&As[(p * 8 + dd) * 128 + ty * 8];
                    float4 ra1 = *(const float4*)&As[(p * 8 + dd) * 128 + ty * 8 + 4];
                    float4 rb0 = *(const float4*)&Bs[(p * 8 + dd) * 128 + tx * 8];
                    float4 rb1 = *(const float4*)&Bs[(p * 8 + dd) * 128 + tx * 8 + 4];
                    ULL b0 = pack2(rb0.x, rb0.y), b1 = pack2(rb0.z, rb0.w);
                    ULL b2 = pack2(rb1.x, rb1.y), b3 = pack2(rb1.z, rb1.w);
                    ULL a0 = dup2(ra0.x), a1 = dup2(ra0.y), a2 = dup2(ra0.z), a3 = dup2(ra0.w);
                    ULL a4 = dup2(ra1.x), a5 = dup2(ra1.y), a6 = dup2(ra1.z), a7 = dup2(ra1.w);
                    fma2(acc2[0][0], a0, b0); fma2(acc2[0][1], a0, b1); fma2(acc2[0][2], a0, b2); fma2(acc2[0][3], a0, b3);
                    fma2(acc2[1][0], a1, b0); fma2(acc2[1][1], a1, b1); fma2(acc2[1][2], a1, b2); fma2(acc2[1][3], a1, b3);
                    fma2(acc2[2][0], a2, b0); fma2(acc2[2][1], a2, b1); fma2(acc2[2][2], a2, b2); fma2(acc2[2][3], a2, b3);
                    fma2(acc2[3][0], a3, b0); fma2(acc2[3][1], a3, b1); fma2(acc2[3][2], a3, b2); fma2(acc2[3][3], a3, b3);
                    fma2(acc2[4][0], a4, b0); fma2(acc2[4][1], a4, b1); fma2(acc2[4][2], a4, b2); fma2(acc2[4][3], a4, b3);
                    fma2(acc2[5][0], a5, b0); fma2(acc2[5][1], a5, b1); fma2(acc2[5][2], a5, b2); fma2(acc2[5][3], a5, b3);
                    fma2(acc2[6][0], a6, b0); fma2(acc2[6][1], a6, b1); fma2(acc2[6][2], a6, b2); fma2(acc2[6][3], a6, b3);
                    fma2(acc2[7][0], a7, b0); fma2(acc2[7][1], a7, b1); fma2(acc2[7][2], a7, b2); fma2(acc2[7][3], a7, b3);
                }
                p ^= 1;
            }

            // stage + merge in two 64-column passes
#pragma unroll
            for (int h = 0; h < 2; h++) {
                if ((tx >> 3) == h) {
                    const int txl = tx & 7;
#pragma unroll
                    for (int i = 0; i < 8; i++) {
                        const int rr = ty * 8 + i;
#pragma unroll
                        for (int jp = 0; jp < 4; jp++) {
                            float2 pr = unpack2(acc2[i][jp]);
                            const int gc0 = k0 + tx * 8 + jp * 2;
                            float v0 = pr.x * 0.03125f;
                            float v1 = pr.y * 0.03125f;
                            if (gc0 + 0 > q0 + rr) v0 = -INFINITY;
                            if (gc0 + 1 > q0 + rr) v1 = -INFINITY;
                            sc[rr * 65 + txl * 8 + jp * 2 + 0] = v0;
                            sc[rr * 65 + txl * 8 + jp * 2 + 1] = v1;
                        }
                    }
                }
                __syncthreads();
                if (tid < 128) {
                    float tv[TOPK]; int ti[TOPK];
#pragma unroll
                    for (int j = 0; j < TOPK; j++) { tv[j] = tval[tid * 8 + j]; ti[j] = tidx[tid * 8 + j]; }
                    float vmin = tv[0]; int mpos = 0;
#pragma unroll
                    for (int j = 1; j < TOPK; j++) if (tv[j] < vmin) { vmin = tv[j]; mpos = j; }
                    const int cbase = k0 + h * 64;
                    for (int c = 0; c < 64; c++) {
                        const float vv = sc[tid * 65 + c];
                        if (vv > vmin) {
                            tv[mpos] = vv; ti[mpos] = cbase + c;
                            vmin = tv[0]; mpos = 0;
#pragma unroll
                            for (int j = 1; j < TOPK; j++) if (tv[j] < vmin) { vmin = tv[j]; mpos = j; }
                        }
                    }
#pragma unroll
                    for (int j = 0; j < TOPK; j++) { tval[tid * 8 + j] = tv[j]; tidx[tid * 8 + j] = ti[j]; }
                }
                __syncthreads();
            }
        }

        // write partial top-8 for this key-quarter
        if (tid < 128) {
            const int row = b * NSEQ + q0 + tid;
            const size_t base = ((size_t)row * NQUART + quarter) * TOPK;
#pragma unroll
            for (int j = 0; j < TOPK; j++) {
                pval[base + j] = tval[tid * 8 + j];
                pidx[base + j] = tidx[tid * 8 + j];
            }
        }
        __syncthreads();
    }
}

// ---------------- merge NQUART partial top-8 lists + softmax ----------------
__global__ __launch_bounds__(256) void merge_softmax_kernel(
    const float* __restrict__ pv, const int* __restrict__ pi,
    float* __restrict__ probs, int* __restrict__ idxs) {
    const int row = blockIdx.x * 256 + threadIdx.x;
    if (row >= MROWS) return;
    const int NC = NQUART * TOPK;  // 32
    float v[NC]; int id[NC];
#pragma unroll
    for (int j = 0; j < NC; j++) {
        v[j] = pv[(size_t)row * NC + j];
        id[j] = pi[(size_t)row * NC + j];
    }
    float tv[TOPK]; int ti[TOPK];
#pragma unroll
    for (int t = 0; t < TOPK; t++) {
        int m = 0; float best = v[0];
#pragma unroll
        for (int j = 1; j < NC; j++) if (v[j] > best) { best = v[j]; m = j; }
        tv[t] = best; ti[t] = id[m]; v[m] = -INFINITY;
    }
    float mx = tv[0];
#pragma unroll
    for (int j = 1; j < TOPK; j++) mx = fmaxf(mx, tv[j]);
    float e[TOPK]; float ssum = 0.f;
#pragma unroll
    for (int j = 0; j < TOPK; j++) { e[j] = expf(tv[j] - mx); ssum += e[j]; }
    const float inv = 1.f / ssum;
    const size_t base = (size_t)row * TOPK;
#pragma unroll
    for (int j = 0; j < TOPK; j++) { probs[base + j] = e[j] * inv; idxs[base + j] = ti[j]; }
}

// ---------------- sparse AV gather ------------------------------------------
__global__ __launch_bounds__(128) void gather_kernel(
    const float* __restrict__ v, const float* __restrict__ probs,
    const int* __restrict__ idxs, float* __restrict__ out) {
    const int row = blockIdx.x;
    const int b = row >> 12;
    const int tid = threadIdx.x;
    __shared__ float p[TOPK];
    __shared__ int   id[TOPK];
    if (tid < TOPK) {
        p[tid]  = probs[(size_t)row * TOPK + tid];
        id[tid] = idxs[(size_t)row * TOPK + tid];
    }
    __syncthreads();
    const float* vb = v + (size_t)b * NSEQ * DIM;
    const int c = tid * 8;
    float4 a0 = {0.f, 0.f, 0.f, 0.f}, a1 = {0.f, 0.f, 0.f, 0.f};
#pragma unroll
    for (int j = 0; j < TOPK; j++) {
        const float4* vr = (const float4*)(vb + (size_t)id[j] * DIM + c);
        const float pj = p[j];
        float4 v0 = vr[0], v1 = vr[1];
        a0.x += pj * v0.x; a0.y += pj * v0.y; a0.z += pj * v0.z; a0.w += pj * v0.w;
        a1.x += pj * v1.x; a1.y += pj * v1.y; a1.z += pj * v1.z; a1.w += pj * v1.w;
    }
    float4* orow = (float4*)(out + (size_t)row * DIM + c);
    orow[0] = a0; orow[1] = a1;
}

// ---------------- launch -----------------------------------------------------
extern "C" void kernel_launch(void* const* d_in, const int* in_sizes, int n_in,
                              void* d_out, int out_size) {
    const float* S  = (const float*)d_in[0];
    const float* Wq = (const float*)d_in[1];
    const float* bq = (const float*)d_in[2];
    const float* Wk = (const float*)d_in[3];
    const float* bk = (const float*)d_in[4];
    const float* Wv = (const float*)d_in[5];
    const float* bv = (const float*)d_in[6];
    const float* Wo = (const float*)d_in[7];
    const float* bo = (const float*)d_in[8];
    float* out = (float*)d_out;

    float *qp, *kp, *vp, *ap, *pp, *pvp;
    int *ip, *pip;
    cudaGetSymbolAddress((void**)&qp, g_q);
    cudaGetSymbolAddress((void**)&kp, g_k);
    cudaGetSymbolAddress((void**)&vp, g_v);
    cudaGetSymbolAddress((void**)&ap, g_attn);
    cudaGetSymbolAddress((void**)&pp, g_probs);
    cudaGetSymbolAddress((void**)&ip, g_topidx);
    cudaGetSymbolAddress((void**)&pvp, g_pval);
    cudaGetSymbolAddress((void**)&pip, g_pidx);

    const int SCORES_SMEM = (2048 + 2048 + 128 * 65 + 128 * 8) * 4 + 128 * 8 * 4;  // 57856
    cudaFuncSetAttribute(scores_topk_kernel,
                         cudaFuncAttributeMaxDynamicSharedMemorySize, SCORES_SMEM);

    dim3 gemm_grid(DIM / 128, MROWS / 128);  // (8, 128)
    gemm_bias_kernel<<<gemm_grid, 256>>>(S, Wq, bq, qp);
    gemm_bias_kernel<<<gemm_grid, 256>>>(S, Wk, bk, kp);
    gemm_bias_kernel<<<gemm_grid, 256>>>(S, Wv, bv, vp);
    scores_topk_kernel<<<dim3(16, NQUART, BSZ), 256, SCORES_SMEM>>>(qp, kp, pvp, pip);
    merge_softmax_kernel<<<(MROWS + 255) / 256, 256>>>(pvp, pip, pp, ip);
    gather_kernel<<<MROWS, 128>>>(vp, pp, ip, ap);
    gemm_bias_kernel<<<gemm_grid, 256>>>(ap, Wo, bo, out);
}

// round 6
// speedup vs baseline: 1.8024x; 1.1701x over previous
#include <cuda_runtime.h>
#include <math.h>
#include <stdint.h>

#define BSZ   4
#define NSEQ  4096
#define DIM   1024
#define TOPK  8
#define MROWS (BSZ * NSEQ)
#define NQUART 4
#define KS8   (DIM / 8)   // 128 k-steps of 8

typedef unsigned long long ULL;

// ---------------- scratch (__device__ globals; no allocation allowed) -------
__device__ __align__(128) float g_q[(size_t)MROWS * DIM];
__device__ __align__(128) float g_k[(size_t)MROWS * DIM];
__device__ __align__(128) float g_v[(size_t)MROWS * DIM];
__device__ __align__(128) float g_attn[(size_t)MROWS * DIM];
__device__ float g_probs[(size_t)MROWS * TOPK];
__device__ int   g_topidx[(size_t)MROWS * TOPK];
__device__ float g_pval[(size_t)MROWS * NQUART * TOPK];
__device__ int   g_pidx[(size_t)MROWS * NQUART * TOPK];
// fragment-packed 3xTF32 buffers
__device__ __align__(128) float g_ahi[(size_t)MROWS * DIM];   // A packed hi
__device__ __align__(128) float g_alo[(size_t)MROWS * DIM];   // A packed lo
__device__ __align__(128) float g_wthi[4][(size_t)DIM * DIM]; // B packed hi
__device__ __align__(128) float g_wtlo[4][(size_t)DIM * DIM]; // B packed lo

// ---------------- helpers -----------------------------------------------------
__device__ __forceinline__ uint32_t smem_u32(const void* p) {
    uint32_t a;
    asm("{ .reg .u64 t; cvta.to.shared.u64 t, %1; cvt.u32.u64 %0, t; }"
        : "=r"(a) : "l"(p));
    return a;
}
__device__ __forceinline__ float tf32r(float x) {
    uint32_t u;
    asm("cvt.rna.tf32.f32 %0, %1;" : "=r"(u) : "f"(x));
    return __uint_as_float(u);
}
__device__ __forceinline__ void cpasync16(uint32_t saddr, const void* g) {
    asm volatile("cp.async.cg.shared.global [%0], [%1], 16;"
                 :: "r"(saddr), "l"(g));
}
#define CP_COMMIT() asm volatile("cp.async.commit_group;" ::: "memory")
#define CP_WAIT_1() asm volatile("cp.async.wait_group 1;" ::: "memory")
#define CP_WAIT_0() asm volatile("cp.async.wait_group 0;" ::: "memory")

__device__ __forceinline__ void mma8(float4& c, const uint4& a, const uint2& b) {
    asm volatile(
        "mma.sync.aligned.m16n8k8.row.col.f32.tf32.tf32.f32 "
        "{%0,%1,%2,%3}, {%4,%5,%6,%7}, {%8,%9}, {%0,%1,%2,%3};"
        : "+f"(c.x), "+f"(c.y), "+f"(c.z), "+f"(c.w)
        : "r"(a.x), "r"(a.y), "r"(a.z), "r"(a.w), "r"(b.x), "r"(b.y));
}

// ---------------- packed f32x2 helpers (scores kernel) ----------------------
__device__ __forceinline__ ULL dup2(float a) {
    ULL r; asm("mov.b64 %0, {%1, %1};" : "=l"(r) : "f"(a)); return r;
}
__device__ __forceinline__ ULL pack2(float x, float y) {
    ULL r; asm("mov.b64 %0, {%1, %2};" : "=l"(r) : "f"(x), "f"(y)); return r;
}
__device__ __forceinline__ void fma2(ULL& d, ULL a, ULL b) {
    asm("fma.rn.f32x2 %0, %1, %2, %0;" : "+l"(d) : "l"(a), "l"(b));
}
__device__ __forceinline__ float2 unpack2(ULL x) {
    float2 r; asm("mov.b64 {%0, %1}, %2;" : "=f"(r.x), "=f"(r.y) : "l"(x)); return r;
}

// ---------------- split+pack A: X[M,K] -> frag-packed hi/lo -----------------
// Layout: [M/16][K/8][lane 0..31][r 0..3], r order = (a0,a1,a2,a3) of
// mma.m16n8k8: row = g + (r&1)*8, col = t + (r>>1)*4 with g=lane>>2, t=lane&3.
__global__ __launch_bounds__(256) void split_pack_a(
    const float* __restrict__ X, float4* __restrict__ Phi, float4* __restrict__ Plo) {
    const int atom = blockIdx.x * 8 + (threadIdx.x >> 5);
    const int lane = threadIdx.x & 31;
    const int mt = atom >> 7;    // / KS8
    const int ks = atom & 127;
    const int g = lane >> 2, t = lane & 3;
    const size_t r0 = (size_t)(mt * 16 + g) * DIM + ks * 8 + t;
    const size_t r1 = r0 + 8 * DIM;
    float x0 = X[r0], x1 = X[r1], x2 = X[r0 + 4], x3 = X[r1 + 4];
    float4 h, l;
    h.x = tf32r(x0); l.x = tf32r(x0 - h.x);
    h.y = tf32r(x1); l.y = tf32r(x1 - h.y);
    h.z = tf32r(x2); l.z = tf32r(x2 - h.z);
    h.w = tf32r(x3); l.w = tf32r(x3 - h.w);
    Phi[(size_t)atom * 32 + lane] = h;
    Plo[(size_t)atom * 32 + lane] = l;
}

// ---------------- split+pack W: W[K,N] -> B frag-packed hi/lo ---------------
// Layout: [N/8][K/8][lane][r 0..1], b_r = W[ks*8 + t + 4r][nt*8 + g].
__global__ __launch_bounds__(256) void split_pack_w(
    const float* __restrict__ W, float2* __restrict__ Phi, float2* __restrict__ Plo) {
    const int atom = blockIdx.x * 8 + (threadIdx.x >> 5);
    const int lane = threadIdx.x & 31;
    const int nt = atom >> 7;
    const int ks = atom & 127;
    const int g = lane >> 2, t = lane & 3;
    float x0 = W[(size_t)(ks * 8 + t) * DIM + nt * 8 + g];
    float x1 = W[(size_t)(ks * 8 + t + 4) * DIM + nt * 8 + g];
    float2 h, l;
    h.x = tf32r(x0); l.x = tf32r(x0 - h.x);
    h.y = tf32r(x1); l.y = tf32r(x1 - h.y);
    Phi[(size_t)atom * 32 + lane] = h;
    Plo[(size_t)atom * 32 + lane] = l;
}

// ---------------- 3xTF32 mma.sync GEMM: C[M,N]=A@W+bias ---------------------
// Block 256(M)x128(N), BK=16, 8 warps of 64x64, 3-stage cp.async pipeline.
// Stage layout (f32): Ahi[16mt][2ks][128] @0 | Alo @4096 | Bhi[16nt][2ks][64]
// @8192 | Blo @10240. Stage stride 12288 f32. 3 stages = 147456 B.
#define GEMM_SMEM (3 * 12288 * 4)

__global__ __launch_bounds__(256, 1) void gemm_mma_kernel(
    const float* __restrict__ Ahi, const float* __restrict__ Alo,
    const float* __restrict__ Bhi, const float* __restrict__ Blo,
    const float* __restrict__ bias, float* __restrict__ C) {
    extern __shared__ float sm[];
    const int tid = threadIdx.x;
    const int lane = tid & 31, wid = tid >> 5;
    const int wy = wid >> 1, wx = wid & 1;   // 4x2 warp grid of 64x64
    const int br16 = blockIdx.y * 16;        // block A mt base
    const int bn16 = blockIdx.x * 16;        // block B nt base
    const int m0 = blockIdx.y * 256;
    const int n0 = blockIdx.x * 128;
    const uint32_t smb = smem_u32(sm);

    auto load_stage = [&](int kc, int s) {
        const uint32_t sb = smb + s * 49152;
#pragma unroll
        for (int j = 0; j < 4; j++) {
            const int cA = tid + j * 256;            // 0..1023
            const int mtl = cA >> 6, off = cA & 63;
            const uint32_t so = sb + (uint32_t)(mtl * 256 + off * 4) * 4;
            const size_t go = ((size_t)(br16 + mtl) * KS8 + kc * 2) * 128 + off * 4;
            cpasync16(so, Ahi + go);
            cpasync16(so + 4096 * 4, Alo + go);
        }
#pragma unroll
        for (int j = 0; j < 2; j++) {
            const int cB = tid + j * 256;            // 0..511
            const int ntl = cB >> 5, off = cB & 31;
            const uint32_t so = sb + (uint32_t)(8192 + ntl * 128 + off * 4) * 4;
            const size_t go = ((size_t)(bn16 + ntl) * KS8 + kc * 2) * 64 + off * 4;
            cpasync16(so, Bhi + go);
            cpasync16(so + 2048 * 4, Blo + go);
        }
    };

    load_stage(0, 0); CP_COMMIT();
    load_stage(1, 1); CP_COMMIT();

    float4 acc[4][8];
#pragma unroll
    for (int i = 0; i < 4; i++)
#pragma unroll
        for (int j = 0; j < 8; j++) acc[i][j] = make_float4(0.f, 0.f, 0.f, 0.f);

    for (int c = 0; c < 64; c++) {
        if (c < 62) { CP_WAIT_1(); } else { CP_WAIT_0(); }
        __syncthreads();
        if (c + 2 < 64) { load_stage(c + 2, (c + 2) % 3); CP_COMMIT(); }
        const float* st = sm + (c % 3) * 12288;
#pragma unroll
        for (int ks = 0; ks < 2; ks++) {
            uint4 Ah[4], Al[4];
            uint2 Bh[8], Bl[8];
#pragma unroll
            for (int i = 0; i < 4; i++) {
                const float* p = st + ((wy * 4 + i) * 2 + ks) * 128 + lane * 4;
                Ah[i] = *(const uint4*)p;
                Al[i] = *(const uint4*)(p + 4096);
            }
#pragma unroll
            for (int j = 0; j < 8; j++) {
                const float* p = st + 8192 + ((wx * 8 + j) * 2 + ks) * 64 + lane * 2;
                Bh[j] = *(const uint2*)p;
                Bl[j] = *(const uint2*)(p + 2048);
            }
#pragma unroll
            for (int i = 0; i < 4; i++)
#pragma unroll
                for (int j = 0; j < 8; j++) {
                    mma8(acc[i][j], Ah[i], Bh[j]);
                    mma8(acc[i][j], Ah[i], Bl[j]);
                    mma8(acc[i][j], Al[i], Bh[j]);
                }
        }
    }

    // epilogue: direct float2 stores + bias
    const int g = lane >> 2, t = lane & 3;
#pragma unroll
    for (int i = 0; i < 4; i++) {
        const int r0 = m0 + wy * 64 + i * 16 + g;
#pragma unroll
        for (int j = 0; j < 8; j++) {
            const int col = n0 + wx * 64 + j * 8 + t * 2;
            const float2 bb = *(const float2*)(bias + col);
            float2 o0 = {acc[i][j].x + bb.x, acc[i][j].y + bb.y};
            float2 o1 = {acc[i][j].z + bb.x, acc[i][j].w + bb.y};
            *(float2*)(C + (size_t)r0 * DIM + col) = o0;
            *(float2*)(C + (size_t)(r0 + 8) * DIM + col) = o1;
        }
    }
}

// ---------------- causal scores + streaming partial top-8 (R3, passing) -----
__global__ __launch_bounds__(256, 2) void scores_topk_kernel(
    const float* __restrict__ q, const float* __restrict__ k,
    float* __restrict__ pval, int* __restrict__ pidx) {
    extern __shared__ float smx[];
    float* As = smx;
    float* Bs = smx + 2048;
    float* sc = smx + 4096;
    float* tval = smx + 12416;
    int* tidx = (int*)(smx + 13440);

    const int tid = threadIdx.x;
    const int tx = tid & 15;
    const int ty = tid >> 4;
    const int b = blockIdx.z;
    const int quarter = blockIdx.y;
    const int pair = blockIdx.x;

    const float* qb = q + (size_t)b * NSEQ * DIM;
    const float* kb = k + (size_t)b * NSEQ * DIM;

    const int a_row = tid >> 1;
    const int a_col = (tid & 1) * 4;

    for (int s = 0; s < 2; s++) {
        const int qt = (s == 0) ? pair : (31 - pair);
        const int q0 = qt * 128;

        for (int i = tid; i < 128 * TOPK; i += 256) {
            tval[i] = -INFINITY;
            tidx[i] = 0;
        }
        __syncthreads();

        for (int kt = quarter; kt <= qt; kt += NQUART) {
            const int k0 = kt * 128;
            ULL acc2[8][4];
#pragma unroll
            for (int i = 0; i < 8; i++)
#pragma unroll
                for (int j = 0; j < 4; j++) acc2[i][j] = 0ull;

            const float* Aptr = qb + (size_t)(q0 + a_row) * DIM + a_col;
            const float* Bptr = kb + (size_t)(k0 + a_row) * DIM + a_col;
            float4 av = *(const float4*)(Aptr);
            float4 bv = *(const float4*)(Bptr);

            int p = 0;
            for (int dc = 0; dc < DIM; dc += 8) {
                As[(p * 8 + a_col + 0) * 128 + a_row] = av.x;
                As[(p * 8 + a_col + 1) * 128 + a_row] = av.y;
                As[(p * 8 + a_col + 2) * 128 + a_row] = av.z;
                As[(p * 8 + a_col + 3) * 128 + a_row] = av.w;
                Bs[(p * 8 + a_col + 0) * 128 + a_row] = bv.x;
                Bs[(p * 8 + a_col + 1) * 128 + a_row] = bv.y;
                Bs[(p * 8 + a_col + 2) * 128 + a_row] = bv.z;
                Bs[(p * 8 + a_col + 3) * 128 + a_row] = bv.w;
                __syncthreads();
                if (dc + 8 < DIM) {
                    av = *(const float4*)(Aptr + dc + 8);
                    bv = *(const float4*)(Bptr + dc + 8);
                }
#pragma unroll
                for (int dd = 0; dd < 8; dd++) {
                    float4 ra0 = *(const float4*)&As[(p * 8 + dd) * 128 + ty * 8];
                    float4 ra1 = *(const float4*)&As[(p * 8 + dd) * 128 + ty * 8 + 4];
                    float4 rb0 = *(const float4*)&Bs[(p * 8 + dd) * 128 + tx * 8];
                    float4 rb1 = *(const float4*)&Bs[(p * 8 + dd) * 128 + tx * 8 + 4];
                    ULL b0 = pack2(rb0.x, rb0.y), b1 = pack2(rb0.z, rb0.w);
                    ULL b2 = pack2(rb1.x, rb1.y), b3 = pack2(rb1.z, rb1.w);
                    ULL a0 = dup2(ra0.x), a1 = dup2(ra0.y), a2 = dup2(ra0.z), a3 = dup2(ra0.w);
                    ULL a4 = dup2(ra1.x), a5 = dup2(ra1.y), a6 = dup2(ra1.z), a7 = dup2(ra1.w);
                    fma2(acc2[0][0], a0, b0); fma2(acc2[0][1], a0, b1); fma2(acc2[0][2], a0, b2); fma2(acc2[0][3], a0, b3);
                    fma2(acc2[1][0], a1, b0); fma2(acc2[1][1], a1, b1); fma2(acc2[1][2], a1, b2); fma2(acc2[1][3], a1, b3);
                    fma2(acc2[2][0], a2, b0); fma2(acc2[2][1], a2, b1); fma2(acc2[2][2], a2, b2); fma2(acc2[2][3], a2, b3);
                    fma2(acc2[3][0], a3, b0); fma2(acc2[3][1], a3, b1); fma2(acc2[3][2], a3, b2); fma2(acc2[3][3], a3, b3);
                    fma2(acc2[4][0], a4, b0); fma2(acc2[4][1], a4, b1); fma2(acc2[4][2], a4, b2); fma2(acc2[4][3], a4, b3);
                    fma2(acc2[5][0], a5, b0); fma2(acc2[5][1], a5, b1); fma2(acc2[5][2], a5, b2); fma2(acc2[5][3], a5, b3);
                    fma2(acc2[6][0], a6, b0); fma2(acc2[6][1], a6, b1); fma2(acc2[6][2], a6, b2); fma2(acc2[6][3], a6, b3);
                    fma2(acc2[7][0], a7, b0); fma2(acc2[7][1], a7, b1); fma2(acc2[7][2], a7, b2); fma2(acc2[7][3], a7, b3);
                }
                p ^= 1;
            }

#pragma unroll
            for (int h = 0; h < 2; h++) {
                if ((tx >> 3) == h) {
                    const int txl = tx & 7;
#pragma unroll
                    for (int i = 0; i < 8; i++) {
                        const int rr = ty * 8 + i;
#pragma unroll
                        for (int jp = 0; jp < 4; jp++) {
                            float2 pr = unpack2(acc2[i][jp]);
                            const int gc0 = k0 + tx * 8 + jp * 2;
                            float v0 = pr.x * 0.03125f;
                            float v1 = pr.y * 0.03125f;
                            if (gc0 + 0 > q0 + rr) v0 = -INFINITY;
                            if (gc0 + 1 > q0 + rr) v1 = -INFINITY;
                            sc[rr * 65 + txl * 8 + jp * 2 + 0] = v0;
                            sc[rr * 65 + txl * 8 + jp * 2 + 1] = v1;
                        }
                    }
                }
                __syncthreads();
                if (tid < 128) {
                    float tv[TOPK]; int ti[TOPK];
#pragma unroll
                    for (int j = 0; j < TOPK; j++) { tv[j] = tval[tid * 8 + j]; ti[j] = tidx[tid * 8 + j]; }
                    float vmin = tv[0]; int mpos = 0;
#pragma unroll
                    for (int j = 1; j < TOPK; j++) if (tv[j] < vmin) { vmin = tv[j]; mpos = j; }
                    const int cbase = k0 + h * 64;
                    for (int cc = 0; cc < 64; cc++) {
                        const float vv = sc[tid * 65 + cc];
                        if (vv > vmin) {
                            tv[mpos] = vv; ti[mpos] = cbase + cc;
                            vmin = tv[0]; mpos = 0;
#pragma unroll
                            for (int j = 1; j < TOPK; j++) if (tv[j] < vmin) { vmin = tv[j]; mpos = j; }
                        }
                    }
#pragma unroll
                    for (int j = 0; j < TOPK; j++) { tval[tid * 8 + j] = tv[j]; tidx[tid * 8 + j] = ti[j]; }
                }
                __syncthreads();
            }
        }

        if (tid < 128) {
            const int row = b * NSEQ + q0 + tid;
            const size_t base = ((size_t)row * NQUART + quarter) * TOPK;
#pragma unroll
            for (int j = 0; j < TOPK; j++) {
                pval[base + j] = tval[tid * 8 + j];
                pidx[base + j] = tidx[tid * 8 + j];
            }
        }
        __syncthreads();
    }
}

// ---------------- merge NQUART partial top-8 lists + softmax ----------------
__global__ __launch_bounds__(256) void merge_softmax_kernel(
    const float* __restrict__ pv, const int* __restrict__ pi,
    float* __restrict__ probs, int* __restrict__ idxs) {
    const int row = blockIdx.x * 256 + threadIdx.x;
    if (row >= MROWS) return;
    const int NC = NQUART * TOPK;
    float v[NC]; int id[NC];
#pragma unroll
    for (int j = 0; j < NC; j++) {
        v[j] = pv[(size_t)row * NC + j];
        id[j] = pi[(size_t)row * NC + j];
    }
    float tv[TOPK]; int ti[TOPK];
#pragma unroll
    for (int t = 0; t < TOPK; t++) {
        int m = 0; float best = v[0];
#pragma unroll
        for (int j = 1; j < NC; j++) if (v[j] > best) { best = v[j]; m = j; }
        tv[t] = best; ti[t] = id[m]; v[m] = -INFINITY;
    }
    float mx = tv[0];
#pragma unroll
    for (int j = 1; j < TOPK; j++) mx = fmaxf(mx, tv[j]);
    float e[TOPK]; float ssum = 0.f;
#pragma unroll
    for (int j = 0; j < TOPK; j++) { e[j] = expf(tv[j] - mx); ssum += e[j]; }
    const float inv = 1.f / ssum;
    const size_t base = (size_t)row * TOPK;
#pragma unroll
    for (int j = 0; j < TOPK; j++) { probs[base + j] = e[j] * inv; idxs[base + j] = ti[j]; }
}

// ---------------- sparse AV gather ------------------------------------------
__global__ __launch_bounds__(128) void gather_kernel(
    const float* __restrict__ v, const float* __restrict__ probs,
    const int* __restrict__ idxs, float* __restrict__ out) {
    const int row = blockIdx.x;
    const int b = row >> 12;
    const int tid = threadIdx.x;
    __shared__ float p[TOPK];
    __shared__ int   id[TOPK];
    if (tid < TOPK) {
        p[tid]  = probs[(size_t)row * TOPK + tid];
        id[tid] = idxs[(size_t)row * TOPK + tid];
    }
    __syncthreads();
    const float* vb = v + (size_t)b * NSEQ * DIM;
    const int c = tid * 8;
    float4 a0 = {0.f, 0.f, 0.f, 0.f}, a1 = {0.f, 0.f, 0.f, 0.f};
#pragma unroll
    for (int j = 0; j < TOPK; j++) {
        const float4* vr = (const float4*)(vb + (size_t)id[j] * DIM + c);
        const float pj = p[j];
        float4 v0 = vr[0], v1 = vr[1];
        a0.x += pj * v0.x; a0.y += pj * v0.y; a0.z += pj * v0.z; a0.w += pj * v0.w;
        a1.x += pj * v1.x; a1.y += pj * v1.y; a1.z += pj * v1.z; a1.w += pj * v1.w;
    }
    float4* orow = (float4*)(out + (size_t)row * DIM + c);
    orow[0] = a0; orow[1] = a1;
}

// ---------------- launch -----------------------------------------------------
extern "C" void kernel_launch(void* const* d_in, const int* in_sizes, int n_in,
                              void* d_out, int out_size) {
    const float* S  = (const float*)d_in[0];
    const float* Wq = (const float*)d_in[1];
    const float* bq = (const float*)d_in[2];
    const float* Wk = (const float*)d_in[3];
    const float* bk = (const float*)d_in[4];
    const float* Wv = (const float*)d_in[5];
    const float* bv = (const float*)d_in[6];
    const float* Wo = (const float*)d_in[7];
    const float* bo = (const float*)d_in[8];
    float* out = (float*)d_out;

    float *qp, *kp, *vp, *ap, *pp, *pvp, *ahip, *alop, *wthip, *wtlop;
    int *ip, *pip;
    cudaGetSymbolAddress((void**)&qp, g_q);
    cudaGetSymbolAddress((void**)&kp, g_k);
    cudaGetSymbolAddress((void**)&vp, g_v);
    cudaGetSymbolAddress((void**)&ap, g_attn);
    cudaGetSymbolAddress((void**)&pp, g_probs);
    cudaGetSymbolAddress((void**)&ip, g_topidx);
    cudaGetSymbolAddress((void**)&pvp, g_pval);
    cudaGetSymbolAddress((void**)&pip, g_pidx);
    cudaGetSymbolAddress((void**)&ahip, g_ahi);
    cudaGetSymbolAddress((void**)&alop, g_alo);
    cudaGetSymbolAddress((void**)&wthip, g_wthi);
    cudaGetSymbolAddress((void**)&wtlop, g_wtlo);

    const int SCORES_SMEM = (2048 + 2048 + 128 * 65 + 128 * 8) * 4 + 128 * 8 * 4;
    cudaFuncSetAttribute(scores_topk_kernel,
                         cudaFuncAttributeMaxDynamicSharedMemorySize, SCORES_SMEM);
    cudaFuncSetAttribute(gemm_mma_kernel,
                         cudaFuncAttributeMaxDynamicSharedMemorySize, GEMM_SMEM);

    const size_t WSZ = (size_t)DIM * DIM;
    const float* Ws[4] = {Wq, Wk, Wv, Wo};
    // FIX: W has (DIM/8)=128 n-tiles x 128 k-steps = 16384 atoms -> 2048 blocks
    for (int i = 0; i < 4; i++)
        split_pack_w<<<(DIM / 8) * KS8 / 8, 256>>>(
            Ws[i], (float2*)(wthip + i * WSZ), (float2*)(wtlop + i * WSZ));

    split_pack_a<<<(MROWS / 16) * KS8 / 8, 256>>>(S, (float4*)ahip, (float4*)alop);

    dim3 ggrid(DIM / 128, MROWS / 256);  // (8, 64)
    gemm_mma_kernel<<<ggrid, 256, GEMM_SMEM>>>(ahip, alop, wthip + 0 * WSZ, wtlop + 0 * WSZ, bq, qp);
    gemm_mma_kernel<<<ggrid, 256, GEMM_SMEM>>>(ahip, alop, wthip + 1 * WSZ, wtlop + 1 * WSZ, bk, kp);
    gemm_mma_kernel<<<ggrid, 256, GEMM_SMEM>>>(ahip, alop, wthip + 2 * WSZ, wtlop + 2 * WSZ, bv, vp);

    scores_topk_kernel<<<dim3(16, NQUART, BSZ), 256, SCORES_SMEM>>>(qp, kp, pvp, pip);
    merge_softmax_kernel<<<(MROWS + 255) / 256, 256>>>(pvp, pip, pp, ip);
    gather_kernel<<<MROWS, 128>>>(vp, pp, ip, ap);

    split_pack_a<<<(MROWS / 16) * KS8 / 8, 256>>>(ap, (float4*)ahip, (float4*)alop);
    gemm_mma_kernel<<<ggrid, 256, GEMM_SMEM>>>(ahip, alop, wthip + 3 * WSZ, wtlop + 3 * WSZ, bo, out);
}

// round 7
// speedup vs baseline: 2.1558x; 1.1961x over previous
#include <cuda_runtime.h>
#include <math.h>
#include <stdint.h>

#define BSZ   4
#define NSEQ  4096
#define DIM   1024
#define TOPK  8
#define MROWS (BSZ * NSEQ)
#define NQUART 4
#define KS8   (DIM / 8)   // 128 k-steps of 8

typedef unsigned long long ULL;

// ---------------- scratch (__device__ globals; no allocation allowed) -------
__device__ __align__(128) float g_q[(size_t)MROWS * DIM];
__device__ __align__(128) float g_k[(size_t)MROWS * DIM];
__device__ __align__(128) float g_v[(size_t)MROWS * DIM];
__device__ __align__(128) float g_attn[(size_t)MROWS * DIM];
__device__ float g_probs[(size_t)MROWS * TOPK];
__device__ int   g_topidx[(size_t)MROWS * TOPK];
__device__ float g_pval[(size_t)MROWS * NQUART * TOPK];
__device__ int   g_pidx[(size_t)MROWS * NQUART * TOPK];
// fragment-packed 3xTF32 buffers
__device__ __align__(128) float g_ahi[(size_t)MROWS * DIM];   // A-fmt (S / attn)
__device__ __align__(128) float g_alo[(size_t)MROWS * DIM];
__device__ __align__(128) float g_qhi[(size_t)MROWS * DIM];   // A-fmt (q)
__device__ __align__(128) float g_qlo[(size_t)MROWS * DIM];
__device__ __align__(128) float g_khi[(size_t)MROWS * DIM];   // B-fmt (k)
__device__ __align__(128) float g_klo[(size_t)MROWS * DIM];
__device__ __align__(128) float g_wthi[4][(size_t)DIM * DIM]; // B-fmt weights
__device__ __align__(128) float g_wtlo[4][(size_t)DIM * DIM];

// ---------------- helpers -----------------------------------------------------
__device__ __forceinline__ uint32_t smem_u32(const void* p) {
    uint32_t a;
    asm("{ .reg .u64 t; cvta.to.shared.u64 t, %1; cvt.u32.u64 %0, t; }"
        : "=r"(a) : "l"(p));
    return a;
}
__device__ __forceinline__ float tf32r(float x) {
    uint32_t u;
    asm("cvt.rna.tf32.f32 %0, %1;" : "=r"(u) : "f"(x));
    return __uint_as_float(u);
}
__device__ __forceinline__ void cpasync16(uint32_t saddr, const void* g) {
    asm volatile("cp.async.cg.shared.global [%0], [%1], 16;"
                 :: "r"(saddr), "l"(g));
}
#define CP_COMMIT() asm volatile("cp.async.commit_group;" ::: "memory")
#define CP_WAIT_1() asm volatile("cp.async.wait_group 1;" ::: "memory")
#define CP_WAIT_0() asm volatile("cp.async.wait_group 0;" ::: "memory")

__device__ __forceinline__ void mma8(float4& c, const uint4& a, const uint2& b) {
    asm volatile(
        "mma.sync.aligned.m16n8k8.row.col.f32.tf32.tf32.f32 "
        "{%0,%1,%2,%3}, {%4,%5,%6,%7}, {%8,%9}, {%0,%1,%2,%3};"
        : "+f"(c.x), "+f"(c.y), "+f"(c.z), "+f"(c.w)
        : "r"(a.x), "r"(a.y), "r"(a.z), "r"(a.w), "r"(b.x), "r"(b.y));
}

// ---------------- split+pack A-format: X[M,K] row-major ---------------------
// [M/16][K/8][lane][4]; a_r at row g+(r&1)*8, col t+(r>>1)*4 (g=lane>>2,t=lane&3)
__global__ __launch_bounds__(256) void split_pack_a(
    const float* __restrict__ X, float4* __restrict__ Phi, float4* __restrict__ Plo) {
    const int atom = blockIdx.x * 8 + (threadIdx.x >> 5);
    const int lane = threadIdx.x & 31;
    const int mt = atom >> 7;
    const int ks = atom & 127;
    const int g = lane >> 2, t = lane & 3;
    const size_t r0 = (size_t)(mt * 16 + g) * DIM + ks * 8 + t;
    const size_t r1 = r0 + 8 * DIM;
    float x0 = X[r0], x1 = X[r1], x2 = X[r0 + 4], x3 = X[r1 + 4];
    float4 h, l;
    h.x = tf32r(x0); l.x = tf32r(x0 - h.x);
    h.y = tf32r(x1); l.y = tf32r(x1 - h.y);
    h.z = tf32r(x2); l.z = tf32r(x2 - h.z);
    h.w = tf32r(x3); l.w = tf32r(x3 - h.w);
    Phi[(size_t)atom * 32 + lane] = h;
    Plo[(size_t)atom * 32 + lane] = l;
}

// ---------------- split+pack W (B-format): W[K,N] -> [N/8][K/8][lane][2] ----
__global__ __launch_bounds__(256) void split_pack_w(
    const float* __restrict__ W, float2* __restrict__ Phi, float2* __restrict__ Plo) {
    const int atom = blockIdx.x * 8 + (threadIdx.x >> 5);
    const int lane = threadIdx.x & 31;
    const int nt = atom >> 7;
    const int ks = atom & 127;
    const int g = lane >> 2, t = lane & 3;
    float x0 = W[(size_t)(ks * 8 + t) * DIM + nt * 8 + g];
    float x1 = W[(size_t)(ks * 8 + t + 4) * DIM + nt * 8 + g];
    float2 h, l;
    h.x = tf32r(x0); l.x = tf32r(x0 - h.x);
    h.y = tf32r(x1); l.y = tf32r(x1 - h.y);
    Phi[(size_t)atom * 32 + lane] = h;
    Plo[(size_t)atom * 32 + lane] = l;
}

// ---------------- split+pack K (B-format): X[Nrow,K] row-major --------------
// b_r = X[nt*8+g][ks*8+t+4r]
__global__ __launch_bounds__(256) void split_pack_kb(
    const float* __restrict__ X, float2* __restrict__ Phi, float2* __restrict__ Plo) {
    const int atom = blockIdx.x * 8 + (threadIdx.x >> 5);
    const int lane = threadIdx.x & 31;
    const int nt = atom >> 7;
    const int ks = atom & 127;
    const int g = lane >> 2, t = lane & 3;
    const size_t base = (size_t)(nt * 8 + g) * DIM + ks * 8 + t;
    float x0 = X[base];
    float x1 = X[base + 4];
    float2 h, l;
    h.x = tf32r(x0); l.x = tf32r(x0 - h.x);
    h.y = tf32r(x1); l.y = tf32r(x1 - h.y);
    Phi[(size_t)atom * 32 + lane] = h;
    Plo[(size_t)atom * 32 + lane] = l;
}

// ---------------- 3xTF32 mma.sync GEMM: C[M,N]=A@W+bias ---------------------
// Block 256(M)x128(N), BK=16, 8 warps of 64x64, 3-stage cp.async pipeline.
#define GEMM_SMEM (3 * 12288 * 4)

__global__ __launch_bounds__(256, 1) void gemm_mma_kernel(
    const float* __restrict__ Ahi, const float* __restrict__ Alo,
    const float* __restrict__ Bhi, const float* __restrict__ Blo,
    const float* __restrict__ bias, float* __restrict__ C) {
    extern __shared__ float sm[];
    const int tid = threadIdx.x;
    const int lane = tid & 31, wid = tid >> 5;
    const int wy = wid >> 1, wx = wid & 1;
    const int br16 = blockIdx.y * 16;
    const int bn16 = blockIdx.x * 16;
    const int m0 = blockIdx.y * 256;
    const int n0 = blockIdx.x * 128;
    const uint32_t smb = smem_u32(sm);

    auto load_stage = [&](int kc, int s) {
        const uint32_t sb = smb + s * 49152;
#pragma unroll
        for (int j = 0; j < 4; j++) {
            const int cA = tid + j * 256;
            const int mtl = cA >> 6, off = cA & 63;
            const uint32_t so = sb + (uint32_t)(mtl * 256 + off * 4) * 4;
            const size_t go = ((size_t)(br16 + mtl) * KS8 + kc * 2) * 128 + off * 4;
            cpasync16(so, Ahi + go);
            cpasync16(so + 4096 * 4, Alo + go);
        }
#pragma unroll
        for (int j = 0; j < 2; j++) {
            const int cB = tid + j * 256;
            const int ntl = cB >> 5, off = cB & 31;
            const uint32_t so = sb + (uint32_t)(8192 + ntl * 128 + off * 4) * 4;
            const size_t go = ((size_t)(bn16 + ntl) * KS8 + kc * 2) * 64 + off * 4;
            cpasync16(so, Bhi + go);
            cpasync16(so + 2048 * 4, Blo + go);
        }
    };

    load_stage(0, 0); CP_COMMIT();
    load_stage(1, 1); CP_COMMIT();

    float4 acc[4][8];
#pragma unroll
    for (int i = 0; i < 4; i++)
#pragma unroll
        for (int j = 0; j < 8; j++) acc[i][j] = make_float4(0.f, 0.f, 0.f, 0.f);

    for (int c = 0; c < 64; c++) {
        if (c < 62) { CP_WAIT_1(); } else { CP_WAIT_0(); }
        __syncthreads();
        if (c + 2 < 64) { load_stage(c + 2, (c + 2) % 3); CP_COMMIT(); }
        const float* st = sm + (c % 3) * 12288;
#pragma unroll
        for (int ks = 0; ks < 2; ks++) {
            uint4 Ah[4], Al[4];
            uint2 Bh[8], Bl[8];
#pragma unroll
            for (int i = 0; i < 4; i++) {
                const float* p = st + ((wy * 4 + i) * 2 + ks) * 128 + lane * 4;
                Ah[i] = *(const uint4*)p;
                Al[i] = *(const uint4*)(p + 4096);
            }
#pragma unroll
            for (int j = 0; j < 8; j++) {
                const float* p = st + 8192 + ((wx * 8 + j) * 2 + ks) * 64 + lane * 2;
                Bh[j] = *(const uint2*)p;
                Bl[j] = *(const uint2*)(p + 2048);
            }
#pragma unroll
            for (int i = 0; i < 4; i++)
#pragma unroll
                for (int j = 0; j < 8; j++) {
                    mma8(acc[i][j], Ah[i], Bh[j]);
                    mma8(acc[i][j], Ah[i], Bl[j]);
                    mma8(acc[i][j], Al[i], Bh[j]);
                }
        }
    }

    const int g = lane >> 2, t = lane & 3;
#pragma unroll
    for (int i = 0; i < 4; i++) {
        const int r0 = m0 + wy * 64 + i * 16 + g;
#pragma unroll
        for (int j = 0; j < 8; j++) {
            const int col = n0 + wx * 64 + j * 8 + t * 2;
            const float2 bb = *(const float2*)(bias + col);
            float2 o0 = {acc[i][j].x + bb.x, acc[i][j].y + bb.y};
            float2 o1 = {acc[i][j].z + bb.x, acc[i][j].w + bb.y};
            *(float2*)(C + (size_t)r0 * DIM + col) = o0;
            *(float2*)(C + (size_t)(r0 + 8) * DIM + col) = o1;
        }
    }
}

// ---------------- 3xTF32 mma.sync causal scores + streaming top-8 -----------
// Block = (pair, quarter, b); qt = pair & 31-pair; kt = quarter..qt step 4.
// 128q x 128k tile, 8 warps of 32x64 (wy 0..3, wx 0..1), BK=16, 3 stages.
// smem (floats): stages 3x8192 @0 | sc[128][72] @24576 | tval @33792 | tidx @34816
#define SC_SMEM ((3 * 8192 + 9216 + 1024 + 1024) * 4)

__global__ __launch_bounds__(256, 1) void scores_mma_kernel(
    const float* __restrict__ Qhi, const float* __restrict__ Qlo,
    const float* __restrict__ Khi, const float* __restrict__ Klo,
    float* __restrict__ pval, int* __restrict__ pidx) {
    extern __shared__ float sm[];
    float* sc = sm + 24576;           // [128][72]
    float* tval = sm + 33792;         // [128][8]
    int* tidx = (int*)(sm + 34816);   // [128][8]
    const uint32_t smb = smem_u32(sm);

    const int tid = threadIdx.x;
    const int lane = tid & 31, wid = tid >> 5;
    const int wy = wid >> 1, wx = wid & 1;
    const int g = lane >> 2, t = lane & 3;
    const int b = blockIdx.z;
    const int quarter = blockIdx.y;
    const int pair = blockIdx.x;  // 0..15

    for (int s = 0; s < 2; s++) {
        const int qt = (s == 0) ? pair : (31 - pair);
        const int q0 = qt * 128;
        const int mqb = (b * NSEQ + q0) >> 4;   // A atom base (8 atoms)

        for (int i = tid; i < 128 * TOPK; i += 256) {
            tval[i] = -INFINITY;
            tidx[i] = 0;
        }
        __syncthreads();

        for (int kt = quarter; kt <= qt; kt += NQUART) {
            const int k0 = kt * 128;
            const int nkb = (b * NSEQ + k0) >> 3;  // B atom base (16 atoms)

            auto load_stage = [&](int kc, int st) {
                const uint32_t sb = smb + st * 32768;
#pragma unroll
                for (int j = 0; j < 2; j++) {
                    const int cA = tid + j * 256;           // 0..511
                    const int mtl = cA >> 6, off = cA & 63;
                    const uint32_t so = sb + (uint32_t)(mtl * 256 + off * 4) * 4;
                    const size_t go = ((size_t)(mqb + mtl) * KS8 + kc * 2) * 128 + off * 4;
                    cpasync16(so, Qhi + go);
                    cpasync16(so + 8192, Qlo + go);
                }
#pragma unroll
                for (int j = 0; j < 2; j++) {
                    const int cB = tid + j * 256;           // 0..511
                    const int ntl = cB >> 5, off = cB & 31;
                    const uint32_t so = sb + 16384 + (uint32_t)(ntl * 128 + off * 4) * 4;
                    const size_t go = ((size_t)(nkb + ntl) * KS8 + kc * 2) * 64 + off * 4;
                    cpasync16(so, Khi + go);
                    cpasync16(so + 8192, Klo + go);
                }
            };

            load_stage(0, 0); CP_COMMIT();
            load_stage(1, 1); CP_COMMIT();

            float4 acc[2][8];
#pragma unroll
            for (int i = 0; i < 2; i++)
#pragma unroll
                for (int j = 0; j < 8; j++) acc[i][j] = make_float4(0.f, 0.f, 0.f, 0.f);

            for (int c = 0; c < 64; c++) {
                if (c < 62) { CP_WAIT_1(); } else { CP_WAIT_0(); }
                __syncthreads();
                if (c + 2 < 64) { load_stage(c + 2, (c + 2) % 3); CP_COMMIT(); }
                const float* st = sm + (c % 3) * 8192;
#pragma unroll
                for (int ks = 0; ks < 2; ks++) {
                    uint4 Ah[2], Al[2];
                    uint2 Bh[8], Bl[8];
#pragma unroll
                    for (int i = 0; i < 2; i++) {
                        const float* p = st + ((wy * 2 + i) * 2 + ks) * 128 + lane * 4;
                        Ah[i] = *(const uint4*)p;
                        Al[i] = *(const uint4*)(p + 2048);
                    }
#pragma unroll
                    for (int j = 0; j < 8; j++) {
                        const float* p = st + 4096 + ((wx * 8 + j) * 2 + ks) * 64 + lane * 2;
                        Bh[j] = *(const uint2*)p;
                        Bl[j] = *(const uint2*)(p + 2048);
                    }
#pragma unroll
                    for (int i = 0; i < 2; i++)
#pragma unroll
                        for (int j = 0; j < 8; j++) {
                            mma8(acc[i][j], Ah[i], Bh[j]);
                            mma8(acc[i][j], Ah[i], Bl[j]);
                            mma8(acc[i][j], Al[i], Bh[j]);
                        }
                }
            }

            // two half passes: warps with wx==h stage their 64 cols
#pragma unroll
            for (int h = 0; h < 2; h++) {
                if (wx == h) {
#pragma unroll
                    for (int i = 0; i < 2; i++) {
                        const int r0 = wy * 32 + i * 16 + g;
#pragma unroll
                        for (int j = 0; j < 8; j++) {
                            const int col = j * 8 + t * 2;          // local 0..63
                            const int gc = k0 + h * 64 + col;
                            float v0 = acc[i][j].x * 0.03125f;
                            float v1 = acc[i][j].y * 0.03125f;
                            float v2 = acc[i][j].z * 0.03125f;
                            float v3 = acc[i][j].w * 0.03125f;
                            const int gr0 = q0 + r0, gr1 = gr0 + 8;
                            if (gc + 0 > gr0) v0 = -INFINITY;
                            if (gc + 1 > gr0) v1 = -INFINITY;
                            if (gc + 0 > gr1) v2 = -INFINITY;
                            if (gc + 1 > gr1) v3 = -INFINITY;
                            *(float2*)&sc[r0 * 72 + col] = make_float2(v0, v1);
                            *(float2*)&sc[(r0 + 8) * 72 + col] = make_float2(v2, v3);
                        }
                    }
                }
                __syncthreads();
                if (tid < 128) {
                    float tv[TOPK]; int ti[TOPK];
#pragma unroll
                    for (int j = 0; j < TOPK; j++) { tv[j] = tval[tid * 8 + j]; ti[j] = tidx[tid * 8 + j]; }
                    float vmin = tv[0]; int mpos = 0;
#pragma unroll
                    for (int j = 1; j < TOPK; j++) if (tv[j] < vmin) { vmin = tv[j]; mpos = j; }
                    const int cbase = k0 + h * 64;
                    for (int cc = 0; cc < 64; cc++) {
                        const float vv = sc[tid * 72 + cc];
                        if (vv > vmin) {
                            tv[mpos] = vv; ti[mpos] = cbase + cc;
                            vmin = tv[0]; mpos = 0;
#pragma unroll
                            for (int j = 1; j < TOPK; j++) if (tv[j] < vmin) { vmin = tv[j]; mpos = j; }
                        }
                    }
#pragma unroll
                    for (int j = 0; j < TOPK; j++) { tval[tid * 8 + j] = tv[j]; tidx[tid * 8 + j] = ti[j]; }
                }
                __syncthreads();
            }
        }

        if (tid < 128) {
            const int row = b * NSEQ + q0 + tid;
            const size_t base = ((size_t)row * NQUART + quarter) * TOPK;
#pragma unroll
            for (int j = 0; j < TOPK; j++) {
                pval[base + j] = tval[tid * 8 + j];
                pidx[base + j] = tidx[tid * 8 + j];
            }
        }
        __syncthreads();
    }
}

// ---------------- merge NQUART partial top-8 lists + softmax ----------------
__global__ __launch_bounds__(256) void merge_softmax_kernel(
    const float* __restrict__ pv, const int* __restrict__ pi,
    float* __restrict__ probs, int* __restrict__ idxs) {
    const int row = blockIdx.x * 256 + threadIdx.x;
    if (row >= MROWS) return;
    const int NC = NQUART * TOPK;
    float v[NC]; int id[NC];
#pragma unroll
    for (int j = 0; j < NC; j++) {
        v[j] = pv[(size_t)row * NC + j];
        id[j] = pi[(size_t)row * NC + j];
    }
    float tv[TOPK]; int ti[TOPK];
#pragma unroll
    for (int t = 0; t < TOPK; t++) {
        int m = 0; float best = v[0];
#pragma unroll
        for (int j = 1; j < NC; j++) if (v[j] > best) { best = v[j]; m = j; }
        tv[t] = best; ti[t] = id[m]; v[m] = -INFINITY;
    }
    float mx = tv[0];
#pragma unroll
    for (int j = 1; j < TOPK; j++) mx = fmaxf(mx, tv[j]);
    float e[TOPK]; float ssum = 0.f;
#pragma unroll
    for (int j = 0; j < TOPK; j++) { e[j] = expf(tv[j] - mx); ssum += e[j]; }
    const float inv = 1.f / ssum;
    const size_t base = (size_t)row * TOPK;
#pragma unroll
    for (int j = 0; j < TOPK; j++) { probs[base + j] = e[j] * inv; idxs[base + j] = ti[j]; }
}

// ---------------- sparse AV gather ------------------------------------------
__global__ __launch_bounds__(128) void gather_kernel(
    const float* __restrict__ v, const float* __restrict__ probs,
    const int* __restrict__ idxs, float* __restrict__ out) {
    const int row = blockIdx.x;
    const int b = row >> 12;
    const int tid = threadIdx.x;
    __shared__ float p[TOPK];
    __shared__ int   id[TOPK];
    if (tid < TOPK) {
        p[tid]  = probs[(size_t)row * TOPK + tid];
        id[tid] = idxs[(size_t)row * TOPK + tid];
    }
    __syncthreads();
    const float* vb = v + (size_t)b * NSEQ * DIM;
    const int c = tid * 8;
    float4 a0 = {0.f, 0.f, 0.f, 0.f}, a1 = {0.f, 0.f, 0.f, 0.f};
#pragma unroll
    for (int j = 0; j < TOPK; j++) {
        const float4* vr = (const float4*)(vb + (size_t)id[j] * DIM + c);
        const float pj = p[j];
        float4 v0 = vr[0], v1 = vr[1];
        a0.x += pj * v0.x; a0.y += pj * v0.y; a0.z += pj * v0.z; a0.w += pj * v0.w;
        a1.x += pj * v1.x; a1.y += pj * v1.y; a1.z += pj * v1.z; a1.w += pj * v1.w;
    }
    float4* orow = (float4*)(out + (size_t)row * DIM + c);
    orow[0] = a0; orow[1] = a1;
}

// ---------------- launch -----------------------------------------------------
extern "C" void kernel_launch(void* const* d_in, const int* in_sizes, int n_in,
                              void* d_out, int out_size) {
    const float* S  = (const float*)d_in[0];
    const float* Wq = (const float*)d_in[1];
    const float* bq = (const float*)d_in[2];
    const float* Wk = (const float*)d_in[3];
    const float* bk = (const float*)d_in[4];
    const float* Wv = (const float*)d_in[5];
    const float* bv = (const float*)d_in[6];
    const float* Wo = (const float*)d_in[7];
    const float* bo = (const float*)d_in[8];
    float* out = (float*)d_out;

    float *qp, *kp, *vp, *ap, *pp, *pvp, *ahip, *alop, *wthip, *wtlop;
    float *qhip, *qlop, *khip, *klop;
    int *ip, *pip;
    cudaGetSymbolAddress((void**)&qp, g_q);
    cudaGetSymbolAddress((void**)&kp, g_k);
    cudaGetSymbolAddress((void**)&vp, g_v);
    cudaGetSymbolAddress((void**)&ap, g_attn);
    cudaGetSymbolAddress((void**)&pp, g_probs);
    cudaGetSymbolAddress((void**)&ip, g_topidx);
    cudaGetSymbolAddress((void**)&pvp, g_pval);
    cudaGetSymbolAddress((void**)&pip, g_pidx);
    cudaGetSymbolAddress((void**)&ahip, g_ahi);
    cudaGetSymbolAddress((void**)&alop, g_alo);
    cudaGetSymbolAddress((void**)&qhip, g_qhi);
    cudaGetSymbolAddress((void**)&qlop, g_qlo);
    cudaGetSymbolAddress((void**)&khip, g_khi);
    cudaGetSymbolAddress((void**)&klop, g_klo);
    cudaGetSymbolAddress((void**)&wthip, g_wthi);
    cudaGetSymbolAddress((void**)&wtlop, g_wtlo);

    cudaFuncSetAttribute(gemm_mma_kernel,
                         cudaFuncAttributeMaxDynamicSharedMemorySize, GEMM_SMEM);
    cudaFuncSetAttribute(scores_mma_kernel,
                         cudaFuncAttributeMaxDynamicSharedMemorySize, SC_SMEM);

    const size_t WSZ = (size_t)DIM * DIM;
    const float* Ws[4] = {Wq, Wk, Wv, Wo};
    for (int i = 0; i < 4; i++)
        split_pack_w<<<(DIM / 8) * KS8 / 8, 256>>>(
            Ws[i], (float2*)(wthip + i * WSZ), (float2*)(wtlop + i * WSZ));

    split_pack_a<<<(MROWS / 16) * KS8 / 8, 256>>>(S, (float4*)ahip, (float4*)alop);

    dim3 ggrid(DIM / 128, MROWS / 256);  // (8, 64)
    gemm_mma_kernel<<<ggrid, 256, GEMM_SMEM>>>(ahip, alop, wthip + 0 * WSZ, wtlop + 0 * WSZ, bq, qp);
    gemm_mma_kernel<<<ggrid, 256, GEMM_SMEM>>>(ahip, alop, wthip + 1 * WSZ, wtlop + 1 * WSZ, bk, kp);
    gemm_mma_kernel<<<ggrid, 256, GEMM_SMEM>>>(ahip, alop, wthip + 2 * WSZ, wtlop + 2 * WSZ, bv, vp);

    // pack q (A-format) and k (B-format) for the scores MMA
    split_pack_a<<<(MROWS / 16) * KS8 / 8, 256>>>(qp, (float4*)qhip, (float4*)qlop);
    split_pack_kb<<<(MROWS / 8) * KS8 / 8, 256>>>(kp, (float2*)khip, (float2*)klop);

    scores_mma_kernel<<<dim3(16, NQUART, BSZ), 256, SC_SMEM>>>(
        qhip, qlop, khip, klop, pvp, pip);
    merge_softmax_kernel<<<(MROWS + 255) / 256, 256>>>(pvp, pip, pp, ip);
    gather_kernel<<<MROWS, 128>>>(vp, pp, ip, ap);

    split_pack_a<<<(MROWS / 16) * KS8 / 8, 256>>>(ap, (float4*)ahip, (float4*)alop);
    gemm_mma_kernel<<<ggrid, 256, GEMM_SMEM>>>(ahip, alop, wthip + 3 * WSZ, wtlop + 3 * WSZ, bo, out);
}

// round 8
// speedup vs baseline: 2.3112x; 1.0721x over previous
#include <cuda_runtime.h>
#include <math.h>
#include <stdint.h>

#define BSZ   4
#define NSEQ  4096
#define DIM   1024
#define TOPK  8
#define MROWS (BSZ * NSEQ)
#define KS8   (DIM / 8)   // 128 k-steps of 8
#define NQT   32          // 128-row tiles per batch
#define NTRI  (NQT * (NQT + 1) / 2)   // 528 causal tiles per batch

typedef unsigned long long ULL;

// ---------------- scratch (__device__ globals; no allocation allowed) -------
__device__ __align__(128) float g_q[(size_t)MROWS * DIM];
__device__ __align__(128) float g_k[(size_t)MROWS * DIM];
__device__ __align__(128) float g_v[(size_t)MROWS * DIM];
__device__ __align__(128) float g_attn[(size_t)MROWS * DIM];
__device__ float g_probs[(size_t)MROWS * TOPK];
__device__ int   g_topidx[(size_t)MROWS * TOPK];
__device__ float g_pval[(size_t)BSZ * NTRI * 128 * TOPK];
__device__ int   g_pidx[(size_t)BSZ * NTRI * 128 * TOPK];
// fragment-packed 3xTF32 buffers
__device__ __align__(128) float g_ahi[(size_t)MROWS * DIM];   // A-fmt (S / attn)
__device__ __align__(128) float g_alo[(size_t)MROWS * DIM];
__device__ __align__(128) float g_qhi[(size_t)MROWS * DIM];   // A-fmt (q)
__device__ __align__(128) float g_qlo[(size_t)MROWS * DIM];
__device__ __align__(128) float g_khi[(size_t)MROWS * DIM];   // B-fmt (k)
__device__ __align__(128) float g_klo[(size_t)MROWS * DIM];
__device__ __align__(128) float g_wthi[3][(size_t)DIM * DIM]; // B-fmt Wq/Wk/Wv
__device__ __align__(128) float g_wtlo[3][(size_t)DIM * DIM];
__device__ __align__(128) float g_wohi[(size_t)DIM * DIM];    // B-fmt Wo
__device__ __align__(128) float g_wolo[(size_t)DIM * DIM];

// ---------------- helpers -----------------------------------------------------
__device__ __forceinline__ uint32_t smem_u32(const void* p) {
    uint32_t a;
    asm("{ .reg .u64 t; cvta.to.shared.u64 t, %1; cvt.u32.u64 %0, t; }"
        : "=r"(a) : "l"(p));
    return a;
}
__device__ __forceinline__ float tf32r(float x) {
    uint32_t u;
    asm("cvt.rna.tf32.f32 %0, %1;" : "=r"(u) : "f"(x));
    return __uint_as_float(u);
}
__device__ __forceinline__ void cpasync16(uint32_t saddr, const void* g) {
    asm volatile("cp.async.cg.shared.global [%0], [%1], 16;"
                 :: "r"(saddr), "l"(g));
}
#define CP_COMMIT() asm volatile("cp.async.commit_group;" ::: "memory")
#define CP_WAIT_1() asm volatile("cp.async.wait_group 1;" ::: "memory")
#define CP_WAIT_0() asm volatile("cp.async.wait_group 0;" ::: "memory")

__device__ __forceinline__ void mma8(float4& c, const uint4& a, const uint2& b) {
    asm volatile(
        "mma.sync.aligned.m16n8k8.row.col.f32.tf32.tf32.f32 "
        "{%0,%1,%2,%3}, {%4,%5,%6,%7}, {%8,%9}, {%0,%1,%2,%3};"
        : "+f"(c.x), "+f"(c.y), "+f"(c.z), "+f"(c.w)
        : "r"(a.x), "r"(a.y), "r"(a.z), "r"(a.w), "r"(b.x), "r"(b.y));
}

// ---------------- split+pack A-format: X[M,K] row-major ---------------------
__global__ __launch_bounds__(256) void split_pack_a(
    const float* __restrict__ X, float4* __restrict__ Phi, float4* __restrict__ Plo) {
    const int atom = blockIdx.x * 8 + (threadIdx.x >> 5);
    const int lane = threadIdx.x & 31;
    const int mt = atom >> 7;
    const int ks = atom & 127;
    const int g = lane >> 2, t = lane & 3;
    const size_t r0 = (size_t)(mt * 16 + g) * DIM + ks * 8 + t;
    const size_t r1 = r0 + 8 * DIM;
    float x0 = X[r0], x1 = X[r1], x2 = X[r0 + 4], x3 = X[r1 + 4];
    float4 h, l;
    h.x = tf32r(x0); l.x = tf32r(x0 - h.x);
    h.y = tf32r(x1); l.y = tf32r(x1 - h.y);
    h.z = tf32r(x2); l.z = tf32r(x2 - h.z);
    h.w = tf32r(x3); l.w = tf32r(x3 - h.w);
    Phi[(size_t)atom * 32 + lane] = h;
    Plo[(size_t)atom * 32 + lane] = l;
}

// ---------------- split+pack W (B-format): W[K,N] -> [N/8][K/8][lane][2] ----
__global__ __launch_bounds__(256) void split_pack_w(
    const float* __restrict__ W, float2* __restrict__ Phi, float2* __restrict__ Plo) {
    const int atom = blockIdx.x * 8 + (threadIdx.x >> 5);
    const int lane = threadIdx.x & 31;
    const int nt = atom >> 7;
    const int ks = atom & 127;
    const int g = lane >> 2, t = lane & 3;
    float x0 = W[(size_t)(ks * 8 + t) * DIM + nt * 8 + g];
    float x1 = W[(size_t)(ks * 8 + t + 4) * DIM + nt * 8 + g];
    float2 h, l;
    h.x = tf32r(x0); l.x = tf32r(x0 - h.x);
    h.y = tf32r(x1); l.y = tf32r(x1 - h.y);
    Phi[(size_t)atom * 32 + lane] = h;
    Plo[(size_t)atom * 32 + lane] = l;
}

// ---------------- split+pack K (B-format): X[Nrow,K] row-major --------------
__global__ __launch_bounds__(256) void split_pack_kb(
    const float* __restrict__ X, float2* __restrict__ Phi, float2* __restrict__ Plo) {
    const int atom = blockIdx.x * 8 + (threadIdx.x >> 5);
    const int lane = threadIdx.x & 31;
    const int nt = atom >> 7;
    const int ks = atom & 127;
    const int g = lane >> 2, t = lane & 3;
    const size_t base = (size_t)(nt * 8 + g) * DIM + ks * 8 + t;
    float x0 = X[base];
    float x1 = X[base + 4];
    float2 h, l;
    h.x = tf32r(x0); l.x = tf32r(x0 - h.x);
    h.y = tf32r(x1); l.y = tf32r(x1 - h.y);
    Phi[(size_t)atom * 32 + lane] = h;
    Plo[(size_t)atom * 32 + lane] = l;
}

// ---------------- GEMM core (shared by QKV-fused and single) ----------------
// Block 256(M)x128(N), BK=16, 8 warps of 64x64, 3-stage cp.async pipeline.
#define GEMM_SMEM (3 * 12288 * 4)

__device__ __forceinline__ void gemm_body(
    float* sm, const float* __restrict__ Ahi, const float* __restrict__ Alo,
    const float* __restrict__ Bhi, const float* __restrict__ Blo,
    const float* __restrict__ bias, float* __restrict__ C,
    int br16, int bn16, int m0, int n0) {
    const int tid = threadIdx.x;
    const int lane = tid & 31, wid = tid >> 5;
    const int wy = wid >> 1, wx = wid & 1;
    const uint32_t smb = smem_u32(sm);

    auto load_stage = [&](int kc, int s) {
        const uint32_t sb = smb + s * 49152;
#pragma unroll
        for (int j = 0; j < 4; j++) {
            const int cA = tid + j * 256;
            const int mtl = cA >> 6, off = cA & 63;
            const uint32_t so = sb + (uint32_t)(mtl * 256 + off * 4) * 4;
            const size_t go = ((size_t)(br16 + mtl) * KS8 + kc * 2) * 128 + off * 4;
            cpasync16(so, Ahi + go);
            cpasync16(so + 4096 * 4, Alo + go);
        }
#pragma unroll
        for (int j = 0; j < 2; j++) {
            const int cB = tid + j * 256;
            const int ntl = cB >> 5, off = cB & 31;
            const uint32_t so = sb + (uint32_t)(8192 + ntl * 128 + off * 4) * 4;
            const size_t go = ((size_t)(bn16 + ntl) * KS8 + kc * 2) * 64 + off * 4;
            cpasync16(so, Bhi + go);
            cpasync16(so + 2048 * 4, Blo + go);
        }
    };

    load_stage(0, 0); CP_COMMIT();
    load_stage(1, 1); CP_COMMIT();

    float4 acc[4][8];
#pragma unroll
    for (int i = 0; i < 4; i++)
#pragma unroll
        for (int j = 0; j < 8; j++) acc[i][j] = make_float4(0.f, 0.f, 0.f, 0.f);

    for (int c = 0; c < 64; c++) {
        if (c < 62) { CP_WAIT_1(); } else { CP_WAIT_0(); }
        __syncthreads();
        if (c + 2 < 64) { load_stage(c + 2, (c + 2) % 3); CP_COMMIT(); }
        const float* st = sm + (c % 3) * 12288;
#pragma unroll
        for (int ks = 0; ks < 2; ks++) {
            uint4 Ah[4], Al[4];
            uint2 Bh[8], Bl[8];
#pragma unroll
            for (int i = 0; i < 4; i++) {
                const float* p = st + ((wy * 4 + i) * 2 + ks) * 128 + lane * 4;
                Ah[i] = *(const uint4*)p;
                Al[i] = *(const uint4*)(p + 4096);
            }
#pragma unroll
            for (int j = 0; j < 8; j++) {
                const float* p = st + 8192 + ((wx * 8 + j) * 2 + ks) * 64 + lane * 2;
                Bh[j] = *(const uint2*)p;
                Bl[j] = *(const uint2*)(p + 2048);
            }
#pragma unroll
            for (int i = 0; i < 4; i++)
#pragma unroll
                for (int j = 0; j < 8; j++) {
                    mma8(acc[i][j], Ah[i], Bh[j]);
                    mma8(acc[i][j], Ah[i], Bl[j]);
                    mma8(acc[i][j], Al[i], Bh[j]);
                }
        }
    }

    const int g = lane >> 2, t = lane & 3;
#pragma unroll
    for (int i = 0; i < 4; i++) {
        const int r0 = m0 + wy * 64 + i * 16 + g;
#pragma unroll
        for (int j = 0; j < 8; j++) {
            const int col = n0 + wx * 64 + j * 8 + t * 2;
            const float2 bb = *(const float2*)(bias + col);
            float2 o0 = {acc[i][j].x + bb.x, acc[i][j].y + bb.y};
            float2 o1 = {acc[i][j].z + bb.x, acc[i][j].w + bb.y};
            *(float2*)(C + (size_t)r0 * DIM + col) = o0;
            *(float2*)(C + (size_t)(r0 + 8) * DIM + col) = o1;
        }
    }
}

// Fused Q/K/V projection: grid (24, 64); bx%3 selects weight/bias/output.
__global__ __launch_bounds__(256, 1) void gemm_qkv_kernel(
    const float* __restrict__ Ahi, const float* __restrict__ Alo,
    const float* __restrict__ Whi, const float* __restrict__ Wlo,
    const float* __restrict__ bq, const float* __restrict__ bk,
    const float* __restrict__ bv,
    float* __restrict__ Q, float* __restrict__ K, float* __restrict__ V) {
    extern __shared__ float sm[];
    const int wsel = blockIdx.x % 3;
    const int nxt = blockIdx.x / 3;   // 0..7
    const float* Bhi = Whi + (size_t)wsel * DIM * DIM;
    const float* Blo = Wlo + (size_t)wsel * DIM * DIM;
    const float* bias = (wsel == 0) ? bq : ((wsel == 1) ? bk : bv);
    float* C = (wsel == 0) ? Q : ((wsel == 1) ? K : V);
    gemm_body(sm, Ahi, Alo, Bhi, Blo, bias, C,
              blockIdx.y * 16, nxt * 16, blockIdx.y * 256, nxt * 128);
}

// Single GEMM (output projection): grid (8, 64).
__global__ __launch_bounds__(256, 1) void gemm_mma_kernel(
    const float* __restrict__ Ahi, const float* __restrict__ Alo,
    const float* __restrict__ Bhi, const float* __restrict__ Blo,
    const float* __restrict__ bias, float* __restrict__ C) {
    extern __shared__ float sm[];
    gemm_body(sm, Ahi, Alo, Bhi, Blo, bias, C,
              blockIdx.y * 16, blockIdx.x * 16, blockIdx.y * 256, blockIdx.x * 128);
}

// ---------------- per-tile 3xTF32 causal scores + tile top-8 ----------------
// grid (NTRI, BSZ): one 128q x 128k tile per block (triangular decode).
// smem (floats): stages 3x8192 @0 | sc[128][72] @24576 | tval @33792 | tidx @34816
#define SC_SMEM ((3 * 8192 + 9216 + 1024 + 1024) * 4)

__global__ __launch_bounds__(256, 1) void scores_tile_kernel(
    const float* __restrict__ Qhi, const float* __restrict__ Qlo,
    const float* __restrict__ Khi, const float* __restrict__ Klo,
    float* __restrict__ pval, int* __restrict__ pidx) {
    extern __shared__ float sm[];
    float* sc = sm + 24576;           // [128][72]
    float* tval = sm + 33792;         // [128][8]
    int* tidx = (int*)(sm + 34816);   // [128][8]
    const uint32_t smb = smem_u32(sm);

    const int tid = threadIdx.x;
    const int lane = tid & 31, wid = tid >> 5;
    const int wy = wid >> 1, wx = wid & 1;
    const int g = lane >> 2, t = lane & 3;
    const int b = blockIdx.y;
    const int tri = blockIdx.x;

    int qt = (int)((sqrtf(8.0f * (float)tri + 1.0f) - 1.0f) * 0.5f);
    while ((qt + 1) * (qt + 2) / 2 <= tri) qt++;
    while (qt * (qt + 1) / 2 > tri) qt--;
    const int kt = tri - qt * (qt + 1) / 2;
    const int q0 = qt * 128, k0 = kt * 128;
    const int mqb = (b * NSEQ + q0) >> 4;   // A atom base (8 atoms)
    const int nkb = (b * NSEQ + k0) >> 3;   // B atom base (16 atoms)

    for (int i = tid; i < 128 * TOPK; i += 256) {
        tval[i] = -INFINITY;
        tidx[i] = 0;
    }

    auto load_stage = [&](int kc, int st) {
        const uint32_t sb = smb + st * 32768;
#pragma unroll
        for (int j = 0; j < 2; j++) {
            const int cA = tid + j * 256;
            const int mtl = cA >> 6, off = cA & 63;
            const uint32_t so = sb + (uint32_t)(mtl * 256 + off * 4) * 4;
            const size_t go = ((size_t)(mqb + mtl) * KS8 + kc * 2) * 128 + off * 4;
            cpasync16(so, Qhi + go);
            cpasync16(so + 8192, Qlo + go);
        }
#pragma unroll
        for (int j = 0; j < 2; j++) {
            const int cB = tid + j * 256;
            const int ntl = cB >> 5, off = cB & 31;
            const uint32_t so = sb + 16384 + (uint32_t)(ntl * 128 + off * 4) * 4;
            const size_t go = ((size_t)(nkb + ntl) * KS8 + kc * 2) * 64 + off * 4;
            cpasync16(so, Khi + go);
            cpasync16(so + 8192, Klo + go);
        }
    };

    load_stage(0, 0); CP_COMMIT();
    load_stage(1, 1); CP_COMMIT();

    float4 acc[2][8];
#pragma unroll
    for (int i = 0; i < 2; i++)
#pragma unroll
        for (int j = 0; j < 8; j++) acc[i][j] = make_float4(0.f, 0.f, 0.f, 0.f);

    for (int c = 0; c < 64; c++) {
        if (c < 62) { CP_WAIT_1(); } else { CP_WAIT_0(); }
        __syncthreads();
        if (c + 2 < 64) { load_stage(c + 2, (c + 2) % 3); CP_COMMIT(); }
        const float* st = sm + (c % 3) * 8192;
#pragma unroll
        for (int ks = 0; ks < 2; ks++) {
            uint4 Ah[2], Al[2];
            uint2 Bh[8], Bl[8];
#pragma unroll
            for (int i = 0; i < 2; i++) {
                const float* p = st + ((wy * 2 + i) * 2 + ks) * 128 + lane * 4;
                Ah[i] = *(const uint4*)p;
                Al[i] = *(const uint4*)(p + 2048);
            }
#pragma unroll
            for (int j = 0; j < 8; j++) {
                const float* p = st + 4096 + ((wx * 8 + j) * 2 + ks) * 64 + lane * 2;
                Bh[j] = *(const uint2*)p;
                Bl[j] = *(const uint2*)(p + 2048);
            }
#pragma unroll
            for (int i = 0; i < 2; i++)
#pragma unroll
                for (int j = 0; j < 8; j++) {
                    mma8(acc[i][j], Ah[i], Bh[j]);
                    mma8(acc[i][j], Ah[i], Bl[j]);
                    mma8(acc[i][j], Al[i], Bh[j]);
                }
        }
    }

    // two half passes: warps with wx==h stage their 64 cols; 128 threads merge
#pragma unroll
    for (int h = 0; h < 2; h++) {
        if (wx == h) {
#pragma unroll
            for (int i = 0; i < 2; i++) {
                const int r0 = wy * 32 + i * 16 + g;
#pragma unroll
                for (int j = 0; j < 8; j++) {
                    const int col = j * 8 + t * 2;
                    const int gc = k0 + h * 64 + col;
                    float v0 = acc[i][j].x * 0.03125f;
                    float v1 = acc[i][j].y * 0.03125f;
                    float v2 = acc[i][j].z * 0.03125f;
                    float v3 = acc[i][j].w * 0.03125f;
                    const int gr0 = q0 + r0, gr1 = gr0 + 8;
                    if (gc + 0 > gr0) v0 = -INFINITY;
                    if (gc + 1 > gr0) v1 = -INFINITY;
                    if (gc + 0 > gr1) v2 = -INFINITY;
                    if (gc + 1 > gr1) v3 = -INFINITY;
                    *(float2*)&sc[r0 * 72 + col] = make_float2(v0, v1);
                    *(float2*)&sc[(r0 + 8) * 72 + col] = make_float2(v2, v3);
                }
            }
        }
        __syncthreads();
        if (tid < 128) {
            float tv[TOPK]; int ti[TOPK];
#pragma unroll
            for (int j = 0; j < TOPK; j++) { tv[j] = tval[tid * 8 + j]; ti[j] = tidx[tid * 8 + j]; }
            float vmin = tv[0]; int mpos = 0;
#pragma unroll
            for (int j = 1; j < TOPK; j++) if (tv[j] < vmin) { vmin = tv[j]; mpos = j; }
            const int cbase = k0 + h * 64;
            for (int cc = 0; cc < 64; cc++) {
                const float vv = sc[tid * 72 + cc];
                if (vv > vmin) {
                    tv[mpos] = vv; ti[mpos] = cbase + cc;
                    vmin = tv[0]; mpos = 0;
#pragma unroll
                    for (int j = 1; j < TOPK; j++) if (tv[j] < vmin) { vmin = tv[j]; mpos = j; }
                }
            }
#pragma unroll
            for (int j = 0; j < TOPK; j++) { tval[tid * 8 + j] = tv[j]; tidx[tid * 8 + j] = ti[j]; }
        }
        __syncthreads();
    }

    if (tid < 128) {
        const size_t base = (((size_t)b * NTRI + tri) * 128 + tid) * TOPK;
#pragma unroll
        for (int j = 0; j < TOPK; j++) {
            pval[base + j] = tval[tid * 8 + j];
            pidx[base + j] = tidx[tid * 8 + j];
        }
    }
}

// ---------------- merge per-row partial top-8 lists + softmax ----------------
__global__ __launch_bounds__(256) void merge_softmax_kernel(
    const float* __restrict__ pv, const int* __restrict__ pi,
    float* __restrict__ probs, int* __restrict__ idxs) {
    const int row = blockIdx.x * 256 + threadIdx.x;
    if (row >= MROWS) return;
    const int b = row >> 12, rr = row & 4095;
    const int qt = rr >> 7, ri = rr & 127;
    const size_t tbase = ((size_t)b * NTRI + (size_t)qt * (qt + 1) / 2) * 128 + ri;

    float tv[TOPK]; int ti[TOPK];
#pragma unroll
    for (int j = 0; j < TOPK; j++) { tv[j] = -INFINITY; ti[j] = 0; }
    float vmin = -INFINITY; int mpos = 0;

    for (int kt = 0; kt <= qt; kt++) {
        const size_t base = (tbase + (size_t)kt * 128) * TOPK;
#pragma unroll
        for (int j = 0; j < TOPK; j++) {
            const float vv = pv[base + j];
            if (vv > vmin) {
                tv[mpos] = vv; ti[mpos] = pi[base + j];
                vmin = tv[0]; mpos = 0;
#pragma unroll
                for (int q = 1; q < TOPK; q++) if (tv[q] < vmin) { vmin = tv[q]; mpos = q; }
            }
        }
    }

    float mx = tv[0];
#pragma unroll
    for (int j = 1; j < TOPK; j++) mx = fmaxf(mx, tv[j]);
    float e[TOPK]; float ssum = 0.f;
#pragma unroll
    for (int j = 0; j < TOPK; j++) { e[j] = expf(tv[j] - mx); ssum += e[j]; }
    const float inv = 1.f / ssum;
    const size_t obase = (size_t)row * TOPK;
#pragma unroll
    for (int j = 0; j < TOPK; j++) { probs[obase + j] = e[j] * inv; idxs[obase + j] = ti[j]; }
}

// ---------------- sparse AV gather ------------------------------------------
__global__ __launch_bounds__(128) void gather_kernel(
    const float* __restrict__ v, const float* __restrict__ probs,
    const int* __restrict__ idxs, float* __restrict__ out) {
    const int row = blockIdx.x;
    const int b = row >> 12;
    const int tid = threadIdx.x;
    __shared__ float p[TOPK];
    __shared__ int   id[TOPK];
    if (tid < TOPK) {
        p[tid]  = probs[(size_t)row * TOPK + tid];
        id[tid] = idxs[(size_t)row * TOPK + tid];
    }
    __syncthreads();
    const float* vb = v + (size_t)b * NSEQ * DIM;
    const int c = tid * 8;
    float4 a0 = {0.f, 0.f, 0.f, 0.f}, a1 = {0.f, 0.f, 0.f, 0.f};
#pragma unroll
    for (int j = 0; j < TOPK; j++) {
        const float4* vr = (const float4*)(vb + (size_t)id[j] * DIM + c);
        const float pj = p[j];
        float4 v0 = vr[0], v1 = vr[1];
        a0.x += pj * v0.x; a0.y += pj * v0.y; a0.z += pj * v0.z; a0.w += pj * v0.w;
        a1.x += pj * v1.x; a1.y += pj * v1.y; a1.z += pj * v1.z; a1.w += pj * v1.w;
    }
    float4* orow = (float4*)(out + (size_t)row * DIM + c);
    orow[0] = a0; orow[1] = a1;
}

// ---------------- launch -----------------------------------------------------
extern "C" void kernel_launch(void* const* d_in, const int* in_sizes, int n_in,
                              void* d_out, int out_size) {
    const float* S  = (const float*)d_in[0];
    const float* Wq = (const float*)d_in[1];
    const float* bq = (const float*)d_in[2];
    const float* Wk = (const float*)d_in[3];
    const float* bk = (const float*)d_in[4];
    const float* Wv = (const float*)d_in[5];
    const float* bv = (const float*)d_in[6];
    const float* Wo = (const float*)d_in[7];
    const float* bo = (const float*)d_in[8];
    float* out = (float*)d_out;

    float *qp, *kp, *vp, *ap, *pp, *pvp, *ahip, *alop;
    float *qhip, *qlop, *khip, *klop, *wthip, *wtlop, *wohip, *wolop;
    int *ip, *pip;
    cudaGetSymbolAddress((void**)&qp, g_q);
    cudaGetSymbolAddress((void**)&kp, g_k);
    cudaGetSymbolAddress((void**)&vp, g_v);
    cudaGetSymbolAddress((void**)&ap, g_attn);
    cudaGetSymbolAddress((void**)&pp, g_probs);
    cudaGetSymbolAddress((void**)&ip, g_topidx);
    cudaGetSymbolAddress((void**)&pvp, g_pval);
    cudaGetSymbolAddress((void**)&pip, g_pidx);
    cudaGetSymbolAddress((void**)&ahip, g_ahi);
    cudaGetSymbolAddress((void**)&alop, g_alo);
    cudaGetSymbolAddress((void**)&qhip, g_qhi);
    cudaGetSymbolAddress((void**)&qlop, g_qlo);
    cudaGetSymbolAddress((void**)&khip, g_khi);
    cudaGetSymbolAddress((void**)&klop, g_klo);
    cudaGetSymbolAddress((void**)&wthip, g_wthi);
    cudaGetSymbolAddress((void**)&wtlop, g_wtlo);
    cudaGetSymbolAddress((void**)&wohip, g_wohi);
    cudaGetSymbolAddress((void**)&wolop, g_wolo);

    cudaFuncSetAttribute(gemm_qkv_kernel,
                         cudaFuncAttributeMaxDynamicSharedMemorySize, GEMM_SMEM);
    cudaFuncSetAttribute(gemm_mma_kernel,
                         cudaFuncAttributeMaxDynamicSharedMemorySize, GEMM_SMEM);
    cudaFuncSetAttribute(scores_tile_kernel,
                         cudaFuncAttributeMaxDynamicSharedMemorySize, SC_SMEM);

    const size_t WSZ = (size_t)DIM * DIM;
    const int WPACK_GRID = (DIM / 8) * KS8 / 8;   // 2048
    split_pack_w<<<WPACK_GRID, 256>>>(Wq, (float2*)(wthip + 0 * WSZ), (float2*)(wtlop + 0 * WSZ));
    split_pack_w<<<WPACK_GRID, 256>>>(Wk, (float2*)(wthip + 1 * WSZ), (float2*)(wtlop + 1 * WSZ));
    split_pack_w<<<WPACK_GRID, 256>>>(Wv, (float2*)(wthip + 2 * WSZ), (float2*)(wtlop + 2 * WSZ));
    split_pack_w<<<WPACK_GRID, 256>>>(Wo, (float2*)wohip, (float2*)wolop);

    split_pack_a<<<(MROWS / 16) * KS8 / 8, 256>>>(S, (float4*)ahip, (float4*)alop);

    gemm_qkv_kernel<<<dim3(24, MROWS / 256), 256, GEMM_SMEM>>>(
        ahip, alop, wthip, wtlop, bq, bk, bv, qp, kp, vp);

    split_pack_a<<<(MROWS / 16) * KS8 / 8, 256>>>(qp, (float4*)qhip, (float4*)qlop);
    split_pack_kb<<<(MROWS / 8) * KS8 / 8, 256>>>(kp, (float2*)khip, (float2*)klop);

    scores_tile_kernel<<<dim3(NTRI, BSZ), 256, SC_SMEM>>>(
        qhip, qlop, khip, klop, pvp, pip);
    merge_softmax_kernel<<<(MROWS + 255) / 256, 256>>>(pvp, pip, pp, ip);
    gather_kernel<<<MROWS, 128>>>(vp, pp, ip, ap);

    split_pack_a<<<(MROWS / 16) * KS8 / 8, 256>>>(ap, (float4*)ahip, (float4*)alop);
    gemm_mma_kernel<<<dim3(DIM / 128, MROWS / 256), 256, GEMM_SMEM>>>(
        ahip, alop, wohip, wolop, bo, out);
}

// round 9
// speedup vs baseline: 2.3251x; 1.0060x over previous
#include <cuda_runtime.h>
#include <math.h>
#include <stdint.h>

#define BSZ   4
#define NSEQ  4096
#define DIM   1024
#define TOPK  8
#define MROWS (BSZ * NSEQ)
#define KS8   (DIM / 8)   // 128 k-steps of 8
#define NSB   272         // supertile score blocks per batch: sum_{sq<16}(2sq+2)

typedef unsigned long long ULL;

// ---------------- scratch (__device__ globals; no allocation allowed) -------
__device__ __align__(128) float g_v[(size_t)MROWS * DIM];
__device__ __align__(128) float g_attn[(size_t)MROWS * DIM];
__device__ float g_probs[(size_t)MROWS * TOPK];
__device__ int   g_topidx[(size_t)MROWS * TOPK];
__device__ float g_pval[(size_t)BSZ * NSB * 256 * TOPK];
__device__ int   g_pidx[(size_t)BSZ * NSB * 256 * TOPK];
// fragment-packed 3xTF32 buffers
__device__ __align__(128) float g_ahi[(size_t)MROWS * DIM];   // A-fmt (S / attn)
__device__ __align__(128) float g_alo[(size_t)MROWS * DIM];
__device__ __align__(128) float g_qhi[(size_t)MROWS * DIM];   // A-fmt (q)
__device__ __align__(128) float g_qlo[(size_t)MROWS * DIM];
__device__ __align__(128) float g_khi[(size_t)MROWS * DIM];   // B-fmt (k)
__device__ __align__(128) float g_klo[(size_t)MROWS * DIM];
__device__ __align__(128) float g_wthi[3][(size_t)DIM * DIM]; // B-fmt Wq/Wk/Wv
__device__ __align__(128) float g_wtlo[3][(size_t)DIM * DIM];
__device__ __align__(128) float g_wohi[(size_t)DIM * DIM];    // B-fmt Wo
__device__ __align__(128) float g_wolo[(size_t)DIM * DIM];

// ---------------- helpers -----------------------------------------------------
__device__ __forceinline__ uint32_t smem_u32(const void* p) {
    uint32_t a;
    asm("{ .reg .u64 t; cvta.to.shared.u64 t, %1; cvt.u32.u64 %0, t; }"
        : "=r"(a) : "l"(p));
    return a;
}
__device__ __forceinline__ float tf32r(float x) {
    uint32_t u;
    asm("cvt.rna.tf32.f32 %0, %1;" : "=r"(u) : "f"(x));
    return __uint_as_float(u);
}
__device__ __forceinline__ void cpasync16(uint32_t saddr, const void* g) {
    asm volatile("cp.async.cg.shared.global [%0], [%1], 16;"
                 :: "r"(saddr), "l"(g));
}
#define CP_COMMIT() asm volatile("cp.async.commit_group;" ::: "memory")
#define CP_WAIT_1() asm volatile("cp.async.wait_group 1;" ::: "memory")
#define CP_WAIT_0() asm volatile("cp.async.wait_group 0;" ::: "memory")

__device__ __forceinline__ void mma8(float4& c, const uint4& a, const uint2& b) {
    asm volatile(
        "mma.sync.aligned.m16n8k8.row.col.f32.tf32.tf32.f32 "
        "{%0,%1,%2,%3}, {%4,%5,%6,%7}, {%8,%9}, {%0,%1,%2,%3};"
        : "+f"(c.x), "+f"(c.y), "+f"(c.z), "+f"(c.w)
        : "r"(a.x), "r"(a.y), "r"(a.z), "r"(a.w), "r"(b.x), "r"(b.y));
}

// ---------------- split+pack A-format: X[M,K] row-major ---------------------
__global__ __launch_bounds__(256) void split_pack_a(
    const float* __restrict__ X, float4* __restrict__ Phi, float4* __restrict__ Plo) {
    const int atom = blockIdx.x * 8 + (threadIdx.x >> 5);
    const int lane = threadIdx.x & 31;
    const int mt = atom >> 7;
    const int ks = atom & 127;
    const int g = lane >> 2, t = lane & 3;
    const size_t r0 = (size_t)(mt * 16 + g) * DIM + ks * 8 + t;
    const size_t r1 = r0 + 8 * DIM;
    float x0 = X[r0], x1 = X[r1], x2 = X[r0 + 4], x3 = X[r1 + 4];
    float4 h, l;
    h.x = tf32r(x0); l.x = tf32r(x0 - h.x);
    h.y = tf32r(x1); l.y = tf32r(x1 - h.y);
    h.z = tf32r(x2); l.z = tf32r(x2 - h.z);
    h.w = tf32r(x3); l.w = tf32r(x3 - h.w);
    Phi[(size_t)atom * 32 + lane] = h;
    Plo[(size_t)atom * 32 + lane] = l;
}

// ---------------- split+pack W (B-format): W[K,N] -> [N/8][K/8][lane][2] ----
__global__ __launch_bounds__(256) void split_pack_w(
    const float* __restrict__ W, float2* __restrict__ Phi, float2* __restrict__ Plo) {
    const int atom = blockIdx.x * 8 + (threadIdx.x >> 5);
    const int lane = threadIdx.x & 31;
    const int nt = atom >> 7;
    const int ks = atom & 127;
    const int g = lane >> 2, t = lane & 3;
    float x0 = W[(size_t)(ks * 8 + t) * DIM + nt * 8 + g];
    float x1 = W[(size_t)(ks * 8 + t + 4) * DIM + nt * 8 + g];
    float2 h, l;
    h.x = tf32r(x0); l.x = tf32r(x0 - h.x);
    h.y = tf32r(x1); l.y = tf32r(x1 - h.y);
    Phi[(size_t)atom * 32 + lane] = h;
    Plo[(size_t)atom * 32 + lane] = l;
}

// ---------------- shared 3xTF32 mainloop (256x128 tile, BK=16, 3 stages) ----
#define GEMM_SMEM (3 * 12288 * 4)

__device__ __forceinline__ void mma_mainloop(
    float* sm, const float* __restrict__ Ahi, const float* __restrict__ Alo,
    const float* __restrict__ Bhi, const float* __restrict__ Blo,
    int br16, int bn16, float4 (&acc)[4][8]) {
    const int tid = threadIdx.x;
    const int lane = tid & 31, wid = tid >> 5;
    const int wy = wid >> 1, wx = wid & 1;
    const uint32_t smb = smem_u32(sm);

    auto load_stage = [&](int kc, int s) {
        const uint32_t sb = smb + s * 49152;
#pragma unroll
        for (int j = 0; j < 4; j++) {
            const int cA = tid + j * 256;
            const int mtl = cA >> 6, off = cA & 63;
            const uint32_t so = sb + (uint32_t)(mtl * 256 + off * 4) * 4;
            const size_t go = ((size_t)(br16 + mtl) * KS8 + kc * 2) * 128 + off * 4;
            cpasync16(so, Ahi + go);
            cpasync16(so + 4096 * 4, Alo + go);
        }
#pragma unroll
        for (int j = 0; j < 2; j++) {
            const int cB = tid + j * 256;
            const int ntl = cB >> 5, off = cB & 31;
            const uint32_t so = sb + (uint32_t)(8192 + ntl * 128 + off * 4) * 4;
            const size_t go = ((size_t)(bn16 + ntl) * KS8 + kc * 2) * 64 + off * 4;
            cpasync16(so, Bhi + go);
            cpasync16(so + 2048 * 4, Blo + go);
        }
    };

    load_stage(0, 0); CP_COMMIT();
    load_stage(1, 1); CP_COMMIT();

#pragma unroll
    for (int i = 0; i < 4; i++)
#pragma unroll
        for (int j = 0; j < 8; j++) acc[i][j] = make_float4(0.f, 0.f, 0.f, 0.f);

    for (int c = 0; c < 64; c++) {
        if (c < 62) { CP_WAIT_1(); } else { CP_WAIT_0(); }
        __syncthreads();
        if (c + 2 < 64) { load_stage(c + 2, (c + 2) % 3); CP_COMMIT(); }
        const float* st = sm + (c % 3) * 12288;
#pragma unroll
        for (int ks = 0; ks < 2; ks++) {
            uint4 Ah[4], Al[4];
            uint2 Bh[8], Bl[8];
#pragma unroll
            for (int i = 0; i < 4; i++) {
                const float* p = st + ((wy * 4 + i) * 2 + ks) * 128 + lane * 4;
                Ah[i] = *(const uint4*)p;
                Al[i] = *(const uint4*)(p + 4096);
            }
#pragma unroll
            for (int j = 0; j < 8; j++) {
                const float* p = st + 8192 + ((wx * 8 + j) * 2 + ks) * 64 + lane * 2;
                Bh[j] = *(const uint2*)p;
                Bl[j] = *(const uint2*)(p + 2048);
            }
#pragma unroll
            for (int i = 0; i < 4; i++)
#pragma unroll
                for (int j = 0; j < 8; j++) {
                    mma8(acc[i][j], Ah[i], Bh[j]);
                    mma8(acc[i][j], Ah[i], Bl[j]);
                    mma8(acc[i][j], Al[i], Bh[j]);
                }
        }
    }
}

// Fused Q/K/V projection. wsel 0 -> q packed A-fmt, 1 -> k packed B-fmt,
// 2 -> v raw. Pack staging reuses pipeline smem (stride 132, conflict-free).
__global__ __launch_bounds__(256, 1) void gemm_qkv_kernel(
    const float* __restrict__ Ahi, const float* __restrict__ Alo,
    const float* __restrict__ Whi, const float* __restrict__ Wlo,
    const float* __restrict__ bq, const float* __restrict__ bk,
    const float* __restrict__ bv,
    float* __restrict__ Qhi, float* __restrict__ Qlo,
    float* __restrict__ Khi, float* __restrict__ Klo,
    float* __restrict__ V) {
    extern __shared__ float sm[];
    const int wsel = blockIdx.x % 3;
    const int nxt = blockIdx.x / 3;   // 0..7
    const int tid = threadIdx.x;
    const int lane = tid & 31, wid = tid >> 5;
    const int wy = wid >> 1, wx = wid & 1;
    const int g = lane >> 2, t = lane & 3;
    const int m0 = blockIdx.y * 256, n0 = nxt * 128;

    float4 acc[4][8];
    mma_mainloop(sm, Ahi, Alo,
                 Whi + (size_t)wsel * DIM * DIM, Wlo + (size_t)wsel * DIM * DIM,
                 blockIdx.y * 16, nxt * 16, acc);

    if (wsel == 2) {
        // raw V + bias
#pragma unroll
        for (int i = 0; i < 4; i++) {
            const int r0 = m0 + wy * 64 + i * 16 + g;
#pragma unroll
            for (int j = 0; j < 8; j++) {
                const int col = n0 + wx * 64 + j * 8 + t * 2;
                const float2 bb = *(const float2*)(bv + col);
                *(float2*)(V + (size_t)r0 * DIM + col) =
                    make_float2(acc[i][j].x + bb.x, acc[i][j].y + bb.y);
                *(float2*)(V + (size_t)(r0 + 8) * DIM + col) =
                    make_float2(acc[i][j].z + bb.x, acc[i][j].w + bb.y);
            }
        }
        return;
    }

    const float* bias = (wsel == 0) ? bq : bk;
    __syncthreads();  // pipeline smem free
#pragma unroll
    for (int i = 0; i < 4; i++) {
        const int r0 = wy * 64 + i * 16 + g;
#pragma unroll
        for (int j = 0; j < 8; j++) {
            const int col = wx * 64 + j * 8 + t * 2;
            const float2 bb = *(const float2*)(bias + n0 + col);
            *(float2*)&sm[r0 * 132 + col] =
                make_float2(acc[i][j].x + bb.x, acc[i][j].y + bb.y);
            *(float2*)&sm[(r0 + 8) * 132 + col] =
                make_float2(acc[i][j].z + bb.x, acc[i][j].w + bb.y);
        }
    }
    __syncthreads();

    if (wsel == 0) {
        // A-format: 16 mt-atoms x 16 ks-atoms
        for (int a = wid; a < 256; a += 8) {
            const int amt = a >> 4, aks = a & 15;
            const float* bp = sm + (amt * 16 + g) * 132 + aks * 8 + t;
            float x0 = bp[0], x1 = bp[8 * 132], x2 = bp[4], x3 = bp[8 * 132 + 4];
            float4 h, l;
            h.x = tf32r(x0); l.x = tf32r(x0 - h.x);
            h.y = tf32r(x1); l.y = tf32r(x1 - h.y);
            h.z = tf32r(x2); l.z = tf32r(x2 - h.z);
            h.w = tf32r(x3); l.w = tf32r(x3 - h.w);
            const size_t atom = (size_t)(blockIdx.y * 16 + amt) * KS8 + (nxt * 16 + aks);
            ((float4*)Qhi)[atom * 32 + lane] = h;
            ((float4*)Qlo)[atom * 32 + lane] = l;
        }
    } else {
        // B-format: 32 nt-atoms x 16 ks-atoms
        for (int a = wid; a < 512; a += 8) {
            const int ant = a >> 4, aks = a & 15;
            const float* bp = sm + (ant * 8 + g) * 132 + aks * 8 + t;
            float x0 = bp[0], x1 = bp[4];
            float2 h, l;
            h.x = tf32r(x0); l.x = tf32r(x0 - h.x);
            h.y = tf32r(x1); l.y = tf32r(x1 - h.y);
            const size_t atom = (size_t)(blockIdx.y * 32 + ant) * KS8 + (nxt * 16 + aks);
            ((float2*)Khi)[atom * 32 + lane] = h;
            ((float2*)Klo)[atom * 32 + lane] = l;
        }
    }
}

// Single GEMM (output projection): raw epilogue + bias. grid (8, 64).
__global__ __launch_bounds__(256, 1) void gemm_mma_kernel(
    const float* __restrict__ Ahi, const float* __restrict__ Alo,
    const float* __restrict__ Bhi, const float* __restrict__ Blo,
    const float* __restrict__ bias, float* __restrict__ C) {
    extern __shared__ float sm[];
    const int tid = threadIdx.x;
    const int lane = tid & 31, wid = tid >> 5;
    const int wy = wid >> 1, wx = wid & 1;
    const int g = lane >> 2, t = lane & 3;
    const int m0 = blockIdx.y * 256, n0 = blockIdx.x * 128;
    float4 acc[4][8];
    mma_mainloop(sm, Ahi, Alo, Bhi, Blo, blockIdx.y * 16, blockIdx.x * 16, acc);
#pragma unroll
    for (int i = 0; i < 4; i++) {
        const int r0 = m0 + wy * 64 + i * 16 + g;
#pragma unroll
        for (int j = 0; j < 8; j++) {
            const int col = n0 + wx * 64 + j * 8 + t * 2;
            const float2 bb = *(const float2*)(bias + col);
            *(float2*)(C + (size_t)r0 * DIM + col) =
                make_float2(acc[i][j].x + bb.x, acc[i][j].y + bb.y);
            *(float2*)(C + (size_t)(r0 + 8) * DIM + col) =
                make_float2(acc[i][j].z + bb.x, acc[i][j].w + bb.y);
        }
    }
}

// ---------------- supertile 3xTF32 causal scores + top-8 --------------------
// Block = 256 q-rows x 128 k-cols; triangular grid: sq=0..15 (q-tiles 2sq,2sq+1),
// kt=0..2sq+1. Uses the same 85 B/MMA mainloop as the GEMM.
// smem (floats): stages 3x12288 @0 | sc[128][72] @36864 | tval[256][8] @46080
//               | tidx[256][8] @48128   => 200704 bytes
#define SSC_SMEM ((3 * 12288 + 128 * 72 + 256 * 8 + 256 * 8) * 4)

__global__ __launch_bounds__(256, 1) void scores_super_kernel(
    const float* __restrict__ Qhi, const float* __restrict__ Qlo,
    const float* __restrict__ Khi, const float* __restrict__ Klo,
    float* __restrict__ pval, int* __restrict__ pidx) {
    extern __shared__ float sm[];
    float* sc = sm + 36864;           // [128][72]
    float* tval = sm + 46080;         // [256][8]
    int* tidx = (int*)(sm + 48128);   // [256][8]

    const int tid = threadIdx.x;
    const int lane = tid & 31, wid = tid >> 5;
    const int wy = wid >> 1, wx = wid & 1;
    const int g = lane >> 2, t = lane & 3;
    const int b = blockIdx.y;
    const int bidx = blockIdx.x;

    // decode sq, kt from triangular index: cum(sq) = sq*(sq+1)
    int sq = (int)((sqrtf(4.0f * (float)bidx + 1.0f) - 1.0f) * 0.5f);
    while ((sq + 1) * (sq + 2) <= bidx) sq++;
    while (sq * (sq + 1) > bidx) sq--;
    const int kt = bidx - sq * (sq + 1);
    const int q0 = sq * 256, k0 = kt * 128;

    for (int i = tid; i < 256 * TOPK; i += 256) {
        tval[i] = -INFINITY;
        tidx[i] = 0;
    }

    float4 acc[4][8];
    mma_mainloop(sm, Qhi, Qlo, Khi, Klo,
                 b * 256 + sq * 16, b * 512 + kt * 16, acc);

    // 4 merge passes: row halves rh, col halves h
#pragma unroll
    for (int rh = 0; rh < 2; rh++) {
#pragma unroll
        for (int h = 0; h < 2; h++) {
            if ((wy >> 1) == rh && wx == h) {
#pragma unroll
                for (int i = 0; i < 4; i++) {
                    const int rl = wy * 64 + i * 16 + g;     // 0..255
                    const int srow = rl - rh * 128;           // 0..119
#pragma unroll
                    for (int j = 0; j < 8; j++) {
                        const int col = j * 8 + t * 2;        // 0..63
                        const int gc = k0 + h * 64 + col;
                        const int gr0 = q0 + rl, gr1 = gr0 + 8;
                        float v0 = acc[i][j].x * 0.03125f;
                        float v1 = acc[i][j].y * 0.03125f;
                        float v2 = acc[i][j].z * 0.03125f;
                        float v3 = acc[i][j].w * 0.03125f;
                        if (gc + 0 > gr0) v0 = -INFINITY;
                        if (gc + 1 > gr0) v1 = -INFINITY;
                        if (gc + 0 > gr1) v2 = -INFINITY;
                        if (gc + 1 > gr1) v3 = -INFINITY;
                        *(float2*)&sc[srow * 72 + col] = make_float2(v0, v1);
                        *(float2*)&sc[(srow + 8) * 72 + col] = make_float2(v2, v3);
                    }
                }
            }
            __syncthreads();
            if (tid < 128) {
                const int row = rh * 128 + tid;
                float tv[TOPK]; int ti[TOPK];
#pragma unroll
                for (int j = 0; j < TOPK; j++) { tv[j] = tval[row * 8 + j]; ti[j] = tidx[row * 8 + j]; }
                float vmin = tv[0]; int mpos = 0;
#pragma unroll
                for (int j = 1; j < TOPK; j++) if (tv[j] < vmin) { vmin = tv[j]; mpos = j; }
                const int cbase = k0 + h * 64;
                for (int cc = 0; cc < 64; cc++) {
                    const float vv = sc[tid * 72 + cc];
                    if (vv > vmin) {
                        tv[mpos] = vv; ti[mpos] = cbase + cc;
                        vmin = tv[0]; mpos = 0;
#pragma unroll
                        for (int j = 1; j < TOPK; j++) if (tv[j] < vmin) { vmin = tv[j]; mpos = j; }
                    }
                }
#pragma unroll
                for (int j = 0; j < TOPK; j++) { tval[row * 8 + j] = tv[j]; tidx[row * 8 + j] = ti[j]; }
            }
            __syncthreads();
        }
    }

    const size_t base = (((size_t)b * NSB + bidx) * 256 + tid) * TOPK;
#pragma unroll
    for (int j = 0; j < TOPK; j++) {
        pval[base + j] = tval[tid * 8 + j];
        pidx[base + j] = tidx[tid * 8 + j];
    }
}

// ---------------- merge per-row partial top-8 lists + softmax ----------------
__global__ __launch_bounds__(256) void merge_softmax_kernel(
    const float* __restrict__ pv, const int* __restrict__ pi,
    float* __restrict__ probs, int* __restrict__ idxs) {
    const int row = blockIdx.x * 256 + threadIdx.x;
    if (row >= MROWS) return;
    const int b = row >> 12, rr = row & 4095;
    const int qt = rr >> 7;
    const int sq = qt >> 1;
    const int rib = rr - sq * 256;    // row within supertile block (0..255)
    const size_t sbase = ((size_t)b * NSB + (size_t)sq * (sq + 1)) * 256 + rib;

    float tv[TOPK]; int ti[TOPK];
#pragma unroll
    for (int j = 0; j < TOPK; j++) { tv[j] = -INFINITY; ti[j] = 0; }
    float vmin = -INFINITY; int mpos = 0;

    for (int kt = 0; kt <= qt; kt++) {
        const size_t base = (sbase + (size_t)kt * 256) * TOPK;
#pragma unroll
        for (int j = 0; j < TOPK; j++) {
            const float vv = pv[base + j];
            if (vv > vmin) {
                tv[mpos] = vv; ti[mpos] = pi[base + j];
                vmin = tv[0]; mpos = 0;
#pragma unroll
                for (int q = 1; q < TOPK; q++) if (tv[q] < vmin) { vmin = tv[q]; mpos = q; }
            }
        }
    }

    float mx = tv[0];
#pragma unroll
    for (int j = 1; j < TOPK; j++) mx = fmaxf(mx, tv[j]);
    float e[TOPK]; float ssum = 0.f;
#pragma unroll
    for (int j = 0; j < TOPK; j++) { e[j] = expf(tv[j] - mx); ssum += e[j]; }
    const float inv = 1.f / ssum;
    const size_t obase = (size_t)row * TOPK;
#pragma unroll
    for (int j = 0; j < TOPK; j++) { probs[obase + j] = e[j] * inv; idxs[obase + j] = ti[j]; }
}

// ---------------- sparse AV gather ------------------------------------------
__global__ __launch_bounds__(128) void gather_kernel(
    const float* __restrict__ v, const float* __restrict__ probs,
    const int* __restrict__ idxs, float* __restrict__ out) {
    const int row = blockIdx.x;
    const int b = row >> 12;
    const int tid = threadIdx.x;
    __shared__ float p[TOPK];
    __shared__ int   id[TOPK];
    if (tid < TOPK) {
        p[tid]  = probs[(size_t)row * TOPK + tid];
        id[tid] = idxs[(size_t)row * TOPK + tid];
    }
    __syncthreads();
    const float* vb = v + (size_t)b * NSEQ * DIM;
    const int c = tid * 8;
    float4 a0 = {0.f, 0.f, 0.f, 0.f}, a1 = {0.f, 0.f, 0.f, 0.f};
#pragma unroll
    for (int j = 0; j < TOPK; j++) {
        const float4* vr = (const float4*)(vb + (size_t)id[j] * DIM + c);
        const float pj = p[j];
        float4 v0 = vr[0], v1 = vr[1];
        a0.x += pj * v0.x; a0.y += pj * v0.y; a0.z += pj * v0.z; a0.w += pj * v0.w;
        a1.x += pj * v1.x; a1.y += pj * v1.y; a1.z += pj * v1.z; a1.w += pj * v1.w;
    }
    float4* orow = (float4*)(out + (size_t)row * DIM + c);
    orow[0] = a0; orow[1] = a1;
}

// ---------------- launch -----------------------------------------------------
extern "C" void kernel_launch(void* const* d_in, const int* in_sizes, int n_in,
                              void* d_out, int out_size) {
    const float* S  = (const float*)d_in[0];
    const float* Wq = (const float*)d_in[1];
    const float* bq = (const float*)d_in[2];
    const float* Wk = (const float*)d_in[3];
    const float* bk = (const float*)d_in[4];
    const float* Wv = (const float*)d_in[5];
    const float* bv = (const float*)d_in[6];
    const float* Wo = (const float*)d_in[7];
    const float* bo = (const float*)d_in[8];
    float* out = (float*)d_out;

    float *vp, *ap, *pp, *pvp, *ahip, *alop;
    float *qhip, *qlop, *khip, *klop, *wthip, *wtlop, *wohip, *wolop;
    int *ip, *pip;
    cudaGetSymbolAddress((void**)&vp, g_v);
    cudaGetSymbolAddress((void**)&ap, g_attn);
    cudaGetSymbolAddress((void**)&pp, g_probs);
    cudaGetSymbolAddress((void**)&ip, g_topidx);
    cudaGetSymbolAddress((void**)&pvp, g_pval);
    cudaGetSymbolAddress((void**)&pip, g_pidx);
    cudaGetSymbolAddress((void**)&ahip, g_ahi);
    cudaGetSymbolAddress((void**)&alop, g_alo);
    cudaGetSymbolAddress((void**)&qhip, g_qhi);
    cudaGetSymbolAddress((void**)&qlop, g_qlo);
    cudaGetSymbolAddress((void**)&khip, g_khi);
    cudaGetSymbolAddress((void**)&klop, g_klo);
    cudaGetSymbolAddress((void**)&wthip, g_wthi);
    cudaGetSymbolAddress((void**)&wtlop, g_wtlo);
    cudaGetSymbolAddress((void**)&wohip, g_wohi);
    cudaGetSymbolAddress((void**)&wolop, g_wolo);

    cudaFuncSetAttribute(gemm_qkv_kernel,
                         cudaFuncAttributeMaxDynamicSharedMemorySize, GEMM_SMEM);
    cudaFuncSetAttribute(gemm_mma_kernel,
                         cudaFuncAttributeMaxDynamicSharedMemorySize, GEMM_SMEM);
    cudaFuncSetAttribute(scores_super_kernel,
                         cudaFuncAttributeMaxDynamicSharedMemorySize, SSC_SMEM);

    const size_t WSZ = (size_t)DIM * DIM;
    const int WPACK_GRID = (DIM / 8) * KS8 / 8;   // 2048
    split_pack_w<<<WPACK_GRID, 256>>>(Wq, (float2*)(wthip + 0 * WSZ), (float2*)(wtlop + 0 * WSZ));
    split_pack_w<<<WPACK_GRID, 256>>>(Wk, (float2*)(wthip + 1 * WSZ), (float2*)(wtlop + 1 * WSZ));
    split_pack_w<<<WPACK_GRID, 256>>>(Wv, (float2*)(wthip + 2 * WSZ), (float2*)(wtlop + 2 * WSZ));
    split_pack_w<<<WPACK_GRID, 256>>>(Wo, (float2*)wohip, (float2*)wolop);

    split_pack_a<<<(MROWS / 16) * KS8 / 8, 256>>>(S, (float4*)ahip, (float4*)alop);

    // fused QKV: q -> packed A-fmt, k -> packed B-fmt, v -> raw
    gemm_qkv_kernel<<<dim3(24, MROWS / 256), 256, GEMM_SMEM>>>(
        ahip, alop, wthip, wtlop, bq, bk, bv, qhip, qlop, khip, klop, vp);

    scores_super_kernel<<<dim3(NSB, BSZ), 256, SSC_SMEM>>>(
        qhip, qlop, khip, klop, pvp, pip);
    merge_softmax_kernel<<<(MROWS + 255) / 256, 256>>>(pvp, pip, pp, ip);
    gather_kernel<<<MROWS, 128>>>(vp, pp, ip, ap);

    split_pack_a<<<(MROWS / 16) * KS8 / 8, 256>>>(ap, (float4*)ahip, (float4*)alop);
    gemm_mma_kernel<<<dim3(DIM / 128, MROWS / 256), 256, GEMM_SMEM>>>(
        ahip, alop, wohip, wolop, bo, out);
}

// round 10
// speedup vs baseline: 2.5953x; 1.1162x over previous
#include <cuda_runtime.h>
#include <math.h>
#include <stdint.h>

#define BSZ   4
#define NSEQ  4096
#define DIM   1024
#define TOPK  8
#define MROWS (BSZ * NSEQ)
#define KS8   (DIM / 8)   // 128 k-steps of 8
#define NSB   272         // supertile score blocks per batch

typedef unsigned long long ULL;

// ---------------- scratch (__device__ globals; no allocation allowed) -------
__device__ __align__(128) float g_u[(size_t)MROWS * DIM];   // U = S @ Wvo (raw)
__device__ float g_probs[(size_t)MROWS * TOPK];
__device__ int   g_topidx[(size_t)MROWS * TOPK];
__device__ float g_pval[(size_t)BSZ * NSB * 256 * TOPK];
__device__ int   g_pidx[(size_t)BSZ * NSB * 256 * TOPK];
__device__ float g_bvo[DIM];
__device__ float g_zerob[DIM];   // zero bias (device globals zero-init)
// fragment-packed 3xTF32 buffers
__device__ __align__(128) float g_ahi[(size_t)MROWS * DIM];   // A-fmt (S / Wv)
__device__ __align__(128) float g_alo[(size_t)MROWS * DIM];
__device__ __align__(128) float g_qhi[(size_t)MROWS * DIM];   // A-fmt (q)
__device__ __align__(128) float g_qlo[(size_t)MROWS * DIM];
__device__ __align__(128) float g_khi[(size_t)MROWS * DIM];   // B-fmt (k)
__device__ __align__(128) float g_klo[(size_t)MROWS * DIM];
__device__ __align__(128) float g_wthi[3][(size_t)DIM * DIM]; // B-fmt Wq/Wk/Wvo
__device__ __align__(128) float g_wtlo[3][(size_t)DIM * DIM];
__device__ __align__(128) float g_wohi[(size_t)DIM * DIM];    // B-fmt Wo
__device__ __align__(128) float g_wolo[(size_t)DIM * DIM];

// ---------------- helpers -----------------------------------------------------
__device__ __forceinline__ uint32_t smem_u32(const void* p) {
    uint32_t a;
    asm("{ .reg .u64 t; cvta.to.shared.u64 t, %1; cvt.u32.u64 %0, t; }"
        : "=r"(a) : "l"(p));
    return a;
}
__device__ __forceinline__ float tf32r(float x) {
    uint32_t u;
    asm("cvt.rna.tf32.f32 %0, %1;" : "=r"(u) : "f"(x));
    return __uint_as_float(u);
}
__device__ __forceinline__ void cpasync16(uint32_t saddr, const void* g) {
    asm volatile("cp.async.cg.shared.global [%0], [%1], 16;"
                 :: "r"(saddr), "l"(g));
}
#define CP_COMMIT() asm volatile("cp.async.commit_group;" ::: "memory")
#define CP_WAIT_1() asm volatile("cp.async.wait_group 1;" ::: "memory")
#define CP_WAIT_0() asm volatile("cp.async.wait_group 0;" ::: "memory")

__device__ __forceinline__ void mma8(float4& c, const uint4& a, const uint2& b) {
    asm volatile(
        "mma.sync.aligned.m16n8k8.row.col.f32.tf32.tf32.f32 "
        "{%0,%1,%2,%3}, {%4,%5,%6,%7}, {%8,%9}, {%0,%1,%2,%3};"
        : "+f"(c.x), "+f"(c.y), "+f"(c.z), "+f"(c.w)
        : "r"(a.x), "r"(a.y), "r"(a.z), "r"(a.w), "r"(b.x), "r"(b.y));
}

// ---------------- split+pack A-format: X[M,K] row-major ---------------------
__global__ __launch_bounds__(256) void split_pack_a(
    const float* __restrict__ X, float4* __restrict__ Phi, float4* __restrict__ Plo) {
    const int atom = blockIdx.x * 8 + (threadIdx.x >> 5);
    const int lane = threadIdx.x & 31;
    const int mt = atom >> 7;
    const int ks = atom & 127;
    const int g = lane >> 2, t = lane & 3;
    const size_t r0 = (size_t)(mt * 16 + g) * DIM + ks * 8 + t;
    const size_t r1 = r0 + 8 * DIM;
    float x0 = X[r0], x1 = X[r1], x2 = X[r0 + 4], x3 = X[r1 + 4];
    float4 h, l;
    h.x = tf32r(x0); l.x = tf32r(x0 - h.x);
    h.y = tf32r(x1); l.y = tf32r(x1 - h.y);
    h.z = tf32r(x2); l.z = tf32r(x2 - h.z);
    h.w = tf32r(x3); l.w = tf32r(x3 - h.w);
    Phi[(size_t)atom * 32 + lane] = h;
    Plo[(size_t)atom * 32 + lane] = l;
}

// ---------------- split+pack W (B-format): W[K,N] -> [N/8][K/8][lane][2] ----
__global__ __launch_bounds__(256) void split_pack_w(
    const float* __restrict__ W, float2* __restrict__ Phi, float2* __restrict__ Plo) {
    const int atom = blockIdx.x * 8 + (threadIdx.x >> 5);
    const int lane = threadIdx.x & 31;
    const int nt = atom >> 7;
    const int ks = atom & 127;
    const int g = lane >> 2, t = lane & 3;
    float x0 = W[(size_t)(ks * 8 + t) * DIM + nt * 8 + g];
    float x1 = W[(size_t)(ks * 8 + t + 4) * DIM + nt * 8 + g];
    float2 h, l;
    h.x = tf32r(x0); l.x = tf32r(x0 - h.x);
    h.y = tf32r(x1); l.y = tf32r(x1 - h.y);
    Phi[(size_t)atom * 32 + lane] = h;
    Plo[(size_t)atom * 32 + lane] = l;
}

// ---------------- bvo = bv @ Wo + bo ----------------------------------------
__global__ __launch_bounds__(128) void bvo_kernel(
    const float* __restrict__ bv, const float* __restrict__ Wo,
    const float* __restrict__ bo, float* __restrict__ bvo) {
    const int n = blockIdx.x * 128 + threadIdx.x;
    float acc = bo[n];
    for (int k = 0; k < DIM; k++) acc += bv[k] * Wo[(size_t)k * DIM + n];
    bvo[n] = acc;
}

// ---------------- shared 3xTF32 mainloop (256x128 tile, BK=16, 3 stages) ----
#define GEMM_SMEM (3 * 12288 * 4)

__device__ __forceinline__ void mma_mainloop(
    float* sm, const float* __restrict__ Ahi, const float* __restrict__ Alo,
    const float* __restrict__ Bhi, const float* __restrict__ Blo,
    int br16, int bn16, float4 (&acc)[4][8]) {
    const int tid = threadIdx.x;
    const int lane = tid & 31, wid = tid >> 5;
    const int wy = wid >> 1, wx = wid & 1;
    const uint32_t smb = smem_u32(sm);

    auto load_stage = [&](int kc, int s) {
        const uint32_t sb = smb + s * 49152;
#pragma unroll
        for (int j = 0; j < 4; j++) {
            const int cA = tid + j * 256;
            const int mtl = cA >> 6, off = cA & 63;
            const uint32_t so = sb + (uint32_t)(mtl * 256 + off * 4) * 4;
            const size_t go = ((size_t)(br16 + mtl) * KS8 + kc * 2) * 128 + off * 4;
            cpasync16(so, Ahi + go);
            cpasync16(so + 4096 * 4, Alo + go);
        }
#pragma unroll
        for (int j = 0; j < 2; j++) {
            const int cB = tid + j * 256;
            const int ntl = cB >> 5, off = cB & 31;
            const uint32_t so = sb + (uint32_t)(8192 + ntl * 128 + off * 4) * 4;
            const size_t go = ((size_t)(bn16 + ntl) * KS8 + kc * 2) * 64 + off * 4;
            cpasync16(so, Bhi + go);
            cpasync16(so + 2048 * 4, Blo + go);
        }
    };

    load_stage(0, 0); CP_COMMIT();
    load_stage(1, 1); CP_COMMIT();

#pragma unroll
    for (int i = 0; i < 4; i++)
#pragma unroll
        for (int j = 0; j < 8; j++) acc[i][j] = make_float4(0.f, 0.f, 0.f, 0.f);

    for (int c = 0; c < 64; c++) {
        if (c < 62) { CP_WAIT_1(); } else { CP_WAIT_0(); }
        __syncthreads();
        if (c + 2 < 64) { load_stage(c + 2, (c + 2) % 3); CP_COMMIT(); }
        const float* st = sm + (c % 3) * 12288;
#pragma unroll
        for (int ks = 0; ks < 2; ks++) {
            uint4 Ah[4], Al[4];
            uint2 Bh[8], Bl[8];
#pragma unroll
            for (int i = 0; i < 4; i++) {
                const float* p = st + ((wy * 4 + i) * 2 + ks) * 128 + lane * 4;
                Ah[i] = *(const uint4*)p;
                Al[i] = *(const uint4*)(p + 4096);
            }
#pragma unroll
            for (int j = 0; j < 8; j++) {
                const float* p = st + 8192 + ((wx * 8 + j) * 2 + ks) * 64 + lane * 2;
                Bh[j] = *(const uint2*)p;
                Bl[j] = *(const uint2*)(p + 2048);
            }
#pragma unroll
            for (int i = 0; i < 4; i++)
#pragma unroll
                for (int j = 0; j < 8; j++) {
                    mma8(acc[i][j], Ah[i], Bh[j]);
                    mma8(acc[i][j], Ah[i], Bl[j]);
                    mma8(acc[i][j], Al[i], Bh[j]);
                }
        }
    }
}

// Fused Q/K/U projection. wsel 0 -> q packed A-fmt, 1 -> k packed B-fmt,
// 2 -> U = S@Wvo raw (zero bias).
__global__ __launch_bounds__(256, 1) void gemm_qkv_kernel(
    const float* __restrict__ Ahi, const float* __restrict__ Alo,
    const float* __restrict__ Whi, const float* __restrict__ Wlo,
    const float* __restrict__ bq, const float* __restrict__ bk,
    const float* __restrict__ bu,
    float* __restrict__ Qhi, float* __restrict__ Qlo,
    float* __restrict__ Khi, float* __restrict__ Klo,
    float* __restrict__ U) {
    extern __shared__ float sm[];
    const int wsel = blockIdx.x % 3;
    const int nxt = blockIdx.x / 3;   // 0..7
    const int tid = threadIdx.x;
    const int lane = tid & 31, wid = tid >> 5;
    const int wy = wid >> 1, wx = wid & 1;
    const int g = lane >> 2, t = lane & 3;
    const int m0 = blockIdx.y * 256, n0 = nxt * 128;

    float4 acc[4][8];
    mma_mainloop(sm, Ahi, Alo,
                 Whi + (size_t)wsel * DIM * DIM, Wlo + (size_t)wsel * DIM * DIM,
                 blockIdx.y * 16, nxt * 16, acc);

    if (wsel == 2) {
#pragma unroll
        for (int i = 0; i < 4; i++) {
            const int r0 = m0 + wy * 64 + i * 16 + g;
#pragma unroll
            for (int j = 0; j < 8; j++) {
                const int col = n0 + wx * 64 + j * 8 + t * 2;
                const float2 bb = *(const float2*)(bu + col);
                *(float2*)(U + (size_t)r0 * DIM + col) =
                    make_float2(acc[i][j].x + bb.x, acc[i][j].y + bb.y);
                *(float2*)(U + (size_t)(r0 + 8) * DIM + col) =
                    make_float2(acc[i][j].z + bb.x, acc[i][j].w + bb.y);
            }
        }
        return;
    }

    const float* bias = (wsel == 0) ? bq : bk;
    __syncthreads();  // pipeline smem free
#pragma unroll
    for (int i = 0; i < 4; i++) {
        const int r0 = wy * 64 + i * 16 + g;
#pragma unroll
        for (int j = 0; j < 8; j++) {
            const int col = wx * 64 + j * 8 + t * 2;
            const float2 bb = *(const float2*)(bias + n0 + col);
            *(float2*)&sm[r0 * 132 + col] =
                make_float2(acc[i][j].x + bb.x, acc[i][j].y + bb.y);
            *(float2*)&sm[(r0 + 8) * 132 + col] =
                make_float2(acc[i][j].z + bb.x, acc[i][j].w + bb.y);
        }
    }
    __syncthreads();

    if (wsel == 0) {
        for (int a = wid; a < 256; a += 8) {
            const int amt = a >> 4, aks = a & 15;
            const float* bp = sm + (amt * 16 + g) * 132 + aks * 8 + t;
            float x0 = bp[0], x1 = bp[8 * 132], x2 = bp[4], x3 = bp[8 * 132 + 4];
            float4 h, l;
            h.x = tf32r(x0); l.x = tf32r(x0 - h.x);
            h.y = tf32r(x1); l.y = tf32r(x1 - h.y);
            h.z = tf32r(x2); l.z = tf32r(x2 - h.z);
            h.w = tf32r(x3); l.w = tf32r(x3 - h.w);
            const size_t atom = (size_t)(blockIdx.y * 16 + amt) * KS8 + (nxt * 16 + aks);
            ((float4*)Qhi)[atom * 32 + lane] = h;
            ((float4*)Qlo)[atom * 32 + lane] = l;
        }
    } else {
        for (int a = wid; a < 512; a += 8) {
            const int ant = a >> 4, aks = a & 15;
            const float* bp = sm + (ant * 8 + g) * 132 + aks * 8 + t;
            float x0 = bp[0], x1 = bp[4];
            float2 h, l;
            h.x = tf32r(x0); l.x = tf32r(x0 - h.x);
            h.y = tf32r(x1); l.y = tf32r(x1 - h.y);
            const size_t atom = (size_t)(blockIdx.y * 32 + ant) * KS8 + (nxt * 16 + aks);
            ((float2*)Khi)[atom * 32 + lane] = h;
            ((float2*)Klo)[atom * 32 + lane] = l;
        }
    }
}

// Single GEMM (used for Wvo = Wv @ Wo): raw epilogue + bias.
__global__ __launch_bounds__(256, 1) void gemm_mma_kernel(
    const float* __restrict__ Ahi, const float* __restrict__ Alo,
    const float* __restrict__ Bhi, const float* __restrict__ Blo,
    const float* __restrict__ bias, float* __restrict__ C) {
    extern __shared__ float sm[];
    const int tid = threadIdx.x;
    const int lane = tid & 31, wid = tid >> 5;
    const int wy = wid >> 1, wx = wid & 1;
    const int g = lane >> 2, t = lane & 3;
    const int m0 = blockIdx.y * 256, n0 = blockIdx.x * 128;
    float4 acc[4][8];
    mma_mainloop(sm, Ahi, Alo, Bhi, Blo, blockIdx.y * 16, blockIdx.x * 16, acc);
#pragma unroll
    for (int i = 0; i < 4; i++) {
        const int r0 = m0 + wy * 64 + i * 16 + g;
#pragma unroll
        for (int j = 0; j < 8; j++) {
            const int col = n0 + wx * 64 + j * 8 + t * 2;
            const float2 bb = *(const float2*)(bias + col);
            *(float2*)(C + (size_t)r0 * DIM + col) =
                make_float2(acc[i][j].x + bb.x, acc[i][j].y + bb.y);
            *(float2*)(C + (size_t)(r0 + 8) * DIM + col) =
                make_float2(acc[i][j].z + bb.x, acc[i][j].w + bb.y);
        }
    }
}

// ---------------- supertile 3xTF32 causal scores + top-8 --------------------
#define SSC_SMEM ((3 * 12288 + 128 * 72 + 256 * 8 + 256 * 8) * 4)

__global__ __launch_bounds__(256, 1) void scores_super_kernel(
    const float* __restrict__ Qhi, const float* __restrict__ Qlo,
    const float* __restrict__ Khi, const float* __restrict__ Klo,
    float* __restrict__ pval, int* __restrict__ pidx) {
    extern __shared__ float sm[];
    float* sc = sm + 36864;           // [128][72]
    float* tval = sm + 46080;         // [256][8]
    int* tidx = (int*)(sm + 48128);   // [256][8]

    const int tid = threadIdx.x;
    const int lane = tid & 31, wid = tid >> 5;
    const int wy = wid >> 1, wx = wid & 1;
    const int g = lane >> 2, t = lane & 3;
    const int b = blockIdx.y;
    const int bidx = blockIdx.x;

    int sq = (int)((sqrtf(4.0f * (float)bidx + 1.0f) - 1.0f) * 0.5f);
    while ((sq + 1) * (sq + 2) <= bidx) sq++;
    while (sq * (sq + 1) > bidx) sq--;
    const int kt = bidx - sq * (sq + 1);
    const int q0 = sq * 256, k0 = kt * 128;

    for (int i = tid; i < 256 * TOPK; i += 256) {
        tval[i] = -INFINITY;
        tidx[i] = 0;
    }

    float4 acc[4][8];
    mma_mainloop(sm, Qhi, Qlo, Khi, Klo,
                 b * 256 + sq * 16, b * 512 + kt * 16, acc);

#pragma unroll
    for (int rh = 0; rh < 2; rh++) {
#pragma unroll
        for (int h = 0; h < 2; h++) {
            if ((wy >> 1) == rh && wx == h) {
#pragma unroll
                for (int i = 0; i < 4; i++) {
                    const int rl = wy * 64 + i * 16 + g;
                    const int srow = rl - rh * 128;
#pragma unroll
                    for (int j = 0; j < 8; j++) {
                        const int col = j * 8 + t * 2;
                        const int gc = k0 + h * 64 + col;
                        const int gr0 = q0 + rl, gr1 = gr0 + 8;
                        float v0 = acc[i][j].x * 0.03125f;
                        float v1 = acc[i][j].y * 0.03125f;
                        float v2 = acc[i][j].z * 0.03125f;
                        float v3 = acc[i][j].w * 0.03125f;
                        if (gc + 0 > gr0) v0 = -INFINITY;
                        if (gc + 1 > gr0) v1 = -INFINITY;
                        if (gc + 0 > gr1) v2 = -INFINITY;
                        if (gc + 1 > gr1) v3 = -INFINITY;
                        *(float2*)&sc[srow * 72 + col] = make_float2(v0, v1);
                        *(float2*)&sc[(srow + 8) * 72 + col] = make_float2(v2, v3);
                    }
                }
            }
            __syncthreads();
            if (tid < 128) {
                const int row = rh * 128 + tid;
                float tv[TOPK]; int ti[TOPK];
#pragma unroll
                for (int j = 0; j < TOPK; j++) { tv[j] = tval[row * 8 + j]; ti[j] = tidx[row * 8 + j]; }
                float vmin = tv[0]; int mpos = 0;
#pragma unroll
                for (int j = 1; j < TOPK; j++) if (tv[j] < vmin) { vmin = tv[j]; mpos = j; }
                const int cbase = k0 + h * 64;
                for (int cc = 0; cc < 64; cc++) {
                    const float vv = sc[tid * 72 + cc];
                    if (vv > vmin) {
                        tv[mpos] = vv; ti[mpos] = cbase + cc;
                        vmin = tv[0]; mpos = 0;
#pragma unroll
                        for (int j = 1; j < TOPK; j++) if (tv[j] < vmin) { vmin = tv[j]; mpos = j; }
                    }
                }
#pragma unroll
                for (int j = 0; j < TOPK; j++) { tval[row * 8 + j] = tv[j]; tidx[row * 8 + j] = ti[j]; }
            }
            __syncthreads();
        }
    }

    const size_t base = (((size_t)b * NSB + bidx) * 256 + tid) * TOPK;
#pragma unroll
    for (int j = 0; j < TOPK; j++) {
        pval[base + j] = tval[tid * 8 + j];
        pidx[base + j] = tidx[tid * 8 + j];
    }
}

// ---------------- merge per-row partial top-8 lists + softmax ----------------
__global__ __launch_bounds__(256) void merge_softmax_kernel(
    const float* __restrict__ pv, const int* __restrict__ pi,
    float* __restrict__ probs, int* __restrict__ idxs) {
    const int row = blockIdx.x * 256 + threadIdx.x;
    if (row >= MROWS) return;
    const int b = row >> 12, rr = row & 4095;
    const int qt = rr >> 7;
    const int sq = qt >> 1;
    const int rib = rr - sq * 256;
    const size_t sbase = ((size_t)b * NSB + (size_t)sq * (sq + 1)) * 256 + rib;

    float tv[TOPK]; int ti[TOPK];
#pragma unroll
    for (int j = 0; j < TOPK; j++) { tv[j] = -INFINITY; ti[j] = 0; }
    float vmin = -INFINITY; int mpos = 0;

    for (int kt = 0; kt <= qt; kt++) {
        const size_t base = (sbase + (size_t)kt * 256) * TOPK;
#pragma unroll
        for (int j = 0; j < TOPK; j++) {
            const float vv = pv[base + j];
            if (vv > vmin) {
                tv[mpos] = vv; ti[mpos] = pi[base + j];
                vmin = tv[0]; mpos = 0;
#pragma unroll
                for (int q = 1; q < TOPK; q++) if (tv[q] < vmin) { vmin = tv[q]; mpos = q; }
            }
        }
    }

    float mx = tv[0];
#pragma unroll
    for (int j = 1; j < TOPK; j++) mx = fmaxf(mx, tv[j]);
    float e[TOPK]; float ssum = 0.f;
#pragma unroll
    for (int j = 0; j < TOPK; j++) { e[j] = expf(tv[j] - mx); ssum += e[j]; }
    const float inv = 1.f / ssum;
    const size_t obase = (size_t)row * TOPK;
#pragma unroll
    for (int j = 0; j < TOPK; j++) { probs[obase + j] = e[j] * inv; idxs[obase + j] = ti[j]; }
}

// ---------------- sparse gather of U + bvo -> out -----------------------------
__global__ __launch_bounds__(128) void gather_out_kernel(
    const float* __restrict__ U, const float* __restrict__ probs,
    const int* __restrict__ idxs, const float* __restrict__ bvo,
    float* __restrict__ out) {
    const int row = blockIdx.x;
    const int b = row >> 12;
    const int tid = threadIdx.x;
    __shared__ float p[TOPK];
    __shared__ int   id[TOPK];
    if (tid < TOPK) {
        p[tid]  = probs[(size_t)row * TOPK + tid];
        id[tid] = idxs[(size_t)row * TOPK + tid];
    }
    __syncthreads();
    const float* ub = U + (size_t)b * NSEQ * DIM;
    const int c = tid * 8;
    float4 a0 = *(const float4*)(bvo + c);
    float4 a1 = *(const float4*)(bvo + c + 4);
#pragma unroll
    for (int j = 0; j < TOPK; j++) {
        const float4* vr = (const float4*)(ub + (size_t)id[j] * DIM + c);
        const float pj = p[j];
        float4 v0 = vr[0], v1 = vr[1];
        a0.x += pj * v0.x; a0.y += pj * v0.y; a0.z += pj * v0.z; a0.w += pj * v0.w;
        a1.x += pj * v1.x; a1.y += pj * v1.y; a1.z += pj * v1.z; a1.w += pj * v1.w;
    }
    float4* orow = (float4*)(out + (size_t)row * DIM + c);
    orow[0] = a0; orow[1] = a1;
}

// ---------------- launch -----------------------------------------------------
extern "C" void kernel_launch(void* const* d_in, const int* in_sizes, int n_in,
                              void* d_out, int out_size) {
    const float* S  = (const float*)d_in[0];
    const float* Wq = (const float*)d_in[1];
    const float* bq = (const float*)d_in[2];
    const float* Wk = (const float*)d_in[3];
    const float* bk = (const float*)d_in[4];
    const float* Wv = (const float*)d_in[5];
    const float* bv = (const float*)d_in[6];
    const float* Wo = (const float*)d_in[7];
    const float* bo = (const float*)d_in[8];
    float* out = (float*)d_out;

    float *up, *pp, *pvp, *ahip, *alop;
    float *qhip, *qlop, *khip, *klop, *wthip, *wtlop, *wohip, *wolop;
    float *bvop, *zerop;
    int *ip, *pip;
    cudaGetSymbolAddress((void**)&up, g_u);
    cudaGetSymbolAddress((void**)&pp, g_probs);
    cudaGetSymbolAddress((void**)&ip, g_topidx);
    cudaGetSymbolAddress((void**)&pvp, g_pval);
    cudaGetSymbolAddress((void**)&pip, g_pidx);
    cudaGetSymbolAddress((void**)&ahip, g_ahi);
    cudaGetSymbolAddress((void**)&alop, g_alo);
    cudaGetSymbolAddress((void**)&qhip, g_qhi);
    cudaGetSymbolAddress((void**)&qlop, g_qlo);
    cudaGetSymbolAddress((void**)&khip, g_khi);
    cudaGetSymbolAddress((void**)&klop, g_klo);
    cudaGetSymbolAddress((void**)&wthip, g_wthi);
    cudaGetSymbolAddress((void**)&wtlop, g_wtlo);
    cudaGetSymbolAddress((void**)&wohip, g_wohi);
    cudaGetSymbolAddress((void**)&wolop, g_wolo);
    cudaGetSymbolAddress((void**)&bvop, g_bvo);
    cudaGetSymbolAddress((void**)&zerop, g_zerob);

    cudaFuncSetAttribute(gemm_qkv_kernel,
                         cudaFuncAttributeMaxDynamicSharedMemorySize, GEMM_SMEM);
    cudaFuncSetAttribute(gemm_mma_kernel,
                         cudaFuncAttributeMaxDynamicSharedMemorySize, GEMM_SMEM);
    cudaFuncSetAttribute(scores_super_kernel,
                         cudaFuncAttributeMaxDynamicSharedMemorySize, SSC_SMEM);

    const size_t WSZ = (size_t)DIM * DIM;
    const int WPACK_GRID = (DIM / 8) * KS8 / 8;   // 2048

    // --- Wvo = Wv @ Wo prep chain (tiny) ---
    split_pack_w<<<WPACK_GRID, 256>>>(Wo, (float2*)wohip, (float2*)wolop);
    // pack Wv rows A-format into ahip/alop (first 1024 rows)
    split_pack_a<<<(DIM / 16) * KS8 / 8, 256>>>(Wv, (float4*)ahip, (float4*)alop);
    // Wvo raw -> g_u (overwritten later by U)
    gemm_mma_kernel<<<dim3(DIM / 128, DIM / 256), 256, GEMM_SMEM>>>(
        ahip, alop, wohip, wolop, zerop, up);
    // Wvo -> B-format slot 2
    split_pack_w<<<WPACK_GRID, 256>>>(up, (float2*)(wthip + 2 * WSZ), (float2*)(wtlop + 2 * WSZ));
    bvo_kernel<<<DIM / 128, 128>>>(bv, Wo, bo, bvop);

    // --- Wq / Wk packs ---
    split_pack_w<<<WPACK_GRID, 256>>>(Wq, (float2*)(wthip + 0 * WSZ), (float2*)(wtlop + 0 * WSZ));
    split_pack_w<<<WPACK_GRID, 256>>>(Wk, (float2*)(wthip + 1 * WSZ), (float2*)(wtlop + 1 * WSZ));

    // --- S pack (overwrites Wv pack; done with it) ---
    split_pack_a<<<(MROWS / 16) * KS8 / 8, 256>>>(S, (float4*)ahip, (float4*)alop);

    // fused: q -> packed A-fmt, k -> packed B-fmt, U = S@Wvo raw (zero bias)
    gemm_qkv_kernel<<<dim3(24, MROWS / 256), 256, GEMM_SMEM>>>(
        ahip, alop, wthip, wtlop, bq, bk, zerop, qhip, qlop, khip, klop, up);

    scores_super_kernel<<<dim3(NSB, BSZ), 256, SSC_SMEM>>>(
        qhip, qlop, khip, klop, pvp, pip);
    merge_softmax_kernel<<<(MROWS + 255) / 256, 256>>>(pvp, pip, pp, ip);
    gather_out_kernel<<<MROWS, 128>>>(up, pp, ip, bvop, out);
}

// round 11
// speedup vs baseline: 2.8678x; 1.1050x over previous
#include <cuda_runtime.h>
#include <math.h>
#include <stdint.h>

#define BSZ   4
#define NSEQ  4096
#define DIM   1024
#define TOPK  8
#define MROWS (BSZ * NSEQ)
#define KS8   (DIM / 8)   // 128 k-steps of 8
#define NSB   272         // supertile score blocks per batch

typedef unsigned long long ULL;

// ---------------- scratch (__device__ globals; no allocation allowed) -------
__device__ __align__(128) float g_u[(size_t)MROWS * DIM];   // temp Wvo/G, then U
__device__ float g_probs[(size_t)MROWS * TOPK];
__device__ int   g_topidx[(size_t)MROWS * TOPK];
__device__ float g_pval[(size_t)BSZ * NSB * 256 * TOPK];
__device__ int   g_pidx[(size_t)BSZ * NSB * 256 * TOPK];
__device__ float g_bvo[DIM];
__device__ float g_y[DIM];       // y = Wk @ bq
__device__ float g_w[MROWS];     // w = (S @ y) / 32  (per-key score correction)
__device__ float g_zerob[DIM];   // zero bias (device globals zero-init)
// fragment-packed 3xTF32 buffers
__device__ __align__(128) float g_ahi[(size_t)MROWS * DIM];   // A-fmt (S / Wv / Wq)
__device__ __align__(128) float g_alo[(size_t)MROWS * DIM];
__device__ __align__(128) float g_qhi[(size_t)MROWS * DIM];   // A-fmt (T)
__device__ __align__(128) float g_qlo[(size_t)MROWS * DIM];
__device__ __align__(128) float g_khi[(size_t)MROWS * DIM];   // B-fmt (Wk then S)
__device__ __align__(128) float g_klo[(size_t)MROWS * DIM];
__device__ __align__(128) float g_wthi[2][(size_t)DIM * DIM]; // B-fmt G / Wvo
__device__ __align__(128) float g_wtlo[2][(size_t)DIM * DIM];
__device__ __align__(128) float g_wohi[(size_t)DIM * DIM];    // B-fmt Wo
__device__ __align__(128) float g_wolo[(size_t)DIM * DIM];

// ---------------- helpers -----------------------------------------------------
__device__ __forceinline__ uint32_t smem_u32(const void* p) {
    uint32_t a;
    asm("{ .reg .u64 t; cvta.to.shared.u64 t, %1; cvt.u32.u64 %0, t; }"
        : "=r"(a) : "l"(p));
    return a;
}
__device__ __forceinline__ float tf32r(float x) {
    uint32_t u;
    asm("cvt.rna.tf32.f32 %0, %1;" : "=r"(u) : "f"(x));
    return __uint_as_float(u);
}
__device__ __forceinline__ void cpasync16(uint32_t saddr, const void* g) {
    asm volatile("cp.async.cg.shared.global [%0], [%1], 16;"
                 :: "r"(saddr), "l"(g));
}
#define CP_COMMIT() asm volatile("cp.async.commit_group;" ::: "memory")
#define CP_WAIT_1() asm volatile("cp.async.wait_group 1;" ::: "memory")
#define CP_WAIT_0() asm volatile("cp.async.wait_group 0;" ::: "memory")

__device__ __forceinline__ void mma8(float4& c, const uint4& a, const uint2& b) {
    asm volatile(
        "mma.sync.aligned.m16n8k8.row.col.f32.tf32.tf32.f32 "
        "{%0,%1,%2,%3}, {%4,%5,%6,%7}, {%8,%9}, {%0,%1,%2,%3};"
        : "+f"(c.x), "+f"(c.y), "+f"(c.z), "+f"(c.w)
        : "r"(a.x), "r"(a.y), "r"(a.z), "r"(a.w), "r"(b.x), "r"(b.y));
}

// ---------------- split+pack A-format: X[M,K] row-major ---------------------
__global__ __launch_bounds__(256) void split_pack_a(
    const float* __restrict__ X, float4* __restrict__ Phi, float4* __restrict__ Plo) {
    const int atom = blockIdx.x * 8 + (threadIdx.x >> 5);
    const int lane = threadIdx.x & 31;
    const int mt = atom >> 7;
    const int ks = atom & 127;
    const int g = lane >> 2, t = lane & 3;
    const size_t r0 = (size_t)(mt * 16 + g) * DIM + ks * 8 + t;
    const size_t r1 = r0 + 8 * DIM;
    float x0 = X[r0], x1 = X[r1], x2 = X[r0 + 4], x3 = X[r1 + 4];
    float4 h, l;
    h.x = tf32r(x0); l.x = tf32r(x0 - h.x);
    h.y = tf32r(x1); l.y = tf32r(x1 - h.y);
    h.z = tf32r(x2); l.z = tf32r(x2 - h.z);
    h.w = tf32r(x3); l.w = tf32r(x3 - h.w);
    Phi[(size_t)atom * 32 + lane] = h;
    Plo[(size_t)atom * 32 + lane] = l;
}

// ---------------- split+pack W (B-format): W[K,N] -> [N/8][K/8][lane][2] ----
__global__ __launch_bounds__(256) void split_pack_w(
    const float* __restrict__ W, float2* __restrict__ Phi, float2* __restrict__ Plo) {
    const int atom = blockIdx.x * 8 + (threadIdx.x >> 5);
    const int lane = threadIdx.x & 31;
    const int nt = atom >> 7;
    const int ks = atom & 127;
    const int g = lane >> 2, t = lane & 3;
    float x0 = W[(size_t)(ks * 8 + t) * DIM + nt * 8 + g];
    float x1 = W[(size_t)(ks * 8 + t + 4) * DIM + nt * 8 + g];
    float2 h, l;
    h.x = tf32r(x0); l.x = tf32r(x0 - h.x);
    h.y = tf32r(x1); l.y = tf32r(x1 - h.y);
    Phi[(size_t)atom * 32 + lane] = h;
    Plo[(size_t)atom * 32 + lane] = l;
}

// ---------------- split+pack row-major [N,K] -> B-format ---------------------
__global__ __launch_bounds__(256) void split_pack_kb(
    const float* __restrict__ X, float2* __restrict__ Phi, float2* __restrict__ Plo) {
    const int atom = blockIdx.x * 8 + (threadIdx.x >> 5);
    const int lane = threadIdx.x & 31;
    const int nt = atom >> 7;
    const int ks = atom & 127;
    const int g = lane >> 2, t = lane & 3;
    const size_t base = (size_t)(nt * 8 + g) * DIM + ks * 8 + t;
    float x0 = X[base];
    float x1 = X[base + 4];
    float2 h, l;
    h.x = tf32r(x0); l.x = tf32r(x0 - h.x);
    h.y = tf32r(x1); l.y = tf32r(x1 - h.y);
    Phi[(size_t)atom * 32 + lane] = h;
    Plo[(size_t)atom * 32 + lane] = l;
}

// ---------------- bvo = bv @ Wo + bo ----------------------------------------
__global__ __launch_bounds__(128) void bvo_kernel(
    const float* __restrict__ bv, const float* __restrict__ Wo,
    const float* __restrict__ bo, float* __restrict__ bvo) {
    const int n = blockIdx.x * 128 + threadIdx.x;
    float acc = bo[n];
    for (int k = 0; k < DIM; k++) acc += bv[k] * Wo[(size_t)k * DIM + n];
    bvo[n] = acc;
}

// ---------------- y[d] = Wk[d,:] . bq  (one warp per row) --------------------
__global__ __launch_bounds__(256) void ydot_kernel(
    const float* __restrict__ Wk, const float* __restrict__ bq,
    float* __restrict__ y) {
    const int wid = threadIdx.x >> 5, lane = threadIdx.x & 31;
    const int row = blockIdx.x * 8 + wid;
    const float4* r4 = (const float4*)(Wk + (size_t)row * DIM);
    const float4* b4 = (const float4*)bq;
    float acc = 0.f;
    for (int i = lane; i < DIM / 4; i += 32) {
        float4 a = r4[i], b = b4[i];
        acc += a.x * b.x + a.y * b.y + a.z * b.z + a.w * b.w;
    }
#pragma unroll
    for (int o = 16; o; o >>= 1) acc += __shfl_xor_sync(0xffffffffu, acc, o);
    if (lane == 0) y[row] = acc;
}

// ---------------- w[m] = (S[m,:] . y) / 32  (one warp per row) ---------------
__global__ __launch_bounds__(256) void wdot_kernel(
    const float* __restrict__ S, const float* __restrict__ y,
    float* __restrict__ w) {
    const int wid = threadIdx.x >> 5, lane = threadIdx.x & 31;
    const int row = blockIdx.x * 8 + wid;
    const float4* r4 = (const float4*)(S + (size_t)row * DIM);
    const float4* y4 = (const float4*)y;
    float acc = 0.f;
    for (int i = lane; i < DIM / 4; i += 32) {
        float4 a = r4[i], b = y4[i];
        acc += a.x * b.x + a.y * b.y + a.z * b.z + a.w * b.w;
    }
#pragma unroll
    for (int o = 16; o; o >>= 1) acc += __shfl_xor_sync(0xffffffffu, acc, o);
    if (lane == 0) w[row] = acc * 0.03125f;
}

// ---------------- shared 3xTF32 mainloop (256x128 tile, BK=16, 3 stages) ----
#define GEMM_SMEM (3 * 12288 * 4)

__device__ __forceinline__ void mma_mainloop(
    float* sm, const float* __restrict__ Ahi, const float* __restrict__ Alo,
    const float* __restrict__ Bhi, const float* __restrict__ Blo,
    int br16, int bn16, float4 (&acc)[4][8]) {
    const int tid = threadIdx.x;
    const int lane = tid & 31, wid = tid >> 5;
    const int wy = wid >> 1, wx = wid & 1;
    const uint32_t smb = smem_u32(sm);

    auto load_stage = [&](int kc, int s) {
        const uint32_t sb = smb + s * 49152;
#pragma unroll
        for (int j = 0; j < 4; j++) {
            const int cA = tid + j * 256;
            const int mtl = cA >> 6, off = cA & 63;
            const uint32_t so = sb + (uint32_t)(mtl * 256 + off * 4) * 4;
            const size_t go = ((size_t)(br16 + mtl) * KS8 + kc * 2) * 128 + off * 4;
            cpasync16(so, Ahi + go);
            cpasync16(so + 4096 * 4, Alo + go);
        }
#pragma unroll
        for (int j = 0; j < 2; j++) {
            const int cB = tid + j * 256;
            const int ntl = cB >> 5, off = cB & 31;
            const uint32_t so = sb + (uint32_t)(8192 + ntl * 128 + off * 4) * 4;
            const size_t go = ((size_t)(bn16 + ntl) * KS8 + kc * 2) * 64 + off * 4;
            cpasync16(so, Bhi + go);
            cpasync16(so + 2048 * 4, Blo + go);
        }
    };

    load_stage(0, 0); CP_COMMIT();
    load_stage(1, 1); CP_COMMIT();

#pragma unroll
    for (int i = 0; i < 4; i++)
#pragma unroll
        for (int j = 0; j < 8; j++) acc[i][j] = make_float4(0.f, 0.f, 0.f, 0.f);

    for (int c = 0; c < 64; c++) {
        if (c < 62) { CP_WAIT_1(); } else { CP_WAIT_0(); }
        __syncthreads();
        if (c + 2 < 64) { load_stage(c + 2, (c + 2) % 3); CP_COMMIT(); }
        const float* st = sm + (c % 3) * 12288;
#pragma unroll
        for (int ks = 0; ks < 2; ks++) {
            uint4 Ah[4], Al[4];
            uint2 Bh[8], Bl[8];
#pragma unroll
            for (int i = 0; i < 4; i++) {
                const float* p = st + ((wy * 4 + i) * 2 + ks) * 128 + lane * 4;
                Ah[i] = *(const uint4*)p;
                Al[i] = *(const uint4*)(p + 4096);
            }
#pragma unroll
            for (int j = 0; j < 8; j++) {
                const float* p = st + 8192 + ((wx * 8 + j) * 2 + ks) * 64 + lane * 2;
                Bh[j] = *(const uint2*)p;
                Bl[j] = *(const uint2*)(p + 2048);
            }
#pragma unroll
            for (int i = 0; i < 4; i++)
#pragma unroll
                for (int j = 0; j < 8; j++) {
                    mma8(acc[i][j], Ah[i], Bh[j]);
                    mma8(acc[i][j], Ah[i], Bl[j]);
                    mma8(acc[i][j], Al[i], Bh[j]);
                }
        }
    }
}

// Fused T/U projection. wsel 0 -> T = S@G packed A-fmt (no bias),
// wsel 1 -> U = S@Wvo raw (no bias). grid (16, 64).
__global__ __launch_bounds__(256, 1) void gemm_tu_kernel(
    const float* __restrict__ Ahi, const float* __restrict__ Alo,
    const float* __restrict__ Whi, const float* __restrict__ Wlo,
    float* __restrict__ Thi, float* __restrict__ Tlo,
    float* __restrict__ U) {
    extern __shared__ float sm[];
    const int wsel = blockIdx.x & 1;
    const int nxt = blockIdx.x >> 1;   // 0..7
    const int tid = threadIdx.x;
    const int lane = tid & 31, wid = tid >> 5;
    const int wy = wid >> 1, wx = wid & 1;
    const int g = lane >> 2, t = lane & 3;
    const int m0 = blockIdx.y * 256, n0 = nxt * 128;

    float4 acc[4][8];
    mma_mainloop(sm, Ahi, Alo,
                 Whi + (size_t)wsel * DIM * DIM, Wlo + (size_t)wsel * DIM * DIM,
                 blockIdx.y * 16, nxt * 16, acc);

    if (wsel == 1) {
        // raw U (no bias)
#pragma unroll
        for (int i = 0; i < 4; i++) {
            const int r0 = m0 + wy * 64 + i * 16 + g;
#pragma unroll
            for (int j = 0; j < 8; j++) {
                const int col = n0 + wx * 64 + j * 8 + t * 2;
                *(float2*)(U + (size_t)r0 * DIM + col) =
                    make_float2(acc[i][j].x, acc[i][j].y);
                *(float2*)(U + (size_t)(r0 + 8) * DIM + col) =
                    make_float2(acc[i][j].z, acc[i][j].w);
            }
        }
        return;
    }

    // stage T tile to smem, then repack A-format
    __syncthreads();  // pipeline smem free
#pragma unroll
    for (int i = 0; i < 4; i++) {
        const int r0 = wy * 64 + i * 16 + g;
#pragma unroll
        for (int j = 0; j < 8; j++) {
            const int col = wx * 64 + j * 8 + t * 2;
            *(float2*)&sm[r0 * 132 + col] = make_float2(acc[i][j].x, acc[i][j].y);
            *(float2*)&sm[(r0 + 8) * 132 + col] = make_float2(acc[i][j].z, acc[i][j].w);
        }
    }
    __syncthreads();

    for (int a = wid; a < 256; a += 8) {
        const int amt = a >> 4, aks = a & 15;
        const float* bp = sm + (amt * 16 + g) * 132 + aks * 8 + t;
        float x0 = bp[0], x1 = bp[8 * 132], x2 = bp[4], x3 = bp[8 * 132 + 4];
        float4 h, l;
        h.x = tf32r(x0); l.x = tf32r(x0 - h.x);
        h.y = tf32r(x1); l.y = tf32r(x1 - h.y);
        h.z = tf32r(x2); l.z = tf32r(x2 - h.z);
        h.w = tf32r(x3); l.w = tf32r(x3 - h.w);
        const size_t atom = (size_t)(blockIdx.y * 16 + amt) * KS8 + (nxt * 16 + aks);
        ((float4*)Thi)[atom * 32 + lane] = h;
        ((float4*)Tlo)[atom * 32 + lane] = l;
    }
}

// Single GEMM (prep: Wvo = Wv@Wo, G = Wq@Wk^T): raw epilogue + bias.
__global__ __launch_bounds__(256, 1) void gemm_mma_kernel(
    const float* __restrict__ Ahi, const float* __restrict__ Alo,
    const float* __restrict__ Bhi, const float* __restrict__ Blo,
    const float* __restrict__ bias, float* __restrict__ C) {
    extern __shared__ float sm[];
    const int tid = threadIdx.x;
    const int lane = tid & 31, wid = tid >> 5;
    const int wy = wid >> 1, wx = wid & 1;
    const int g = lane >> 2, t = lane & 3;
    const int m0 = blockIdx.y * 256, n0 = blockIdx.x * 128;
    float4 acc[4][8];
    mma_mainloop(sm, Ahi, Alo, Bhi, Blo, blockIdx.y * 16, blockIdx.x * 16, acc);
#pragma unroll
    for (int i = 0; i < 4; i++) {
        const int r0 = m0 + wy * 64 + i * 16 + g;
#pragma unroll
        for (int j = 0; j < 8; j++) {
            const int col = n0 + wx * 64 + j * 8 + t * 2;
            const float2 bb = *(const float2*)(bias + col);
            *(float2*)(C + (size_t)r0 * DIM + col) =
                make_float2(acc[i][j].x + bb.x, acc[i][j].y + bb.y);
            *(float2*)(C + (size_t)(r0 + 8) * DIM + col) =
                make_float2(acc[i][j].z + bb.x, acc[i][j].w + bb.y);
        }
    }
}

// ---------------- supertile 3xTF32 causal scores + top-8 --------------------
// scores = T . S^T * (1/32) + w_m  (w pre-scaled); row-const terms dropped
// (softmax shift-invariant, cannot change top-k order).
#define SSC_SMEM ((3 * 12288 + 128 * 72 + 256 * 8 + 256 * 8 + 128) * 4)

__global__ __launch_bounds__(256, 1) void scores_super_kernel(
    const float* __restrict__ Thi, const float* __restrict__ Tlo,
    const float* __restrict__ Shi, const float* __restrict__ Slo,
    const float* __restrict__ w,
    float* __restrict__ pval, int* __restrict__ pidx) {
    extern __shared__ float sm[];
    float* sc = sm + 36864;           // [128][72]
    float* tval = sm + 46080;         // [256][8]
    int* tidx = (int*)(sm + 48128);   // [256][8]
    float* wsc = sm + 50176;          // [128]

    const int tid = threadIdx.x;
    const int lane = tid & 31, wid = tid >> 5;
    const int wy = wid >> 1, wx = wid & 1;
    const int g = lane >> 2, t = lane & 3;
    const int b = blockIdx.y;
    const int bidx = blockIdx.x;

    int sq = (int)((sqrtf(4.0f * (float)bidx + 1.0f) - 1.0f) * 0.5f);
    while ((sq + 1) * (sq + 2) <= bidx) sq++;
    while (sq * (sq + 1) > bidx) sq--;
    const int kt = bidx - sq * (sq + 1);
    const int q0 = sq * 256, k0 = kt * 128;

    for (int i = tid; i < 256 * TOPK; i += 256) {
        tval[i] = -INFINITY;
        tidx[i] = 0;
    }
    if (tid < 128) wsc[tid] = w[b * NSEQ + k0 + tid];

    float4 acc[4][8];
    mma_mainloop(sm, Thi, Tlo, Shi, Slo,
                 b * 256 + sq * 16, b * 512 + kt * 16, acc);

#pragma unroll
    for (int rh = 0; rh < 2; rh++) {
#pragma unroll
        for (int h = 0; h < 2; h++) {
            if ((wy >> 1) == rh && wx == h) {
#pragma unroll
                for (int i = 0; i < 4; i++) {
                    const int rl = wy * 64 + i * 16 + g;
                    const int srow = rl - rh * 128;
#pragma unroll
                    for (int j = 0; j < 8; j++) {
                        const int col = j * 8 + t * 2;
                        const int lc = h * 64 + col;
                        const int gc = k0 + lc;
                        const int gr0 = q0 + rl, gr1 = gr0 + 8;
                        const float w0 = wsc[lc], w1 = wsc[lc + 1];
                        float v0 = acc[i][j].x * 0.03125f + w0;
                        float v1 = acc[i][j].y * 0.03125f + w1;
                        float v2 = acc[i][j].z * 0.03125f + w0;
                        float v3 = acc[i][j].w * 0.03125f + w1;
                        if (gc + 0 > gr0) v0 = -INFINITY;
                        if (gc + 1 > gr0) v1 = -INFINITY;
                        if (gc + 0 > gr1) v2 = -INFINITY;
                        if (gc + 1 > gr1) v3 = -INFINITY;
                        *(float2*)&sc[srow * 72 + col] = make_float2(v0, v1);
                        *(float2*)&sc[(srow + 8) * 72 + col] = make_float2(v2, v3);
                    }
                }
            }
            __syncthreads();
            if (tid < 128) {
                const int row = rh * 128 + tid;
                float tv[TOPK]; int ti[TOPK];
#pragma unroll
                for (int j = 0; j < TOPK; j++) { tv[j] = tval[row * 8 + j]; ti[j] = tidx[row * 8 + j]; }
                float vmin = tv[0]; int mpos = 0;
#pragma unroll
                for (int j = 1; j < TOPK; j++) if (tv[j] < vmin) { vmin = tv[j]; mpos = j; }
                const int cbase = k0 + h * 64;
                for (int cc = 0; cc < 64; cc++) {
                    const float vv = sc[tid * 72 + cc];
                    if (vv > vmin) {
                        tv[mpos] = vv; ti[mpos] = cbase + cc;
                        vmin = tv[0]; mpos = 0;
#pragma unroll
                        for (int j = 1; j < TOPK; j++) if (tv[j] < vmin) { vmin = tv[j]; mpos = j; }
                    }
                }
#pragma unroll
                for (int j = 0; j < TOPK; j++) { tval[row * 8 + j] = tv[j]; tidx[row * 8 + j] = ti[j]; }
            }
            __syncthreads();
        }
    }

    const size_t base = (((size_t)b * NSB + bidx) * 256 + tid) * TOPK;
#pragma unroll
    for (int j = 0; j < TOPK; j++) {
        pval[base + j] = tval[tid * 8 + j];
        pidx[base + j] = tidx[tid * 8 + j];
    }
}

// ---------------- merge per-row partial top-8 lists + softmax ----------------
__global__ __launch_bounds__(256) void merge_softmax_kernel(
    const float* __restrict__ pv, const int* __restrict__ pi,
    float* __restrict__ probs, int* __restrict__ idxs) {
    const int row = blockIdx.x * 256 + threadIdx.x;
    if (row >= MROWS) return;
    const int b = row >> 12, rr = row & 4095;
    const int qt = rr >> 7;
    const int sq = qt >> 1;
    const int rib = rr - sq * 256;
    const size_t sbase = ((size_t)b * NSB + (size_t)sq * (sq + 1)) * 256 + rib;

    float tv[TOPK]; int ti[TOPK];
#pragma unroll
    for (int j = 0; j < TOPK; j++) { tv[j] = -INFINITY; ti[j] = 0; }
    float vmin = -INFINITY; int mpos = 0;

    for (int kt = 0; kt <= qt; kt++) {
        const size_t base = (sbase + (size_t)kt * 256) * TOPK;
#pragma unroll
        for (int j = 0; j < TOPK; j++) {
            const float vv = pv[base + j];
            if (vv > vmin) {
                tv[mpos] = vv; ti[mpos] = pi[base + j];
                vmin = tv[0]; mpos = 0;
#pragma unroll
                for (int q = 1; q < TOPK; q++) if (tv[q] < vmin) { vmin = tv[q]; mpos = q; }
            }
        }
    }

    float mx = tv[0];
#pragma unroll
    for (int j = 1; j < TOPK; j++) mx = fmaxf(mx, tv[j]);
    float e[TOPK]; float ssum = 0.f;
#pragma unroll
    for (int j = 0; j < TOPK; j++) { e[j] = expf(tv[j] - mx); ssum += e[j]; }
    const float inv = 1.f / ssum;
    const size_t obase = (size_t)row * TOPK;
#pragma unroll
    for (int j = 0; j < TOPK; j++) { probs[obase + j] = e[j] * inv; idxs[obase + j] = ti[j]; }
}

// ---------------- sparse gather of U + bvo -> out -----------------------------
__global__ __launch_bounds__(128) void gather_out_kernel(
    const float* __restrict__ U, const float* __restrict__ probs,
    const int* __restrict__ idxs, const float* __restrict__ bvo,
    float* __restrict__ out) {
    const int row = blockIdx.x;
    const int b = row >> 12;
    const int tid = threadIdx.x;
    __shared__ float p[TOPK];
    __shared__ int   id[TOPK];
    if (tid < TOPK) {
        p[tid]  = probs[(size_t)row * TOPK + tid];
        id[tid] = idxs[(size_t)row * TOPK + tid];
    }
    __syncthreads();
    const float* ub = U + (size_t)b * NSEQ * DIM;
    const int c = tid * 8;
    float4 a0 = *(const float4*)(bvo + c);
    float4 a1 = *(const float4*)(bvo + c + 4);
#pragma unroll
    for (int j = 0; j < TOPK; j++) {
        const float4* vr = (const float4*)(ub + (size_t)id[j] * DIM + c);
        const float pj = p[j];
        float4 v0 = vr[0], v1 = vr[1];
        a0.x += pj * v0.x; a0.y += pj * v0.y; a0.z += pj * v0.z; a0.w += pj * v0.w;
        a1.x += pj * v1.x; a1.y += pj * v1.y; a1.z += pj * v1.z; a1.w += pj * v1.w;
    }
    float4* orow = (float4*)(out + (size_t)row * DIM + c);
    orow[0] = a0; orow[1] = a1;
}

// ---------------- launch -----------------------------------------------------
extern "C" void kernel_launch(void* const* d_in, const int* in_sizes, int n_in,
                              void* d_out, int out_size) {
    const float* S  = (const float*)d_in[0];
    const float* Wq = (const float*)d_in[1];
    const float* bq = (const float*)d_in[2];
    const float* Wk = (const float*)d_in[3];
    const float* bk = (const float*)d_in[4];  // (row-const in softmax; drops out)
    const float* Wv = (const float*)d_in[5];
    const float* bv = (const float*)d_in[6];
    const float* Wo = (const float*)d_in[7];
    const float* bo = (const float*)d_in[8];
    float* out = (float*)d_out;
    (void)bk;

    float *up, *pp, *pvp, *ahip, *alop;
    float *qhip, *qlop, *khip, *klop, *wthip, *wtlop, *wohip, *wolop;
    float *bvop, *zerop, *yp, *wp;
    int *ip, *pip;
    cudaGetSymbolAddress((void**)&up, g_u);
    cudaGetSymbolAddress((void**)&pp, g_probs);
    cudaGetSymbolAddress((void**)&ip, g_topidx);
    cudaGetSymbolAddress((void**)&pvp, g_pval);
    cudaGetSymbolAddress((void**)&pip, g_pidx);
    cudaGetSymbolAddress((void**)&ahip, g_ahi);
    cudaGetSymbolAddress((void**)&alop, g_alo);
    cudaGetSymbolAddress((void**)&qhip, g_qhi);
    cudaGetSymbolAddress((void**)&qlop, g_qlo);
    cudaGetSymbolAddress((void**)&khip, g_khi);
    cudaGetSymbolAddress((void**)&klop, g_klo);
    cudaGetSymbolAddress((void**)&wthip, g_wthi);
    cudaGetSymbolAddress((void**)&wtlop, g_wtlo);
    cudaGetSymbolAddress((void**)&wohip, g_wohi);
    cudaGetSymbolAddress((void**)&wolop, g_wolo);
    cudaGetSymbolAddress((void**)&bvop, g_bvo);
    cudaGetSymbolAddress((void**)&zerop, g_zerob);
    cudaGetSymbolAddress((void**)&yp, g_y);
    cudaGetSymbolAddress((void**)&wp, g_w);

    cudaFuncSetAttribute(gemm_tu_kernel,
                         cudaFuncAttributeMaxDynamicSharedMemorySize, GEMM_SMEM);
    cudaFuncSetAttribute(gemm_mma_kernel,
                         cudaFuncAttributeMaxDynamicSharedMemorySize, GEMM_SMEM);
    cudaFuncSetAttribute(scores_super_kernel,
                         cudaFuncAttributeMaxDynamicSharedMemorySize, SSC_SMEM);

    const size_t WSZ = (size_t)DIM * DIM;
    const int WPACK_GRID = (DIM / 8) * KS8 / 8;   // 2048
    const int APACK_1K = (DIM / 16) * KS8 / 8;    // 1024

    // --- prep 1: Wvo = Wv @ Wo (raw in g_u), pack into slot 1 ---
    split_pack_w<<<WPACK_GRID, 256>>>(Wo, (float2*)wohip, (float2*)wolop);
    split_pack_a<<<APACK_1K, 256>>>(Wv, (float4*)ahip, (float4*)alop);
    gemm_mma_kernel<<<dim3(DIM / 128, DIM / 256), 256, GEMM_SMEM>>>(
        ahip, alop, wohip, wolop, zerop, up);
    split_pack_w<<<WPACK_GRID, 256>>>(up, (float2*)(wthip + 1 * WSZ), (float2*)(wtlop + 1 * WSZ));

    // --- prep 2: G = Wq @ Wk^T (raw in g_u), pack into slot 0 ---
    split_pack_a<<<APACK_1K, 256>>>(Wq, (float4*)ahip, (float4*)alop);
    split_pack_kb<<<WPACK_GRID, 256>>>(Wk, (float2*)khip, (float2*)klop);
    gemm_mma_kernel<<<dim3(DIM / 128, DIM / 256), 256, GEMM_SMEM>>>(
        ahip, alop, khip, klop, zerop, up);
    split_pack_w<<<WPACK_GRID, 256>>>(up, (float2*)(wthip + 0 * WSZ), (float2*)(wtlop + 0 * WSZ));

    // --- prep 3: bias folds ---
    bvo_kernel<<<DIM / 128, 128>>>(bv, Wo, bo, bvop);
    ydot_kernel<<<DIM / 8, 256>>>(Wk, bq, yp);
    wdot_kernel<<<MROWS / 8, 256>>>(S, yp, wp);

    // --- S packs: A-fmt (for T/U GEMMs) and B-fmt (scores B operand) ---
    split_pack_a<<<(MROWS / 16) * KS8 / 8, 256>>>(S, (float4*)ahip, (float4*)alop);
    split_pack_kb<<<(MROWS / 8) * KS8 / 8, 256>>>(S, (float2*)khip, (float2*)klop);

    // --- fused: T = S@G packed A-fmt, U = S@Wvo raw ---
    gemm_tu_kernel<<<dim3(16, MROWS / 256), 256, GEMM_SMEM>>>(
        ahip, alop, wthip, wtlop, qhip, qlop, up);

    scores_super_kernel<<<dim3(NSB, BSZ), 256, SSC_SMEM>>>(
        qhip, qlop, khip, klop, wp, pvp, pip);
    merge_softmax_kernel<<<(MROWS + 255) / 256, 256>>>(pvp, pip, pp, ip);
    gather_out_kernel<<<MROWS, 128>>>(up, pp, ip, bvop, out);
}

// round 12
// speedup vs baseline: 3.1237x; 1.0892x over previous
#include <cuda_runtime.h>
#include <math.h>
#include <stdint.h>

#define BSZ   4
#define NSEQ  4096
#define DIM   1024
#define TOPK  8
#define MROWS (BSZ * NSEQ)
#define KS8   (DIM / 8)   // 128 k-steps of 8
#define NSB   272         // supertile score blocks per batch
#define WSZF  ((size_t)DIM * DIM)

typedef unsigned long long ULL;

// ---------------- scratch (__device__ globals; no allocation allowed) -------
__device__ __align__(128) float g_u[(size_t)MROWS * DIM];   // prep partials, then U
__device__ float g_probs[(size_t)MROWS * TOPK];
__device__ int   g_topidx[(size_t)MROWS * TOPK];
__device__ float g_pval[(size_t)BSZ * NSB * 256 * TOPK];
__device__ int   g_pidx[(size_t)BSZ * NSB * 256 * TOPK];
__device__ float g_bvo[DIM];
__device__ float g_y[DIM];       // y = Wk @ bq
__device__ float g_w[MROWS];     // w = (S @ y) / 32
// fragment-packed 3xTF32 buffers
__device__ __align__(128) float g_ahi[(size_t)MROWS * DIM];   // A-fmt (Wv/Wq then S)
__device__ __align__(128) float g_alo[(size_t)MROWS * DIM];
__device__ __align__(128) float g_qhi[(size_t)MROWS * DIM];   // A-fmt (T)
__device__ __align__(128) float g_qlo[(size_t)MROWS * DIM];
__device__ __align__(128) float g_khi[(size_t)MROWS * DIM];   // B-fmt (Wo/Wk then S)
__device__ __align__(128) float g_klo[(size_t)MROWS * DIM];
__device__ __align__(128) float g_wthi[2][WSZF];              // B-fmt: slot0 G, slot1 Wvo
__device__ __align__(128) float g_wtlo[2][WSZF];

// ---------------- helpers -----------------------------------------------------
__device__ __forceinline__ uint32_t smem_u32(const void* p) {
    uint32_t a;
    asm("{ .reg .u64 t; cvta.to.shared.u64 t, %1; cvt.u32.u64 %0, t; }"
        : "=r"(a) : "l"(p));
    return a;
}
__device__ __forceinline__ float tf32r(float x) {
    uint32_t u;
    asm("cvt.rna.tf32.f32 %0, %1;" : "=r"(u) : "f"(x));
    return __uint_as_float(u);
}
__device__ __forceinline__ void cpasync16(uint32_t saddr, const void* g) {
    asm volatile("cp.async.cg.shared.global [%0], [%1], 16;"
                 :: "r"(saddr), "l"(g));
}
#define CP_COMMIT() asm volatile("cp.async.commit_group;" ::: "memory")
#define CP_WAIT_1() asm volatile("cp.async.wait_group 1;" ::: "memory")
#define CP_WAIT_0() asm volatile("cp.async.wait_group 0;" ::: "memory")

__device__ __forceinline__ void mma8(float4& c, const uint4& a, const uint2& b) {
    asm volatile(
        "mma.sync.aligned.m16n8k8.row.col.f32.tf32.tf32.f32 "
        "{%0,%1,%2,%3}, {%4,%5,%6,%7}, {%8,%9}, {%0,%1,%2,%3};"
        : "+f"(c.x), "+f"(c.y), "+f"(c.z), "+f"(c.w)
        : "r"(a.x), "r"(a.y), "r"(a.z), "r"(a.w), "r"(b.x), "r"(b.y));
}

// ---------------- split+pack A-format: X[M,K] row-major ---------------------
__global__ __launch_bounds__(256) void split_pack_a(
    const float* __restrict__ X, float4* __restrict__ Phi, float4* __restrict__ Plo) {
    const int atom = blockIdx.x * 8 + (threadIdx.x >> 5);
    const int lane = threadIdx.x & 31;
    const int mt = atom >> 7;
    const int ks = atom & 127;
    const int g = lane >> 2, t = lane & 3;
    const size_t r0 = (size_t)(mt * 16 + g) * DIM + ks * 8 + t;
    const size_t r1 = r0 + 8 * DIM;
    float x0 = X[r0], x1 = X[r1], x2 = X[r0 + 4], x3 = X[r1 + 4];
    float4 h, l;
    h.x = tf32r(x0); l.x = tf32r(x0 - h.x);
    h.y = tf32r(x1); l.y = tf32r(x1 - h.y);
    h.z = tf32r(x2); l.z = tf32r(x2 - h.z);
    h.w = tf32r(x3); l.w = tf32r(x3 - h.w);
    Phi[(size_t)atom * 32 + lane] = h;
    Plo[(size_t)atom * 32 + lane] = l;
}

// ---------------- split+pack W (B-format): W[K,N] -> [N/8][K/8][lane][2] ----
__global__ __launch_bounds__(256) void split_pack_w(
    const float* __restrict__ W, float2* __restrict__ Phi, float2* __restrict__ Plo) {
    const int atom = blockIdx.x * 8 + (threadIdx.x >> 5);
    const int lane = threadIdx.x & 31;
    const int nt = atom >> 7;
    const int ks = atom & 127;
    const int g = lane >> 2, t = lane & 3;
    float x0 = W[(size_t)(ks * 8 + t) * DIM + nt * 8 + g];
    float x1 = W[(size_t)(ks * 8 + t + 4) * DIM + nt * 8 + g];
    float2 h, l;
    h.x = tf32r(x0); l.x = tf32r(x0 - h.x);
    h.y = tf32r(x1); l.y = tf32r(x1 - h.y);
    Phi[(size_t)atom * 32 + lane] = h;
    Plo[(size_t)atom * 32 + lane] = l;
}

// ---------------- split+pack row-major [N,K] -> B-format ---------------------
__global__ __launch_bounds__(256) void split_pack_kb(
    const float* __restrict__ X, float2* __restrict__ Phi, float2* __restrict__ Plo) {
    const int atom = blockIdx.x * 8 + (threadIdx.x >> 5);
    const int lane = threadIdx.x & 31;
    const int nt = atom >> 7;
    const int ks = atom & 127;
    const int g = lane >> 2, t = lane & 3;
    const size_t base = (size_t)(nt * 8 + g) * DIM + ks * 8 + t;
    float x0 = X[base];
    float x1 = X[base + 4];
    float2 h, l;
    h.x = tf32r(x0); l.x = tf32r(x0 - h.x);
    h.y = tf32r(x1); l.y = tf32r(x1 - h.y);
    Phi[(size_t)atom * 32 + lane] = h;
    Plo[(size_t)atom * 32 + lane] = l;
}

// ------- fused S pack: A-format + B-format in one pass (S read once) --------
__global__ __launch_bounds__(256) void split_pack_s(
    const float* __restrict__ X,
    float4* __restrict__ Ahi, float4* __restrict__ Alo,
    float2* __restrict__ Bhi, float2* __restrict__ Blo) {
    const int atom = blockIdx.x * 8 + (threadIdx.x >> 5);   // A atom
    const int lane = threadIdx.x & 31;
    const int mt = atom >> 7;
    const int ks = atom & 127;
    const int g = lane >> 2, t = lane & 3;
    const size_t r0 = (size_t)(mt * 16 + g) * DIM + ks * 8 + t;
    const size_t r1 = r0 + 8 * DIM;
    float x0 = X[r0], x1 = X[r1], x2 = X[r0 + 4], x3 = X[r1 + 4];
    float4 h, l;
    h.x = tf32r(x0); l.x = tf32r(x0 - h.x);
    h.y = tf32r(x1); l.y = tf32r(x1 - h.y);
    h.z = tf32r(x2); l.z = tf32r(x2 - h.z);
    h.w = tf32r(x3); l.w = tf32r(x3 - h.w);
    Ahi[(size_t)atom * 32 + lane] = h;
    Alo[(size_t)atom * 32 + lane] = l;
    // B atoms: nt = 2mt (rows 16mt+g: x0@t, x2@t+4) and 2mt+1 (rows +8: x1, x3)
    const size_t b0 = ((size_t)(2 * mt) * KS8 + ks) * 32 + lane;
    const size_t b1 = b0 + (size_t)KS8 * 32;
    Bhi[b0] = make_float2(h.x, h.z);
    Blo[b0] = make_float2(l.x, l.z);
    Bhi[b1] = make_float2(h.y, h.w);
    Blo[b1] = make_float2(l.y, l.w);
}

// ---------------- bvo = bv @ Wo + bo ----------------------------------------
__global__ __launch_bounds__(128) void bvo_kernel(
    const float* __restrict__ bv, const float* __restrict__ Wo,
    const float* __restrict__ bo, float* __restrict__ bvo) {
    const int n = blockIdx.x * 128 + threadIdx.x;
    float acc = bo[n];
    for (int k = 0; k < DIM; k++) acc += bv[k] * Wo[(size_t)k * DIM + n];
    bvo[n] = acc;
}

// ---------------- y[d] = Wk[d,:] . bq  (one warp per row) --------------------
__global__ __launch_bounds__(256) void ydot_kernel(
    const float* __restrict__ Wk, const float* __restrict__ bq,
    float* __restrict__ y) {
    const int wid = threadIdx.x >> 5, lane = threadIdx.x & 31;
    const int row = blockIdx.x * 8 + wid;
    const float4* r4 = (const float4*)(Wk + (size_t)row * DIM);
    const float4* b4 = (const float4*)bq;
    float acc = 0.f;
    for (int i = lane; i < DIM / 4; i += 32) {
        float4 a = r4[i], b = b4[i];
        acc += a.x * b.x + a.y * b.y + a.z * b.z + a.w * b.w;
    }
#pragma unroll
    for (int o = 16; o; o >>= 1) acc += __shfl_xor_sync(0xffffffffu, acc, o);
    if (lane == 0) y[row] = acc;
}

// ---------------- w[m] = (S[m,:] . y) / 32  (one warp per row) ---------------
__global__ __launch_bounds__(256) void wdot_kernel(
    const float* __restrict__ S, const float* __restrict__ y,
    float* __restrict__ w) {
    const int wid = threadIdx.x >> 5, lane = threadIdx.x & 31;
    const int row = blockIdx.x * 8 + wid;
    const float4* r4 = (const float4*)(S + (size_t)row * DIM);
    const float4* y4 = (const float4*)y;
    float acc = 0.f;
    for (int i = lane; i < DIM / 4; i += 32) {
        float4 a = r4[i], b = y4[i];
        acc += a.x * b.x + a.y * b.y + a.z * b.z + a.w * b.w;
    }
#pragma unroll
    for (int o = 16; o; o >>= 1) acc += __shfl_xor_sync(0xffffffffu, acc, o);
    if (lane == 0) w[row] = acc * 0.03125f;
}

// ---------------- shared 3xTF32 mainloop (256x128 tile, BK=16, 3 stages) ----
// kc0/iters select a K window (in BK=16 units).
#define GEMM_SMEM (3 * 12288 * 4)

__device__ __forceinline__ void mma_mainloop(
    float* sm, const float* __restrict__ Ahi, const float* __restrict__ Alo,
    const float* __restrict__ Bhi, const float* __restrict__ Blo,
    int br16, int bn16, int kc0, int iters, float4 (&acc)[4][8]) {
    const int tid = threadIdx.x;
    const int lane = tid & 31, wid = tid >> 5;
    const int wy = wid >> 1, wx = wid & 1;
    const uint32_t smb = smem_u32(sm);

    auto load_stage = [&](int kc, int s) {
        const uint32_t sb = smb + s * 49152;
#pragma unroll
        for (int j = 0; j < 4; j++) {
            const int cA = tid + j * 256;
            const int mtl = cA >> 6, off = cA & 63;
            const uint32_t so = sb + (uint32_t)(mtl * 256 + off * 4) * 4;
            const size_t go = ((size_t)(br16 + mtl) * KS8 + kc * 2) * 128 + off * 4;
            cpasync16(so, Ahi + go);
            cpasync16(so + 4096 * 4, Alo + go);
        }
#pragma unroll
        for (int j = 0; j < 2; j++) {
            const int cB = tid + j * 256;
            const int ntl = cB >> 5, off = cB & 31;
            const uint32_t so = sb + (uint32_t)(8192 + ntl * 128 + off * 4) * 4;
            const size_t go = ((size_t)(bn16 + ntl) * KS8 + kc * 2) * 64 + off * 4;
            cpasync16(so, Bhi + go);
            cpasync16(so + 2048 * 4, Blo + go);
        }
    };

    load_stage(kc0, 0); CP_COMMIT();
    load_stage(kc0 + 1, 1); CP_COMMIT();

#pragma unroll
    for (int i = 0; i < 4; i++)
#pragma unroll
        for (int j = 0; j < 8; j++) acc[i][j] = make_float4(0.f, 0.f, 0.f, 0.f);

    for (int c = 0; c < iters; c++) {
        if (c < iters - 2) { CP_WAIT_1(); } else { CP_WAIT_0(); }
        __syncthreads();
        if (c + 2 < iters) { load_stage(kc0 + c + 2, (c + 2) % 3); CP_COMMIT(); }
        const float* st = sm + (c % 3) * 12288;
#pragma unroll
        for (int ks = 0; ks < 2; ks++) {
            uint4 Ah[4], Al[4];
            uint2 Bh[8], Bl[8];
#pragma unroll
            for (int i = 0; i < 4; i++) {
                const float* p = st + ((wy * 4 + i) * 2 + ks) * 128 + lane * 4;
                Ah[i] = *(const uint4*)p;
                Al[i] = *(const uint4*)(p + 4096);
            }
#pragma unroll
            for (int j = 0; j < 8; j++) {
                const float* p = st + 8192 + ((wx * 8 + j) * 2 + ks) * 64 + lane * 2;
                Bh[j] = *(const uint2*)p;
                Bl[j] = *(const uint2*)(p + 2048);
            }
#pragma unroll
            for (int i = 0; i < 4; i++)
#pragma unroll
                for (int j = 0; j < 8; j++) {
                    mma8(acc[i][j], Ah[i], Bh[j]);
                    mma8(acc[i][j], Ah[i], Bl[j]);
                    mma8(acc[i][j], Al[i], Bh[j]);
                }
        }
    }
}

// --------- fused prep GEMMs: Wvo = Wv@Wo and G = Wq@Wk^T, split-K x2 --------
// grid (8, 4, 4): z = wsel*2 + khalf. Partials -> g_u regions:
//   region r = wsel*2 + khalf, rows [r*1024, r*1024+1024)
// A-fmt buffer: Wv at mt 0..63, Wq at mt 64..127.
// B-fmt buffer: Wo at nt 0..127, Wk at nt 128..255.
__global__ __launch_bounds__(256, 1) void gemm_prep_kernel(
    const float* __restrict__ Ahi, const float* __restrict__ Alo,
    const float* __restrict__ Bhi, const float* __restrict__ Blo,
    float* __restrict__ P) {
    extern __shared__ float sm[];
    const int wsel = blockIdx.z >> 1;
    const int khalf = blockIdx.z & 1;
    const int tid = threadIdx.x;
    const int lane = tid & 31, wid = tid >> 5;
    const int wy = wid >> 1, wx = wid & 1;
    const int g = lane >> 2, t = lane & 3;
    const int m0 = blockIdx.y * 256, n0 = blockIdx.x * 128;

    float4 acc[4][8];
    mma_mainloop(sm, Ahi, Alo, Bhi, Blo,
                 wsel * 64 + blockIdx.y * 16, wsel * 128 + blockIdx.x * 16,
                 khalf * 32, 32, acc);

    float* out = P + (size_t)(wsel * 2 + khalf) * DIM * DIM;
#pragma unroll
    for (int i = 0; i < 4; i++) {
        const int r0 = m0 + wy * 64 + i * 16 + g;
#pragma unroll
        for (int j = 0; j < 8; j++) {
            const int col = n0 + wx * 64 + j * 8 + t * 2;
            *(float2*)(out + (size_t)r0 * DIM + col) =
                make_float2(acc[i][j].x, acc[i][j].y);
            *(float2*)(out + (size_t)(r0 + 8) * DIM + col) =
                make_float2(acc[i][j].z, acc[i][j].w);
        }
    }
}

// --------- sum split-K partials + pack B-format into weight slots ------------
// grid 4096: blocks [0,2048) -> slot 0 = G (regions 2,3); [2048,4096) -> slot 1 = Wvo (0,1)
__global__ __launch_bounds__(256) void prep_pack_sum(
    const float* __restrict__ P, float2* __restrict__ WHi, float2* __restrict__ WLo) {
    const int bx = blockIdx.x;
    const int w = bx >> 11;                 // 0 -> G, 1 -> Wvo
    const float* p0 = P + (size_t)(w == 0 ? 2 : 0) * DIM * DIM;
    const float* p1 = p0 + (size_t)DIM * DIM;
    float2* dhi = WHi + (size_t)w * WSZF / 2;   // float2 units: WSZF floats / 2
    float2* dlo = WLo + (size_t)w * WSZF / 2;
    const int atom = (bx & 2047) * 8 + (threadIdx.x >> 5);
    const int lane = threadIdx.x & 31;
    const int nt = atom >> 7;
    const int ks = atom & 127;
    const int g = lane >> 2, t = lane & 3;
    const size_t i0 = (size_t)(ks * 8 + t) * DIM + nt * 8 + g;
    const size_t i1 = (size_t)(ks * 8 + t + 4) * DIM + nt * 8 + g;
    float x0 = p0[i0] + p1[i0];
    float x1 = p0[i1] + p1[i1];
    float2 h, l;
    h.x = tf32r(x0); l.x = tf32r(x0 - h.x);
    h.y = tf32r(x1); l.y = tf32r(x1 - h.y);
    dhi[(size_t)atom * 32 + lane] = h;
    dlo[(size_t)atom * 32 + lane] = l;
}

// Fused T/U projection. wsel 0 -> T = S@G packed A-fmt, 1 -> U = S@Wvo raw.
__global__ __launch_bounds__(256, 1) void gemm_tu_kernel(
    const float* __restrict__ Ahi, const float* __restrict__ Alo,
    const float* __restrict__ Whi, const float* __restrict__ Wlo,
    float* __restrict__ Thi, float* __restrict__ Tlo,
    float* __restrict__ U) {
    extern __shared__ float sm[];
    const int wsel = blockIdx.x & 1;
    const int nxt = blockIdx.x >> 1;   // 0..7
    const int tid = threadIdx.x;
    const int lane = tid & 31, wid = tid >> 5;
    const int wy = wid >> 1, wx = wid & 1;
    const int g = lane >> 2, t = lane & 3;
    const int m0 = blockIdx.y * 256, n0 = nxt * 128;

    float4 acc[4][8];
    mma_mainloop(sm, Ahi, Alo,
                 Whi + (size_t)wsel * DIM * DIM, Wlo + (size_t)wsel * DIM * DIM,
                 blockIdx.y * 16, nxt * 16, 0, 64, acc);

    if (wsel == 1) {
#pragma unroll
        for (int i = 0; i < 4; i++) {
            const int r0 = m0 + wy * 64 + i * 16 + g;
#pragma unroll
            for (int j = 0; j < 8; j++) {
                const int col = n0 + wx * 64 + j * 8 + t * 2;
                *(float2*)(U + (size_t)r0 * DIM + col) =
                    make_float2(acc[i][j].x, acc[i][j].y);
                *(float2*)(U + (size_t)(r0 + 8) * DIM + col) =
                    make_float2(acc[i][j].z, acc[i][j].w);
            }
        }
        return;
    }

    __syncthreads();  // pipeline smem free
#pragma unroll
    for (int i = 0; i < 4; i++) {
        const int r0 = wy * 64 + i * 16 + g;
#pragma unroll
        for (int j = 0; j < 8; j++) {
            const int col = wx * 64 + j * 8 + t * 2;
            *(float2*)&sm[r0 * 132 + col] = make_float2(acc[i][j].x, acc[i][j].y);
            *(float2*)&sm[(r0 + 8) * 132 + col] = make_float2(acc[i][j].z, acc[i][j].w);
        }
    }
    __syncthreads();

    for (int a = wid; a < 256; a += 8) {
        const int amt = a >> 4, aks = a & 15;
        const float* bp = sm + (amt * 16 + g) * 132 + aks * 8 + t;
        float x0 = bp[0], x1 = bp[8 * 132], x2 = bp[4], x3 = bp[8 * 132 + 4];
        float4 h, l;
        h.x = tf32r(x0); l.x = tf32r(x0 - h.x);
        h.y = tf32r(x1); l.y = tf32r(x1 - h.y);
        h.z = tf32r(x2); l.z = tf32r(x2 - h.z);
        h.w = tf32r(x3); l.w = tf32r(x3 - h.w);
        const size_t atom = (size_t)(blockIdx.y * 16 + amt) * KS8 + (nxt * 16 + aks);
        ((float4*)Thi)[atom * 32 + lane] = h;
        ((float4*)Tlo)[atom * 32 + lane] = l;
    }
}

// ---------------- supertile 3xTF32 causal scores + top-8 --------------------
#define SSC_SMEM ((3 * 12288 + 128 * 72 + 256 * 8 + 256 * 8 + 128) * 4)

__global__ __launch_bounds__(256, 1) void scores_super_kernel(
    const float* __restrict__ Thi, const float* __restrict__ Tlo,
    const float* __restrict__ Shi, const float* __restrict__ Slo,
    const float* __restrict__ w,
    float* __restrict__ pval, int* __restrict__ pidx) {
    extern __shared__ float sm[];
    float* sc = sm + 36864;           // [128][72]
    float* tval = sm + 46080;         // [256][8]
    int* tidx = (int*)(sm + 48128);   // [256][8]
    float* wsc = sm + 50176;          // [128]

    const int tid = threadIdx.x;
    const int lane = tid & 31, wid = tid >> 5;
    const int wy = wid >> 1, wx = wid & 1;
    const int g = lane >> 2, t = lane & 3;
    const int b = blockIdx.y;
    const int bidx = blockIdx.x;

    int sq = (int)((sqrtf(4.0f * (float)bidx + 1.0f) - 1.0f) * 0.5f);
    while ((sq + 1) * (sq + 2) <= bidx) sq++;
    while (sq * (sq + 1) > bidx) sq--;
    const int kt = bidx - sq * (sq + 1);
    const int q0 = sq * 256, k0 = kt * 128;

    for (int i = tid; i < 256 * TOPK; i += 256) {
        tval[i] = -INFINITY;
        tidx[i] = 0;
    }
    if (tid < 128) wsc[tid] = w[b * NSEQ + k0 + tid];

    float4 acc[4][8];
    mma_mainloop(sm, Thi, Tlo, Shi, Slo,
                 b * 256 + sq * 16, b * 512 + kt * 16, 0, 64, acc);

#pragma unroll
    for (int rh = 0; rh < 2; rh++) {
#pragma unroll
        for (int h = 0; h < 2; h++) {
            if ((wy >> 1) == rh && wx == h) {
#pragma unroll
                for (int i = 0; i < 4; i++) {
                    const int rl = wy * 64 + i * 16 + g;
                    const int srow = rl - rh * 128;
#pragma unroll
                    for (int j = 0; j < 8; j++) {
                        const int col = j * 8 + t * 2;
                        const int lc = h * 64 + col;
                        const int gc = k0 + lc;
                        const int gr0 = q0 + rl, gr1 = gr0 + 8;
                        const float w0 = wsc[lc], w1 = wsc[lc + 1];
                        float v0 = acc[i][j].x * 0.03125f + w0;
                        float v1 = acc[i][j].y * 0.03125f + w1;
                        float v2 = acc[i][j].z * 0.03125f + w0;
                        float v3 = acc[i][j].w * 0.03125f + w1;
                        if (gc + 0 > gr0) v0 = -INFINITY;
                        if (gc + 1 > gr0) v1 = -INFINITY;
                        if (gc + 0 > gr1) v2 = -INFINITY;
                        if (gc + 1 > gr1) v3 = -INFINITY;
                        *(float2*)&sc[srow * 72 + col] = make_float2(v0, v1);
                        *(float2*)&sc[(srow + 8) * 72 + col] = make_float2(v2, v3);
                    }
                }
            }
            __syncthreads();
            if (tid < 128) {
                const int row = rh * 128 + tid;
                float tv[TOPK]; int ti[TOPK];
#pragma unroll
                for (int j = 0; j < TOPK; j++) { tv[j] = tval[row * 8 + j]; ti[j] = tidx[row * 8 + j]; }
                float vmin = tv[0]; int mpos = 0;
#pragma unroll
                for (int j = 1; j < TOPK; j++) if (tv[j] < vmin) { vmin = tv[j]; mpos = j; }
                const int cbase = k0 + h * 64;
                for (int cc = 0; cc < 64; cc++) {
                    const float vv = sc[tid * 72 + cc];
                    if (vv > vmin) {
                        tv[mpos] = vv; ti[mpos] = cbase + cc;
                        vmin = tv[0]; mpos = 0;
#pragma unroll
                        for (int j = 1; j < TOPK; j++) if (tv[j] < vmin) { vmin = tv[j]; mpos = j; }
                    }
                }
#pragma unroll
                for (int j = 0; j < TOPK; j++) { tval[row * 8 + j] = tv[j]; tidx[row * 8 + j] = ti[j]; }
            }
            __syncthreads();
        }
    }

    const size_t base = (((size_t)b * NSB + bidx) * 256 + tid) * TOPK;
#pragma unroll
    for (int j = 0; j < TOPK; j++) {
        pval[base + j] = tval[tid * 8 + j];
        pidx[base + j] = tidx[tid * 8 + j];
    }
}

// ---------------- merge per-row partial top-8 lists + softmax ----------------
__global__ __launch_bounds__(256) void merge_softmax_kernel(
    const float* __restrict__ pv, const int* __restrict__ pi,
    float* __restrict__ probs, int* __restrict__ idxs) {
    const int row = blockIdx.x * 256 + threadIdx.x;
    if (row >= MROWS) return;
    const int b = row >> 12, rr = row & 4095;
    const int qt = rr >> 7;
    const int sq = qt >> 1;
    const int rib = rr - sq * 256;
    const size_t sbase = ((size_t)b * NSB + (size_t)sq * (sq + 1)) * 256 + rib;

    float tv[TOPK]; int ti[TOPK];
#pragma unroll
    for (int j = 0; j < TOPK; j++) { tv[j] = -INFINITY; ti[j] = 0; }
    float vmin = -INFINITY; int mpos = 0;

    for (int kt = 0; kt <= qt; kt++) {
        const size_t base = (sbase + (size_t)kt * 256) * TOPK;
#pragma unroll
        for (int j = 0; j < TOPK; j++) {
            const float vv = pv[base + j];
            if (vv > vmin) {
                tv[mpos] = vv; ti[mpos] = pi[base + j];
                vmin = tv[0]; mpos = 0;
#pragma unroll
                for (int q = 1; q < TOPK; q++) if (tv[q] < vmin) { vmin = tv[q]; mpos = q; }
            }
        }
    }

    float mx = tv[0];
#pragma unroll
    for (int j = 1; j < TOPK; j++) mx = fmaxf(mx, tv[j]);
    float e[TOPK]; float ssum = 0.f;
#pragma unroll
    for (int j = 0; j < TOPK; j++) { e[j] = expf(tv[j] - mx); ssum += e[j]; }
    const float inv = 1.f / ssum;
    const size_t obase = (size_t)row * TOPK;
#pragma unroll
    for (int j = 0; j < TOPK; j++) { probs[obase + j] = e[j] * inv; idxs[obase + j] = ti[j]; }
}

// ---------------- sparse gather of U + bvo -> out -----------------------------
__global__ __launch_bounds__(128) void gather_out_kernel(
    const float* __restrict__ U, const float* __restrict__ probs,
    const int* __restrict__ idxs, const float* __restrict__ bvo,
    float* __restrict__ out) {
    const int row = blockIdx.x;
    const int b = row >> 12;
    const int tid = threadIdx.x;
    __shared__ float p[TOPK];
    __shared__ int   id[TOPK];
    if (tid < TOPK) {
        p[tid]  = probs[(size_t)row * TOPK + tid];
        id[tid] = idxs[(size_t)row * TOPK + tid];
    }
    __syncthreads();
    const float* ub = U + (size_t)b * NSEQ * DIM;
    const int c = tid * 8;
    float4 a0 = *(const float4*)(bvo + c);
    float4 a1 = *(const float4*)(bvo + c + 4);
#pragma unroll
    for (int j = 0; j < TOPK; j++) {
        const float4* vr = (const float4*)(ub + (size_t)id[j] * DIM + c);
        const float pj = p[j];
        float4 v0 = vr[0], v1 = vr[1];
        a0.x += pj * v0.x; a0.y += pj * v0.y; a0.z += pj * v0.z; a0.w += pj * v0.w;
        a1.x += pj * v1.x; a1.y += pj * v1.y; a1.z += pj * v1.z; a1.w += pj * v1.w;
    }
    float4* orow = (float4*)(out + (size_t)row * DIM + c);
    orow[0] = a0; orow[1] = a1;
}

// ---------------- launch -----------------------------------------------------
extern "C" void kernel_launch(void* const* d_in, const int* in_sizes, int n_in,
                              void* d_out, int out_size) {
    const float* S  = (const float*)d_in[0];
    const float* Wq = (const float*)d_in[1];
    const float* bq = (const float*)d_in[2];
    const float* Wk = (const float*)d_in[3];
    const float* bk = (const float*)d_in[4];  // row-const in softmax; drops out
    const float* Wv = (const float*)d_in[5];
    const float* bv = (const float*)d_in[6];
    const float* Wo = (const float*)d_in[7];
    const float* bo = (const float*)d_in[8];
    float* out = (float*)d_out;
    (void)bk;

    float *up, *pp, *pvp, *ahip, *alop;
    float *qhip, *qlop, *khip, *klop, *wthip, *wtlop;
    float *bvop, *yp, *wp;
    int *ip, *pip;
    cudaGetSymbolAddress((void**)&up, g_u);
    cudaGetSymbolAddress((void**)&pp, g_probs);
    cudaGetSymbolAddress((void**)&ip, g_topidx);
    cudaGetSymbolAddress((void**)&pvp, g_pval);
    cudaGetSymbolAddress((void**)&pip, g_pidx);
    cudaGetSymbolAddress((void**)&ahip, g_ahi);
    cudaGetSymbolAddress((void**)&alop, g_alo);
    cudaGetSymbolAddress((void**)&qhip, g_qhi);
    cudaGetSymbolAddress((void**)&qlop, g_qlo);
    cudaGetSymbolAddress((void**)&khip, g_khi);
    cudaGetSymbolAddress((void**)&klop, g_klo);
    cudaGetSymbolAddress((void**)&wthip, g_wthi);
    cudaGetSymbolAddress((void**)&wtlop, g_wtlo);
    cudaGetSymbolAddress((void**)&bvop, g_bvo);
    cudaGetSymbolAddress((void**)&yp, g_y);
    cudaGetSymbolAddress((void**)&wp, g_w);

    cudaFuncSetAttribute(gemm_prep_kernel,
                         cudaFuncAttributeMaxDynamicSharedMemorySize, GEMM_SMEM);
    cudaFuncSetAttribute(gemm_tu_kernel,
                         cudaFuncAttributeMaxDynamicSharedMemorySize, GEMM_SMEM);
    cudaFuncSetAttribute(scores_super_kernel,
                         cudaFuncAttributeMaxDynamicSharedMemorySize, SSC_SMEM);

    const int WPACK_GRID = (DIM / 8) * KS8 / 8;   // 2048
    const int APACK_1K = (DIM / 16) * KS8 / 8;    // 1024

    // --- operand packs for prep: A buffer = [Wv | Wq], B buffer = [Wo | Wk] ---
    split_pack_a<<<APACK_1K, 256>>>(Wv, (float4*)ahip, (float4*)alop);
    split_pack_a<<<APACK_1K, 256>>>(Wq,
        (float4*)ahip + (size_t)8192 * 32, (float4*)alop + (size_t)8192 * 32);
    split_pack_w<<<WPACK_GRID, 256>>>(Wo, (float2*)khip, (float2*)klop);
    split_pack_kb<<<WPACK_GRID, 256>>>(Wk,
        (float2*)khip + (size_t)16384 * 32, (float2*)klop + (size_t)16384 * 32);

    // --- bias folds (independent) ---
    bvo_kernel<<<DIM / 128, 128>>>(bv, Wo, bo, bvop);
    ydot_kernel<<<DIM / 8, 256>>>(Wk, bq, yp);
    wdot_kernel<<<MROWS / 8, 256>>>(S, yp, wp);

    // --- fused prep GEMMs (split-K x2) + partial-sum pack ---
    gemm_prep_kernel<<<dim3(8, 4, 4), 256, GEMM_SMEM>>>(ahip, alop, khip, klop, up);
    prep_pack_sum<<<4096, 256>>>(up, (float2*)wthip, (float2*)wtlop);

    // --- fused S pack: A-fmt + B-fmt in one pass ---
    split_pack_s<<<(MROWS / 16) * KS8 / 8, 256>>>(
        S, (float4*)ahip, (float4*)alop, (float2*)khip, (float2*)klop);

    // --- fused: T = S@G packed A-fmt, U = S@Wvo raw ---
    gemm_tu_kernel<<<dim3(16, MROWS / 256), 256, GEMM_SMEM>>>(
        ahip, alop, wthip, wtlop, qhip, qlop, up);

    scores_super_kernel<<<dim3(NSB, BSZ), 256, SSC_SMEM>>>(
        qhip, qlop, khip, klop, wp, pvp, pip);
    merge_softmax_kernel<<<(MROWS + 255) / 256, 256>>>(pvp, pip, pp, ip);
    gather_out_kernel<<<MROWS, 128>>>(up, pp, ip, bvop, out);
}

// round 13
// speedup vs baseline: 3.3095x; 1.0595x over previous
#include <cuda_runtime.h>
#include <math.h>
#include <stdint.h>

#define BSZ   4
#define NSEQ  4096
#define DIM   1024
#define TOPK  8
#define MROWS (BSZ * NSEQ)
#define KS8   (DIM / 8)   // 128 k-steps of 8
#define NSB   272         // supertile score blocks per batch
#define WSZF  ((size_t)DIM * DIM)

typedef unsigned long long ULL;

// ---------------- scratch (__device__ globals; no allocation allowed) -------
__device__ __align__(128) float g_u[(size_t)MROWS * DIM];   // prep partials, then U
__device__ float g_pval[(size_t)BSZ * NSB * 256 * TOPK];
__device__ int   g_pidx[(size_t)BSZ * NSB * 256 * TOPK];
__device__ float g_bvo[DIM];
__device__ float g_y[DIM];       // y = Wk @ bq
__device__ float g_w[MROWS];     // w = (S @ y) / 32
// fragment-packed 3xTF32 buffers
__device__ __align__(128) float g_ahi[(size_t)MROWS * DIM];   // A-fmt (Wv/Wq then S)
__device__ __align__(128) float g_alo[(size_t)MROWS * DIM];
__device__ __align__(128) float g_qhi[(size_t)MROWS * DIM];   // A-fmt (T)
__device__ __align__(128) float g_qlo[(size_t)MROWS * DIM];
__device__ __align__(128) float g_khi[(size_t)MROWS * DIM];   // B-fmt (Wo/Wk then S)
__device__ __align__(128) float g_klo[(size_t)MROWS * DIM];
__device__ __align__(128) float g_wthi[2][WSZF];              // B-fmt: slot0 G, slot1 Wvo
__device__ __align__(128) float g_wtlo[2][WSZF];

// ---------------- helpers -----------------------------------------------------
__device__ __forceinline__ uint32_t smem_u32(const void* p) {
    uint32_t a;
    asm("{ .reg .u64 t; cvta.to.shared.u64 t, %1; cvt.u32.u64 %0, t; }"
        : "=r"(a) : "l"(p));
    return a;
}
__device__ __forceinline__ float tf32r(float x) {
    uint32_t u;
    asm("cvt.rna.tf32.f32 %0, %1;" : "=r"(u) : "f"(x));
    return __uint_as_float(u);
}
__device__ __forceinline__ void cpasync16(uint32_t saddr, const void* g) {
    asm volatile("cp.async.cg.shared.global [%0], [%1], 16;"
                 :: "r"(saddr), "l"(g));
}
#define CP_COMMIT() asm volatile("cp.async.commit_group;" ::: "memory")
#define CP_WAIT_1() asm volatile("cp.async.wait_group 1;" ::: "memory")
#define CP_WAIT_0() asm volatile("cp.async.wait_group 0;" ::: "memory")

__device__ __forceinline__ void mma8(float4& c, const uint4& a, const uint2& b) {
    asm volatile(
        "mma.sync.aligned.m16n8k8.row.col.f32.tf32.tf32.f32 "
        "{%0,%1,%2,%3}, {%4,%5,%6,%7}, {%8,%9}, {%0,%1,%2,%3};"
        : "+f"(c.x), "+f"(c.y), "+f"(c.z), "+f"(c.w)
        : "r"(a.x), "r"(a.y), "r"(a.z), "r"(a.w), "r"(b.x), "r"(b.y));
}

// ---------------- split+pack A-format: X[M,K] row-major ---------------------
__global__ __launch_bounds__(256) void split_pack_a(
    const float* __restrict__ X, float4* __restrict__ Phi, float4* __restrict__ Plo) {
    const int atom = blockIdx.x * 8 + (threadIdx.x >> 5);
    const int lane = threadIdx.x & 31;
    const int mt = atom >> 7;
    const int ks = atom & 127;
    const int g = lane >> 2, t = lane & 3;
    const size_t r0 = (size_t)(mt * 16 + g) * DIM + ks * 8 + t;
    const size_t r1 = r0 + 8 * DIM;
    float x0 = X[r0], x1 = X[r1], x2 = X[r0 + 4], x3 = X[r1 + 4];
    float4 h, l;
    h.x = tf32r(x0); l.x = tf32r(x0 - h.x);
    h.y = tf32r(x1); l.y = tf32r(x1 - h.y);
    h.z = tf32r(x2); l.z = tf32r(x2 - h.z);
    h.w = tf32r(x3); l.w = tf32r(x3 - h.w);
    Phi[(size_t)atom * 32 + lane] = h;
    Plo[(size_t)atom * 32 + lane] = l;
}

// ---------------- split+pack W (B-format): W[K,N] -> [N/8][K/8][lane][2] ----
__global__ __launch_bounds__(256) void split_pack_w(
    const float* __restrict__ W, float2* __restrict__ Phi, float2* __restrict__ Plo) {
    const int atom = blockIdx.x * 8 + (threadIdx.x >> 5);
    const int lane = threadIdx.x & 31;
    const int nt = atom >> 7;
    const int ks = atom & 127;
    const int g = lane >> 2, t = lane & 3;
    float x0 = W[(size_t)(ks * 8 + t) * DIM + nt * 8 + g];
    float x1 = W[(size_t)(ks * 8 + t + 4) * DIM + nt * 8 + g];
    float2 h, l;
    h.x = tf32r(x0); l.x = tf32r(x0 - h.x);
    h.y = tf32r(x1); l.y = tf32r(x1 - h.y);
    Phi[(size_t)atom * 32 + lane] = h;
    Plo[(size_t)atom * 32 + lane] = l;
}

// ---------------- split+pack row-major [N,K] -> B-format ---------------------
__global__ __launch_bounds__(256) void split_pack_kb(
    const float* __restrict__ X, float2* __restrict__ Phi, float2* __restrict__ Plo) {
    const int atom = blockIdx.x * 8 + (threadIdx.x >> 5);
    const int lane = threadIdx.x & 31;
    const int nt = atom >> 7;
    const int ks = atom & 127;
    const int g = lane >> 2, t = lane & 3;
    const size_t base = (size_t)(nt * 8 + g) * DIM + ks * 8 + t;
    float x0 = X[base];
    float x1 = X[base + 4];
    float2 h, l;
    h.x = tf32r(x0); l.x = tf32r(x0 - h.x);
    h.y = tf32r(x1); l.y = tf32r(x1 - h.y);
    Phi[(size_t)atom * 32 + lane] = h;
    Plo[(size_t)atom * 32 + lane] = l;
}

// ------- fused S pack: A-format + B-format in one pass (S read once) --------
__global__ __launch_bounds__(256) void split_pack_s(
    const float* __restrict__ X,
    float4* __restrict__ Ahi, float4* __restrict__ Alo,
    float2* __restrict__ Bhi, float2* __restrict__ Blo) {
    const int atom = blockIdx.x * 8 + (threadIdx.x >> 5);   // A atom
    const int lane = threadIdx.x & 31;
    const int mt = atom >> 7;
    const int ks = atom & 127;
    const int g = lane >> 2, t = lane & 3;
    const size_t r0 = (size_t)(mt * 16 + g) * DIM + ks * 8 + t;
    const size_t r1 = r0 + 8 * DIM;
    float x0 = X[r0], x1 = X[r1], x2 = X[r0 + 4], x3 = X[r1 + 4];
    float4 h, l;
    h.x = tf32r(x0); l.x = tf32r(x0 - h.x);
    h.y = tf32r(x1); l.y = tf32r(x1 - h.y);
    h.z = tf32r(x2); l.z = tf32r(x2 - h.z);
    h.w = tf32r(x3); l.w = tf32r(x3 - h.w);
    Ahi[(size_t)atom * 32 + lane] = h;
    Alo[(size_t)atom * 32 + lane] = l;
    const size_t b0 = ((size_t)(2 * mt) * KS8 + ks) * 32 + lane;
    const size_t b1 = b0 + (size_t)KS8 * 32;
    Bhi[b0] = make_float2(h.x, h.z);
    Blo[b0] = make_float2(l.x, l.z);
    Bhi[b1] = make_float2(h.y, h.w);
    Blo[b1] = make_float2(l.y, l.w);
}

// ---------------- bvo = bv @ Wo + bo ----------------------------------------
__global__ __launch_bounds__(128) void bvo_kernel(
    const float* __restrict__ bv, const float* __restrict__ Wo,
    const float* __restrict__ bo, float* __restrict__ bvo) {
    const int n = blockIdx.x * 128 + threadIdx.x;
    float acc = bo[n];
    for (int k = 0; k < DIM; k++) acc += bv[k] * Wo[(size_t)k * DIM + n];
    bvo[n] = acc;
}

// ---------------- y[d] = Wk[d,:] . bq  (one warp per row) --------------------
__global__ __launch_bounds__(256) void ydot_kernel(
    const float* __restrict__ Wk, const float* __restrict__ bq,
    float* __restrict__ y) {
    const int wid = threadIdx.x >> 5, lane = threadIdx.x & 31;
    const int row = blockIdx.x * 8 + wid;
    const float4* r4 = (const float4*)(Wk + (size_t)row * DIM);
    const float4* b4 = (const float4*)bq;
    float acc = 0.f;
    for (int i = lane; i < DIM / 4; i += 32) {
        float4 a = r4[i], b = b4[i];
        acc += a.x * b.x + a.y * b.y + a.z * b.z + a.w * b.w;
    }
#pragma unroll
    for (int o = 16; o; o >>= 1) acc += __shfl_xor_sync(0xffffffffu, acc, o);
    if (lane == 0) y[row] = acc;
}

// ---------------- w[m] = (S[m,:] . y) / 32  (one warp per row) ---------------
__global__ __launch_bounds__(256) void wdot_kernel(
    const float* __restrict__ S, const float* __restrict__ y,
    float* __restrict__ w) {
    const int wid = threadIdx.x >> 5, lane = threadIdx.x & 31;
    const int row = blockIdx.x * 8 + wid;
    const float4* r4 = (const float4*)(S + (size_t)row * DIM);
    const float4* y4 = (const float4*)y;
    float acc = 0.f;
    for (int i = lane; i < DIM / 4; i += 32) {
        float4 a = r4[i], b = y4[i];
        acc += a.x * b.x + a.y * b.y + a.z * b.z + a.w * b.w;
    }
#pragma unroll
    for (int o = 16; o; o >>= 1) acc += __shfl_xor_sync(0xffffffffu, acc, o);
    if (lane == 0) w[row] = acc * 0.03125f;
}

// ---------------- shared 3x/2x TF32 mainloop (256x128 tile, BK=16) ----------
// THIRD=true: full 3x split (hi*hi + hi*lo + lo*hi).
// THIRD=false: 2x split keeping A exact vs hi(B): hi*hi + lo*hi (Blo never loaded).
#define GEMM_SMEM (3 * 12288 * 4)

template <bool THIRD>
__device__ __forceinline__ void mma_mainloop(
    float* sm, const float* __restrict__ Ahi, const float* __restrict__ Alo,
    const float* __restrict__ Bhi, const float* __restrict__ Blo,
    int br16, int bn16, int kc0, int iters, float4 (&acc)[4][8]) {
    const int tid = threadIdx.x;
    const int lane = tid & 31, wid = tid >> 5;
    const int wy = wid >> 1, wx = wid & 1;
    const uint32_t smb = smem_u32(sm);

    auto load_stage = [&](int kc, int s) {
        const uint32_t sb = smb + s * 49152;
#pragma unroll
        for (int j = 0; j < 4; j++) {
            const int cA = tid + j * 256;
            const int mtl = cA >> 6, off = cA & 63;
            const uint32_t so = sb + (uint32_t)(mtl * 256 + off * 4) * 4;
            const size_t go = ((size_t)(br16 + mtl) * KS8 + kc * 2) * 128 + off * 4;
            cpasync16(so, Ahi + go);
            cpasync16(so + 4096 * 4, Alo + go);
        }
#pragma unroll
        for (int j = 0; j < 2; j++) {
            const int cB = tid + j * 256;
            const int ntl = cB >> 5, off = cB & 31;
            const uint32_t so = sb + (uint32_t)(8192 + ntl * 128 + off * 4) * 4;
            const size_t go = ((size_t)(bn16 + ntl) * KS8 + kc * 2) * 64 + off * 4;
            cpasync16(so, Bhi + go);
            if (THIRD) cpasync16(so + 2048 * 4, Blo + go);
        }
    };

    load_stage(kc0, 0); CP_COMMIT();
    load_stage(kc0 + 1, 1); CP_COMMIT();

#pragma unroll
    for (int i = 0; i < 4; i++)
#pragma unroll
        for (int j = 0; j < 8; j++) acc[i][j] = make_float4(0.f, 0.f, 0.f, 0.f);

    for (int c = 0; c < iters; c++) {
        if (c < iters - 2) { CP_WAIT_1(); } else { CP_WAIT_0(); }
        __syncthreads();
        if (c + 2 < iters) { load_stage(kc0 + c + 2, (c + 2) % 3); CP_COMMIT(); }
        const float* st = sm + (c % 3) * 12288;
#pragma unroll
        for (int ks = 0; ks < 2; ks++) {
            uint4 Ah[4], Al[4];
            uint2 Bh[8], Bl[8];
#pragma unroll
            for (int i = 0; i < 4; i++) {
                const float* p = st + ((wy * 4 + i) * 2 + ks) * 128 + lane * 4;
                Ah[i] = *(const uint4*)p;
                Al[i] = *(const uint4*)(p + 4096);
            }
#pragma unroll
            for (int j = 0; j < 8; j++) {
                const float* p = st + 8192 + ((wx * 8 + j) * 2 + ks) * 64 + lane * 2;
                Bh[j] = *(const uint2*)p;
                if (THIRD) Bl[j] = *(const uint2*)(p + 2048);
            }
#pragma unroll
            for (int i = 0; i < 4; i++)
#pragma unroll
                for (int j = 0; j < 8; j++) {
                    mma8(acc[i][j], Ah[i], Bh[j]);
                    if (THIRD) mma8(acc[i][j], Ah[i], Bl[j]);
                    mma8(acc[i][j], Al[i], Bh[j]);
                }
        }
    }
}

// --------- fused prep GEMMs: Wvo = Wv@Wo and G = Wq@Wk^T, split-K x2 --------
__global__ __launch_bounds__(256, 1) void gemm_prep_kernel(
    const float* __restrict__ Ahi, const float* __restrict__ Alo,
    const float* __restrict__ Bhi, const float* __restrict__ Blo,
    float* __restrict__ P) {
    extern __shared__ float sm[];
    const int wsel = blockIdx.z >> 1;
    const int khalf = blockIdx.z & 1;
    const int tid = threadIdx.x;
    const int lane = tid & 31, wid = tid >> 5;
    const int wy = wid >> 1, wx = wid & 1;
    const int g = lane >> 2, t = lane & 3;
    const int m0 = blockIdx.y * 256, n0 = blockIdx.x * 128;

    float4 acc[4][8];
    mma_mainloop<true>(sm, Ahi, Alo, Bhi, Blo,
                       wsel * 64 + blockIdx.y * 16, wsel * 128 + blockIdx.x * 16,
                       khalf * 32, 32, acc);

    float* out = P + (size_t)(wsel * 2 + khalf) * DIM * DIM;
#pragma unroll
    for (int i = 0; i < 4; i++) {
        const int r0 = m0 + wy * 64 + i * 16 + g;
#pragma unroll
        for (int j = 0; j < 8; j++) {
            const int col = n0 + wx * 64 + j * 8 + t * 2;
            *(float2*)(out + (size_t)r0 * DIM + col) =
                make_float2(acc[i][j].x, acc[i][j].y);
            *(float2*)(out + (size_t)(r0 + 8) * DIM + col) =
                make_float2(acc[i][j].z, acc[i][j].w);
        }
    }
}

// --------- sum split-K partials + pack B-format into weight slots ------------
__global__ __launch_bounds__(256) void prep_pack_sum(
    const float* __restrict__ P, float2* __restrict__ WHi, float2* __restrict__ WLo) {
    const int bx = blockIdx.x;
    const int w = bx >> 11;                 // 0 -> G, 1 -> Wvo
    const float* p0 = P + (size_t)(w == 0 ? 2 : 0) * DIM * DIM;
    const float* p1 = p0 + (size_t)DIM * DIM;
    float2* dhi = WHi + (size_t)w * WSZF / 2;
    float2* dlo = WLo + (size_t)w * WSZF / 2;
    const int atom = (bx & 2047) * 8 + (threadIdx.x >> 5);
    const int lane = threadIdx.x & 31;
    const int nt = atom >> 7;
    const int ks = atom & 127;
    const int g = lane >> 2, t = lane & 3;
    const size_t i0 = (size_t)(ks * 8 + t) * DIM + nt * 8 + g;
    const size_t i1 = (size_t)(ks * 8 + t + 4) * DIM + nt * 8 + g;
    float x0 = p0[i0] + p1[i0];
    float x1 = p0[i1] + p1[i1];
    float2 h, l;
    h.x = tf32r(x0); l.x = tf32r(x0 - h.x);
    h.y = tf32r(x1); l.y = tf32r(x1 - h.y);
    dhi[(size_t)atom * 32 + lane] = h;
    dlo[(size_t)atom * 32 + lane] = l;
}

// Fused T/U projection. wsel 0 -> T = S@G packed A-fmt (3x split),
// wsel 1 -> U = S@Wvo raw (2x split: value path, no top-k involvement).
__global__ __launch_bounds__(256, 1) void gemm_tu_kernel(
    const float* __restrict__ Ahi, const float* __restrict__ Alo,
    const float* __restrict__ Whi, const float* __restrict__ Wlo,
    float* __restrict__ Thi, float* __restrict__ Tlo,
    float* __restrict__ U) {
    extern __shared__ float sm[];
    const int wsel = blockIdx.x & 1;
    const int nxt = blockIdx.x >> 1;   // 0..7
    const int tid = threadIdx.x;
    const int lane = tid & 31, wid = tid >> 5;
    const int wy = wid >> 1, wx = wid & 1;
    const int g = lane >> 2, t = lane & 3;
    const int m0 = blockIdx.y * 256, n0 = nxt * 128;

    if (wsel == 1) {
        float4 acc[4][8];
        mma_mainloop<false>(sm, Ahi, Alo, Whi + WSZF, Wlo + WSZF,
                            blockIdx.y * 16, nxt * 16, 0, 64, acc);
#pragma unroll
        for (int i = 0; i < 4; i++) {
            const int r0 = m0 + wy * 64 + i * 16 + g;
#pragma unroll
            for (int j = 0; j < 8; j++) {
                const int col = n0 + wx * 64 + j * 8 + t * 2;
                *(float2*)(U + (size_t)r0 * DIM + col) =
                    make_float2(acc[i][j].x, acc[i][j].y);
                *(float2*)(U + (size_t)(r0 + 8) * DIM + col) =
                    make_float2(acc[i][j].z, acc[i][j].w);
            }
        }
        return;
    }

    float4 acc[4][8];
    mma_mainloop<true>(sm, Ahi, Alo, Whi, Wlo,
                       blockIdx.y * 16, nxt * 16, 0, 64, acc);

    __syncthreads();  // pipeline smem free
#pragma unroll
    for (int i = 0; i < 4; i++) {
        const int r0 = wy * 64 + i * 16 + g;
#pragma unroll
        for (int j = 0; j < 8; j++) {
            const int col = wx * 64 + j * 8 + t * 2;
            *(float2*)&sm[r0 * 132 + col] = make_float2(acc[i][j].x, acc[i][j].y);
            *(float2*)&sm[(r0 + 8) * 132 + col] = make_float2(acc[i][j].z, acc[i][j].w);
        }
    }
    __syncthreads();

    for (int a = wid; a < 256; a += 8) {
        const int amt = a >> 4, aks = a & 15;
        const float* bp = sm + (amt * 16 + g) * 132 + aks * 8 + t;
        float x0 = bp[0], x1 = bp[8 * 132], x2 = bp[4], x3 = bp[8 * 132 + 4];
        float4 h, l;
        h.x = tf32r(x0); l.x = tf32r(x0 - h.x);
        h.y = tf32r(x1); l.y = tf32r(x1 - h.y);
        h.z = tf32r(x2); l.z = tf32r(x2 - h.z);
        h.w = tf32r(x3); l.w = tf32r(x3 - h.w);
        const size_t atom = (size_t)(blockIdx.y * 16 + amt) * KS8 + (nxt * 16 + aks);
        ((float4*)Thi)[atom * 32 + lane] = h;
        ((float4*)Tlo)[atom * 32 + lane] = l;
    }
}

// ---------------- supertile 3xTF32 causal scores + top-8 --------------------
#define SSC_SMEM ((3 * 12288 + 128 * 72 + 256 * 8 + 256 * 8 + 128) * 4)

__global__ __launch_bounds__(256, 1) void scores_super_kernel(
    const float* __restrict__ Thi, const float* __restrict__ Tlo,
    const float* __restrict__ Shi, const float* __restrict__ Slo,
    const float* __restrict__ w,
    float* __restrict__ pval, int* __restrict__ pidx) {
    extern __shared__ float sm[];
    float* sc = sm + 36864;           // [128][72]
    float* tval = sm + 46080;         // [256][8]
    int* tidx = (int*)(sm + 48128);   // [256][8]
    float* wsc = sm + 50176;          // [128]

    const int tid = threadIdx.x;
    const int lane = tid & 31, wid = tid >> 5;
    const int wy = wid >> 1, wx = wid & 1;
    const int g = lane >> 2, t = lane & 3;
    const int b = blockIdx.y;
    const int bidx = blockIdx.x;

    int sq = (int)((sqrtf(4.0f * (float)bidx + 1.0f) - 1.0f) * 0.5f);
    while ((sq + 1) * (sq + 2) <= bidx) sq++;
    while (sq * (sq + 1) > bidx) sq--;
    const int kt = bidx - sq * (sq + 1);
    const int q0 = sq * 256, k0 = kt * 128;

    for (int i = tid; i < 256 * TOPK; i += 256) {
        tval[i] = -INFINITY;
        tidx[i] = 0;
    }
    if (tid < 128) wsc[tid] = w[b * NSEQ + k0 + tid];

    float4 acc[4][8];
    mma_mainloop<true>(sm, Thi, Tlo, Shi, Slo,
                       b * 256 + sq * 16, b * 512 + kt * 16, 0, 64, acc);

#pragma unroll
    for (int rh = 0; rh < 2; rh++) {
#pragma unroll
        for (int h = 0; h < 2; h++) {
            if ((wy >> 1) == rh && wx == h) {
#pragma unroll
                for (int i = 0; i < 4; i++) {
                    const int rl = wy * 64 + i * 16 + g;
                    const int srow = rl - rh * 128;
#pragma unroll
                    for (int j = 0; j < 8; j++) {
                        const int col = j * 8 + t * 2;
                        const int lc = h * 64 + col;
                        const int gc = k0 + lc;
                        const int gr0 = q0 + rl, gr1 = gr0 + 8;
                        const float w0 = wsc[lc], w1 = wsc[lc + 1];
                        float v0 = acc[i][j].x * 0.03125f + w0;
                        float v1 = acc[i][j].y * 0.03125f + w1;
                        float v2 = acc[i][j].z * 0.03125f + w0;
                        float v3 = acc[i][j].w * 0.03125f + w1;
                        if (gc + 0 > gr0) v0 = -INFINITY;
                        if (gc + 1 > gr0) v1 = -INFINITY;
                        if (gc + 0 > gr1) v2 = -INFINITY;
                        if (gc + 1 > gr1) v3 = -INFINITY;
                        *(float2*)&sc[srow * 72 + col] = make_float2(v0, v1);
                        *(float2*)&sc[(srow + 8) * 72 + col] = make_float2(v2, v3);
                    }
                }
            }
            __syncthreads();
            if (tid < 128) {
                const int row = rh * 128 + tid;
                float tv[TOPK]; int ti[TOPK];
#pragma unroll
                for (int j = 0; j < TOPK; j++) { tv[j] = tval[row * 8 + j]; ti[j] = tidx[row * 8 + j]; }
                float vmin = tv[0]; int mpos = 0;
#pragma unroll
                for (int j = 1; j < TOPK; j++) if (tv[j] < vmin) { vmin = tv[j]; mpos = j; }
                const int cbase = k0 + h * 64;
                for (int cc = 0; cc < 64; cc++) {
                    const float vv = sc[tid * 72 + cc];
                    if (vv > vmin) {
                        tv[mpos] = vv; ti[mpos] = cbase + cc;
                        vmin = tv[0]; mpos = 0;
#pragma unroll
                        for (int j = 1; j < TOPK; j++) if (tv[j] < vmin) { vmin = tv[j]; mpos = j; }
                    }
                }
#pragma unroll
                for (int j = 0; j < TOPK; j++) { tval[row * 8 + j] = tv[j]; tidx[row * 8 + j] = ti[j]; }
            }
            __syncthreads();
        }
    }

    const size_t base = (((size_t)b * NSB + bidx) * 256 + tid) * TOPK;
#pragma unroll
    for (int j = 0; j < TOPK; j++) {
        pval[base + j] = tval[tid * 8 + j];
        pidx[base + j] = tidx[tid * 8 + j];
    }
}

// ------- fused merge (warp-parallel exact top-8) + softmax + gather ----------
// Block per row, 128 threads. Warp 0: lane l owns partial list kt=l; 8 rounds
// of warp argmax extract the global top-8. Then all 4 warps gather U rows.
__global__ __launch_bounds__(128) void merge_gather_kernel(
    const float* __restrict__ pv, const int* __restrict__ pi,
    const float* __restrict__ U, const float* __restrict__ bvo,
    float* __restrict__ out) {
    const int row = blockIdx.x;
    const int b = row >> 12, rr = row & 4095;
    const int qt = rr >> 7;
    const int sq = qt >> 1;
    const int rib = rr - sq * 256;
    const size_t sbase = ((size_t)b * NSB + (size_t)sq * (sq + 1)) * 256 + rib;

    __shared__ float ps[TOPK];
    __shared__ int   ids[TOPK];

    const int tid = threadIdx.x;
    if (tid < 32) {
        const int lane = tid;
        float v[TOPK]; int id8[TOPK];
        if (lane <= qt) {
            const size_t base = (sbase + (size_t)lane * 256) * TOPK;
#pragma unroll
            for (int j = 0; j < TOPK; j++) { v[j] = pv[base + j]; id8[j] = pi[base + j]; }
        } else {
#pragma unroll
            for (int j = 0; j < TOPK; j++) { v[j] = -INFINITY; id8[j] = 0; }
        }
        float tv[TOPK]; int ti[TOPK];
#pragma unroll
        for (int r = 0; r < TOPK; r++) {
            // local max (static indices)
            float lm = v[0]; int ls = 0;
#pragma unroll
            for (int j = 1; j < TOPK; j++) if (v[j] > lm) { lm = v[j]; ls = j; }
            // warp argmax, lane-asc tie-break
            float m = lm; int who = lane;
#pragma unroll
            for (int o = 16; o; o >>= 1) {
                float om = __shfl_xor_sync(0xffffffffu, m, o);
                int ow = __shfl_xor_sync(0xffffffffu, who, o);
                if (om > m || (om == m && ow < who)) { m = om; who = ow; }
            }
            int widx = 0;
#pragma unroll
            for (int j = 0; j < TOPK; j++) if (j == ls) widx = id8[j];
            const int gidx = __shfl_sync(0xffffffffu, widx, who);
            tv[r] = m; ti[r] = gidx;
            if (lane == who) {
#pragma unroll
                for (int j = 0; j < TOPK; j++) if (j == ls) v[j] = -INFINITY;
            }
        }
        // softmax (redundant across lanes; lane 0 publishes)
        float mx = tv[0];
#pragma unroll
        for (int j = 1; j < TOPK; j++) mx = fmaxf(mx, tv[j]);
        float e[TOPK]; float ssum = 0.f;
#pragma unroll
        for (int j = 0; j < TOPK; j++) { e[j] = expf(tv[j] - mx); ssum += e[j]; }
        const float inv = 1.f / ssum;
        if (lane == 0) {
#pragma unroll
            for (int j = 0; j < TOPK; j++) { ps[j] = e[j] * inv; ids[j] = ti[j]; }
        }
    }
    __syncthreads();

    const float* ub = U + (size_t)b * NSEQ * DIM;
    const int c = tid * 8;
    float4 a0 = *(const float4*)(bvo + c);
    float4 a1 = *(const float4*)(bvo + c + 4);
#pragma unroll
    for (int j = 0; j < TOPK; j++) {
        const float4* vr = (const float4*)(ub + (size_t)ids[j] * DIM + c);
        const float pj = ps[j];
        float4 v0 = vr[0], v1 = vr[1];
        a0.x += pj * v0.x; a0.y += pj * v0.y; a0.z += pj * v0.z; a0.w += pj * v0.w;
        a1.x += pj * v1.x; a1.y += pj * v1.y; a1.z += pj * v1.z; a1.w += pj * v1.w;
    }
    float4* orow = (float4*)(out + (size_t)row * DIM + c);
    orow[0] = a0; orow[1] = a1;
}

// ---------------- launch -----------------------------------------------------
extern "C" void kernel_launch(void* const* d_in, const int* in_sizes, int n_in,
                              void* d_out, int out_size) {
    const float* S  = (const float*)d_in[0];
    const float* Wq = (const float*)d_in[1];
    const float* bq = (const float*)d_in[2];
    const float* Wk = (const float*)d_in[3];
    const float* bk = (const float*)d_in[4];  // row-const in softmax; drops out
    const float* Wv = (const float*)d_in[5];
    const float* bv = (const float*)d_in[6];
    const float* Wo = (const float*)d_in[7];
    const float* bo = (const float*)d_in[8];
    float* out = (float*)d_out;
    (void)bk;

    float *up, *pvp, *ahip, *alop;
    float *qhip, *qlop, *khip, *klop, *wthip, *wtlop;
    float *bvop, *yp, *wp;
    int *pip;
    cudaGetSymbolAddress((void**)&up, g_u);
    cudaGetSymbolAddress((void**)&pvp, g_pval);
    cudaGetSymbolAddress((void**)&pip, g_pidx);
    cudaGetSymbolAddress((void**)&ahip, g_ahi);
    cudaGetSymbolAddress((void**)&alop, g_alo);
    cudaGetSymbolAddress((void**)&qhip, g_qhi);
    cudaGetSymbolAddress((void**)&qlop, g_qlo);
    cudaGetSymbolAddress((void**)&khip, g_khi);
    cudaGetSymbolAddress((void**)&klop, g_klo);
    cudaGetSymbolAddress((void**)&wthip, g_wthi);
    cudaGetSymbolAddress((void**)&wtlop, g_wtlo);
    cudaGetSymbolAddress((void**)&bvop, g_bvo);
    cudaGetSymbolAddress((void**)&yp, g_y);
    cudaGetSymbolAddress((void**)&wp, g_w);

    cudaFuncSetAttribute(gemm_prep_kernel,
                         cudaFuncAttributeMaxDynamicSharedMemorySize, GEMM_SMEM);
    cudaFuncSetAttribute(gemm_tu_kernel,
                         cudaFuncAttributeMaxDynamicSharedMemorySize, GEMM_SMEM);
    cudaFuncSetAttribute(scores_super_kernel,
                         cudaFuncAttributeMaxDynamicSharedMemorySize, SSC_SMEM);

    const int WPACK_GRID = (DIM / 8) * KS8 / 8;   // 2048
    const int APACK_1K = (DIM / 16) * KS8 / 8;    // 1024

    // --- operand packs for prep: A buffer = [Wv | Wq], B buffer = [Wo | Wk] ---
    split_pack_a<<<APACK_1K, 256>>>(Wv, (float4*)ahip, (float4*)alop);
    split_pack_a<<<APACK_1K, 256>>>(Wq,
        (float4*)ahip + (size_t)8192 * 32, (float4*)alop + (size_t)8192 * 32);
    split_pack_w<<<WPACK_GRID, 256>>>(Wo, (float2*)khip, (float2*)klop);
    split_pack_kb<<<WPACK_GRID, 256>>>(Wk,
        (float2*)khip + (size_t)16384 * 32, (float2*)klop + (size_t)16384 * 32);

    // --- bias folds (independent) ---
    bvo_kernel<<<DIM / 128, 128>>>(bv, Wo, bo, bvop);
    ydot_kernel<<<DIM / 8, 256>>>(Wk, bq, yp);
    wdot_kernel<<<MROWS / 8, 256>>>(S, yp, wp);

    // --- fused prep GEMMs (split-K x2) + partial-sum pack ---
    gemm_prep_kernel<<<dim3(8, 4, 4), 256, GEMM_SMEM>>>(ahip, alop, khip, klop, up);
    prep_pack_sum<<<4096, 256>>>(up, (float2*)wthip, (float2*)wtlop);

    // --- fused S pack: A-fmt + B-fmt in one pass ---
    split_pack_s<<<(MROWS / 16) * KS8 / 8, 256>>>(
        S, (float4*)ahip, (float4*)alop, (float2*)khip, (float2*)klop);

    // --- fused: T = S@G packed A-fmt (3x), U = S@Wvo raw (2x) ---
    gemm_tu_kernel<<<dim3(16, MROWS / 256), 256, GEMM_SMEM>>>(
        ahip, alop, wthip, wtlop, qhip, qlop, up);

    scores_super_kernel<<<dim3(NSB, BSZ), 256, SSC_SMEM>>>(
        qhip, qlop, khip, klop, wp, pvp, pip);
    merge_gather_kernel<<<MROWS, 128>>>(pvp, pip, up, bvop, out);
}

// round 14
// speedup vs baseline: 3.6360x; 1.0987x over previous
#include <cuda_runtime.h>
#include <math.h>
#include <stdint.h>

#define BSZ   4
#define NSEQ  4096
#define DIM   1024
#define TOPK  8
#define NCAND 12
#define MROWS (BSZ * NSEQ)
#define KS8   (DIM / 8)
#define NSB   272
#define WSZF  ((size_t)DIM * DIM)

typedef unsigned long long ULL;

// ---------------- scratch (__device__ globals; no allocation allowed) -------
__device__ __align__(128) float g_u[(size_t)MROWS * DIM];     // prep partials, then U
__device__ __align__(128) float g_traw[(size_t)MROWS * DIM];  // raw T (rescore)
__device__ float g_pval[(size_t)BSZ * NSB * 256 * TOPK];
__device__ int   g_pidx[(size_t)BSZ * NSB * 256 * TOPK];
__device__ float g_bvo[DIM];
__device__ float g_y[DIM];
__device__ float g_w[MROWS];
__device__ __align__(128) float g_ahi[(size_t)MROWS * DIM];
__device__ __align__(128) float g_alo[(size_t)MROWS * DIM];
__device__ __align__(128) float g_qhi[(size_t)MROWS * DIM];   // A-fmt (T)
__device__ __align__(128) float g_qlo[(size_t)MROWS * DIM];
__device__ __align__(128) float g_khi[(size_t)MROWS * DIM];   // B-fmt (Wo/Wk then S)
__device__ __align__(128) float g_klo[(size_t)MROWS * DIM];
__device__ __align__(128) float g_wthi[2][WSZF];              // slot0 G, slot1 Wvo
__device__ __align__(128) float g_wtlo[2][WSZF];

// ---------------- helpers -----------------------------------------------------
__device__ __forceinline__ uint32_t smem_u32(const void* p) {
    uint32_t a;
    asm("{ .reg .u64 t; cvta.to.shared.u64 t, %1; cvt.u32.u64 %0, t; }"
        : "=r"(a) : "l"(p));
    return a;
}
__device__ __forceinline__ float tf32r(float x) {
    uint32_t u;
    asm("cvt.rna.tf32.f32 %0, %1;" : "=r"(u) : "f"(x));
    return __uint_as_float(u);
}
__device__ __forceinline__ void cpasync16(uint32_t saddr, const void* g) {
    asm volatile("cp.async.cg.shared.global [%0], [%1], 16;"
                 :: "r"(saddr), "l"(g));
}
#define CP_COMMIT() asm volatile("cp.async.commit_group;" ::: "memory")
#define CP_WAIT_1() asm volatile("cp.async.wait_group 1;" ::: "memory")
#define CP_WAIT_0() asm volatile("cp.async.wait_group 0;" ::: "memory")

__device__ __forceinline__ void mma8(float4& c, const uint4& a, const uint2& b) {
    asm volatile(
        "mma.sync.aligned.m16n8k8.row.col.f32.tf32.tf32.f32 "
        "{%0,%1,%2,%3}, {%4,%5,%6,%7}, {%8,%9}, {%0,%1,%2,%3};"
        : "+f"(c.x), "+f"(c.y), "+f"(c.z), "+f"(c.w)
        : "r"(a.x), "r"(a.y), "r"(a.z), "r"(a.w), "r"(b.x), "r"(b.y));
}

// ---------------- split+pack A-format: X[M,K] row-major ---------------------
__global__ __launch_bounds__(256) void split_pack_a(
    const float* __restrict__ X, float4* __restrict__ Phi, float4* __restrict__ Plo) {
    const int atom = blockIdx.x * 8 + (threadIdx.x >> 5);
    const int lane = threadIdx.x & 31;
    const int mt = atom >> 7;
    const int ks = atom & 127;
    const int g = lane >> 2, t = lane & 3;
    const size_t r0 = (size_t)(mt * 16 + g) * DIM + ks * 8 + t;
    const size_t r1 = r0 + 8 * DIM;
    float x0 = X[r0], x1 = X[r1], x2 = X[r0 + 4], x3 = X[r1 + 4];
    float4 h, l;
    h.x = tf32r(x0); l.x = tf32r(x0 - h.x);
    h.y = tf32r(x1); l.y = tf32r(x1 - h.y);
    h.z = tf32r(x2); l.z = tf32r(x2 - h.z);
    h.w = tf32r(x3); l.w = tf32r(x3 - h.w);
    Phi[(size_t)atom * 32 + lane] = h;
    Plo[(size_t)atom * 32 + lane] = l;
}

// ---------------- split+pack W (B-format) ------------------------------------
__global__ __launch_bounds__(256) void split_pack_w(
    const float* __restrict__ W, float2* __restrict__ Phi, float2* __restrict__ Plo) {
    const int atom = blockIdx.x * 8 + (threadIdx.x >> 5);
    const int lane = threadIdx.x & 31;
    const int nt = atom >> 7;
    const int ks = atom & 127;
    const int g = lane >> 2, t = lane & 3;
    float x0 = W[(size_t)(ks * 8 + t) * DIM + nt * 8 + g];
    float x1 = W[(size_t)(ks * 8 + t + 4) * DIM + nt * 8 + g];
    float2 h, l;
    h.x = tf32r(x0); l.x = tf32r(x0 - h.x);
    h.y = tf32r(x1); l.y = tf32r(x1 - h.y);
    Phi[(size_t)atom * 32 + lane] = h;
    Plo[(size_t)atom * 32 + lane] = l;
}

// ---------------- split+pack row-major [N,K] -> B-format ---------------------
__global__ __launch_bounds__(256) void split_pack_kb(
    const float* __restrict__ X, float2* __restrict__ Phi, float2* __restrict__ Plo) {
    const int atom = blockIdx.x * 8 + (threadIdx.x >> 5);
    const int lane = threadIdx.x & 31;
    const int nt = atom >> 7;
    const int ks = atom & 127;
    const int g = lane >> 2, t = lane & 3;
    const size_t base = (size_t)(nt * 8 + g) * DIM + ks * 8 + t;
    float x0 = X[base];
    float x1 = X[base + 4];
    float2 h, l;
    h.x = tf32r(x0); l.x = tf32r(x0 - h.x);
    h.y = tf32r(x1); l.y = tf32r(x1 - h.y);
    Phi[(size_t)atom * 32 + lane] = h;
    Plo[(size_t)atom * 32 + lane] = l;
}

// ------- fused S pack: A-format + B-format in one pass -----------------------
__global__ __launch_bounds__(256) void split_pack_s(
    const float* __restrict__ X,
    float4* __restrict__ Ahi, float4* __restrict__ Alo,
    float2* __restrict__ Bhi, float2* __restrict__ Blo) {
    const int atom = blockIdx.x * 8 + (threadIdx.x >> 5);
    const int lane = threadIdx.x & 31;
    const int mt = atom >> 7;
    const int ks = atom & 127;
    const int g = lane >> 2, t = lane & 3;
    const size_t r0 = (size_t)(mt * 16 + g) * DIM + ks * 8 + t;
    const size_t r1 = r0 + 8 * DIM;
    float x0 = X[r0], x1 = X[r1], x2 = X[r0 + 4], x3 = X[r1 + 4];
    float4 h, l;
    h.x = tf32r(x0); l.x = tf32r(x0 - h.x);
    h.y = tf32r(x1); l.y = tf32r(x1 - h.y);
    h.z = tf32r(x2); l.z = tf32r(x2 - h.z);
    h.w = tf32r(x3); l.w = tf32r(x3 - h.w);
    Ahi[(size_t)atom * 32 + lane] = h;
    Alo[(size_t)atom * 32 + lane] = l;
    const size_t b0 = ((size_t)(2 * mt) * KS8 + ks) * 32 + lane;
    const size_t b1 = b0 + (size_t)KS8 * 32;
    Bhi[b0] = make_float2(h.x, h.z);
    Blo[b0] = make_float2(l.x, l.z);
    Bhi[b1] = make_float2(h.y, h.w);
    Blo[b1] = make_float2(l.y, l.w);
}

// ---------------- bvo = bv @ Wo + bo ----------------------------------------
__global__ __launch_bounds__(128) void bvo_kernel(
    const float* __restrict__ bv, const float* __restrict__ Wo,
    const float* __restrict__ bo, float* __restrict__ bvo) {
    const int n = blockIdx.x * 128 + threadIdx.x;
    float acc = bo[n];
    for (int k = 0; k < DIM; k++) acc += bv[k] * Wo[(size_t)k * DIM + n];
    bvo[n] = acc;
}

// ---------------- y[d] = Wk[d,:] . bq ----------------------------------------
__global__ __launch_bounds__(256) void ydot_kernel(
    const float* __restrict__ Wk, const float* __restrict__ bq,
    float* __restrict__ y) {
    const int wid = threadIdx.x >> 5, lane = threadIdx.x & 31;
    const int row = blockIdx.x * 8 + wid;
    const float4* r4 = (const float4*)(Wk + (size_t)row * DIM);
    const float4* b4 = (const float4*)bq;
    float acc = 0.f;
    for (int i = lane; i < DIM / 4; i += 32) {
        float4 a = r4[i], b = b4[i];
        acc += a.x * b.x + a.y * b.y + a.z * b.z + a.w * b.w;
    }
#pragma unroll
    for (int o = 16; o; o >>= 1) acc += __shfl_xor_sync(0xffffffffu, acc, o);
    if (lane == 0) y[row] = acc;
}

// ---------------- w[m] = (S[m,:] . y) / 32 -----------------------------------
__global__ __launch_bounds__(256) void wdot_kernel(
    const float* __restrict__ S, const float* __restrict__ y,
    float* __restrict__ w) {
    const int wid = threadIdx.x >> 5, lane = threadIdx.x & 31;
    const int row = blockIdx.x * 8 + wid;
    const float4* r4 = (const float4*)(S + (size_t)row * DIM);
    const float4* y4 = (const float4*)y;
    float acc = 0.f;
    for (int i = lane; i < DIM / 4; i += 32) {
        float4 a = r4[i], b = y4[i];
        acc += a.x * b.x + a.y * b.y + a.z * b.z + a.w * b.w;
    }
#pragma unroll
    for (int o = 16; o; o >>= 1) acc += __shfl_xor_sync(0xffffffffu, acc, o);
    if (lane == 0) w[row] = acc * 0.03125f;
}

// ---------------- shared 3x/2x TF32 mainloop (256x128 tile, BK=16) ----------
#define GEMM_SMEM (3 * 12288 * 4)

template <bool THIRD>
__device__ __forceinline__ void mma_mainloop(
    float* sm, const float* __restrict__ Ahi, const float* __restrict__ Alo,
    const float* __restrict__ Bhi, const float* __restrict__ Blo,
    int br16, int bn16, int kc0, int iters, float4 (&acc)[4][8]) {
    const int tid = threadIdx.x;
    const int lane = tid & 31, wid = tid >> 5;
    const int wy = wid >> 1, wx = wid & 1;
    const uint32_t smb = smem_u32(sm);

    auto load_stage = [&](int kc, int s) {
        const uint32_t sb = smb + s * 49152;
#pragma unroll
        for (int j = 0; j < 4; j++) {
            const int cA = tid + j * 256;
            const int mtl = cA >> 6, off = cA & 63;
            const uint32_t so = sb + (uint32_t)(mtl * 256 + off * 4) * 4;
            const size_t go = ((size_t)(br16 + mtl) * KS8 + kc * 2) * 128 + off * 4;
            cpasync16(so, Ahi + go);
            cpasync16(so + 4096 * 4, Alo + go);
        }
#pragma unroll
        for (int j = 0; j < 2; j++) {
            const int cB = tid + j * 256;
            const int ntl = cB >> 5, off = cB & 31;
            const uint32_t so = sb + (uint32_t)(8192 + ntl * 128 + off * 4) * 4;
            const size_t go = ((size_t)(bn16 + ntl) * KS8 + kc * 2) * 64 + off * 4;
            cpasync16(so, Bhi + go);
            if (THIRD) cpasync16(so + 2048 * 4, Blo + go);
        }
    };

    load_stage(kc0, 0); CP_COMMIT();
    load_stage(kc0 + 1, 1); CP_COMMIT();

#pragma unroll
    for (int i = 0; i < 4; i++)
#pragma unroll
        for (int j = 0; j < 8; j++) acc[i][j] = make_float4(0.f, 0.f, 0.f, 0.f);

    for (int c = 0; c < iters; c++) {
        if (c < iters - 2) { CP_WAIT_1(); } else { CP_WAIT_0(); }
        __syncthreads();
        if (c + 2 < iters) { load_stage(kc0 + c + 2, (c + 2) % 3); CP_COMMIT(); }
        const float* st = sm + (c % 3) * 12288;
#pragma unroll
        for (int ks = 0; ks < 2; ks++) {
            uint4 Ah[4], Al[4];
            uint2 Bh[8], Bl[8];
#pragma unroll
            for (int i = 0; i < 4; i++) {
                const float* p = st + ((wy * 4 + i) * 2 + ks) * 128 + lane * 4;
                Ah[i] = *(const uint4*)p;
                Al[i] = *(const uint4*)(p + 4096);
            }
#pragma unroll
            for (int j = 0; j < 8; j++) {
                const float* p = st + 8192 + ((wx * 8 + j) * 2 + ks) * 64 + lane * 2;
                Bh[j] = *(const uint2*)p;
                if (THIRD) Bl[j] = *(const uint2*)(p + 2048);
            }
#pragma unroll
            for (int i = 0; i < 4; i++)
#pragma unroll
                for (int j = 0; j < 8; j++) {
                    mma8(acc[i][j], Ah[i], Bh[j]);
                    if (THIRD) mma8(acc[i][j], Ah[i], Bl[j]);
                    mma8(acc[i][j], Al[i], Bh[j]);
                }
        }
    }
}

// --------- fused prep GEMMs: Wvo = Wv@Wo and G = Wq@Wk^T, split-K x2 --------
__global__ __launch_bounds__(256, 1) void gemm_prep_kernel(
    const float* __restrict__ Ahi, const float* __restrict__ Alo,
    const float* __restrict__ Bhi, const float* __restrict__ Blo,
    float* __restrict__ P) {
    extern __shared__ float sm[];
    const int wsel = blockIdx.z >> 1;
    const int khalf = blockIdx.z & 1;
    const int tid = threadIdx.x;
    const int lane = tid & 31, wid = tid >> 5;
    const int wy = wid >> 1, wx = wid & 1;
    const int g = lane >> 2, t = lane & 3;
    const int m0 = blockIdx.y * 256, n0 = blockIdx.x * 128;

    float4 acc[4][8];
    mma_mainloop<true>(sm, Ahi, Alo, Bhi, Blo,
                       wsel * 64 + blockIdx.y * 16, wsel * 128 + blockIdx.x * 16,
                       khalf * 32, 32, acc);

    float* out = P + (size_t)(wsel * 2 + khalf) * DIM * DIM;
#pragma unroll
    for (int i = 0; i < 4; i++) {
        const int r0 = m0 + wy * 64 + i * 16 + g;
#pragma unroll
        for (int j = 0; j < 8; j++) {
            const int col = n0 + wx * 64 + j * 8 + t * 2;
            *(float2*)(out + (size_t)r0 * DIM + col) =
                make_float2(acc[i][j].x, acc[i][j].y);
            *(float2*)(out + (size_t)(r0 + 8) * DIM + col) =
                make_float2(acc[i][j].z, acc[i][j].w);
        }
    }
}

// --------- sum split-K partials + pack B-format into weight slots ------------
__global__ __launch_bounds__(256) void prep_pack_sum(
    const float* __restrict__ P, float2* __restrict__ WHi, float2* __restrict__ WLo) {
    const int bx = blockIdx.x;
    const int w = bx >> 11;
    const float* p0 = P + (size_t)(w == 0 ? 2 : 0) * DIM * DIM;
    const float* p1 = p0 + (size_t)DIM * DIM;
    float2* dhi = WHi + (size_t)w * WSZF / 2;
    float2* dlo = WLo + (size_t)w * WSZF / 2;
    const int atom = (bx & 2047) * 8 + (threadIdx.x >> 5);
    const int lane = threadIdx.x & 31;
    const int nt = atom >> 7;
    const int ks = atom & 127;
    const int g = lane >> 2, t = lane & 3;
    const size_t i0 = (size_t)(ks * 8 + t) * DIM + nt * 8 + g;
    const size_t i1 = (size_t)(ks * 8 + t + 4) * DIM + nt * 8 + g;
    float x0 = p0[i0] + p1[i0];
    float x1 = p0[i1] + p1[i1];
    float2 h, l;
    h.x = tf32r(x0); l.x = tf32r(x0 - h.x);
    h.y = tf32r(x1); l.y = tf32r(x1 - h.y);
    dhi[(size_t)atom * 32 + lane] = h;
    dlo[(size_t)atom * 32 + lane] = l;
}

// Fused T/U projection. wsel 0 -> T = S@G packed A-fmt + raw (3x),
// wsel 1 -> U = S@Wvo raw (2x).
__global__ __launch_bounds__(256, 1) void gemm_tu_kernel(
    const float* __restrict__ Ahi, const float* __restrict__ Alo,
    const float* __restrict__ Whi, const float* __restrict__ Wlo,
    float* __restrict__ Thi, float* __restrict__ Tlo,
    float* __restrict__ Traw, float* __restrict__ U) {
    extern __shared__ float sm[];
    const int wsel = blockIdx.x & 1;
    const int nxt = blockIdx.x >> 1;
    const int tid = threadIdx.x;
    const int lane = tid & 31, wid = tid >> 5;
    const int wy = wid >> 1, wx = wid & 1;
    const int g = lane >> 2, t = lane & 3;
    const int m0 = blockIdx.y * 256, n0 = nxt * 128;

    if (wsel == 1) {
        float4 acc[4][8];
        mma_mainloop<false>(sm, Ahi, Alo, Whi + WSZF, Wlo + WSZF,
                            blockIdx.y * 16, nxt * 16, 0, 64, acc);
#pragma unroll
        for (int i = 0; i < 4; i++) {
            const int r0 = m0 + wy * 64 + i * 16 + g;
#pragma unroll
            for (int j = 0; j < 8; j++) {
                const int col = n0 + wx * 64 + j * 8 + t * 2;
                *(float2*)(U + (size_t)r0 * DIM + col) =
                    make_float2(acc[i][j].x, acc[i][j].y);
                *(float2*)(U + (size_t)(r0 + 8) * DIM + col) =
                    make_float2(acc[i][j].z, acc[i][j].w);
            }
        }
        return;
    }

    float4 acc[4][8];
    mma_mainloop<true>(sm, Ahi, Alo, Whi, Wlo,
                       blockIdx.y * 16, nxt * 16, 0, 64, acc);

    // raw T write (for exact rescore)
#pragma unroll
    for (int i = 0; i < 4; i++) {
        const int r0 = m0 + wy * 64 + i * 16 + g;
#pragma unroll
        for (int j = 0; j < 8; j++) {
            const int col = n0 + wx * 64 + j * 8 + t * 2;
            *(float2*)(Traw + (size_t)r0 * DIM + col) =
                make_float2(acc[i][j].x, acc[i][j].y);
            *(float2*)(Traw + (size_t)(r0 + 8) * DIM + col) =
                make_float2(acc[i][j].z, acc[i][j].w);
        }
    }

    __syncthreads();  // pipeline smem free
#pragma unroll
    for (int i = 0; i < 4; i++) {
        const int r0 = wy * 64 + i * 16 + g;
#pragma unroll
        for (int j = 0; j < 8; j++) {
            const int col = wx * 64 + j * 8 + t * 2;
            *(float2*)&sm[r0 * 132 + col] = make_float2(acc[i][j].x, acc[i][j].y);
            *(float2*)&sm[(r0 + 8) * 132 + col] = make_float2(acc[i][j].z, acc[i][j].w);
        }
    }
    __syncthreads();

    for (int a = wid; a < 256; a += 8) {
        const int amt = a >> 4, aks = a & 15;
        const float* bp = sm + (amt * 16 + g) * 132 + aks * 8 + t;
        float x0 = bp[0], x1 = bp[8 * 132], x2 = bp[4], x3 = bp[8 * 132 + 4];
        float4 h, l;
        h.x = tf32r(x0); l.x = tf32r(x0 - h.x);
        h.y = tf32r(x1); l.y = tf32r(x1 - h.y);
        h.z = tf32r(x2); l.z = tf32r(x2 - h.z);
        h.w = tf32r(x3); l.w = tf32r(x3 - h.w);
        const size_t atom = (size_t)(blockIdx.y * 16 + amt) * KS8 + (nxt * 16 + aks);
        ((float4*)Thi)[atom * 32 + lane] = h;
        ((float4*)Tlo)[atom * 32 + lane] = l;
    }
}

// ---------------- supertile 2x TF32 causal scores + candidate top-8 ---------
// Pass 1: scores ~= (Thi+Tlo).Shi/32 + w (2x split; Slo dropped). Candidates only.
#define SSC_SMEM ((3 * 12288 + 128 * 72 + 256 * 8 + 256 * 8 + 128) * 4)

__global__ __launch_bounds__(256, 1) void scores_super_kernel(
    const float* __restrict__ Thi, const float* __restrict__ Tlo,
    const float* __restrict__ Shi, const float* __restrict__ Slo,
    const float* __restrict__ w,
    float* __restrict__ pval, int* __restrict__ pidx) {
    extern __shared__ float sm[];
    float* sc = sm + 36864;
    float* tval = sm + 46080;
    int* tidx = (int*)(sm + 48128);
    float* wsc = sm + 50176;

    const int tid = threadIdx.x;
    const int lane = tid & 31, wid = tid >> 5;
    const int wy = wid >> 1, wx = wid & 1;
    const int g = lane >> 2, t = lane & 3;
    const int b = blockIdx.y;
    const int bidx = blockIdx.x;

    int sq = (int)((sqrtf(4.0f * (float)bidx + 1.0f) - 1.0f) * 0.5f);
    while ((sq + 1) * (sq + 2) <= bidx) sq++;
    while (sq * (sq + 1) > bidx) sq--;
    const int kt = bidx - sq * (sq + 1);
    const int q0 = sq * 256, k0 = kt * 128;

    for (int i = tid; i < 256 * TOPK; i += 256) {
        tval[i] = -INFINITY;
        tidx[i] = 0;
    }
    if (tid < 128) wsc[tid] = w[b * NSEQ + k0 + tid];

    float4 acc[4][8];
    mma_mainloop<false>(sm, Thi, Tlo, Shi, Slo,
                        b * 256 + sq * 16, b * 512 + kt * 16, 0, 64, acc);

#pragma unroll
    for (int rh = 0; rh < 2; rh++) {
#pragma unroll
        for (int h = 0; h < 2; h++) {
            if ((wy >> 1) == rh && wx == h) {
#pragma unroll
                for (int i = 0; i < 4; i++) {
                    const int rl = wy * 64 + i * 16 + g;
                    const int srow = rl - rh * 128;
#pragma unroll
                    for (int j = 0; j < 8; j++) {
                        const int col = j * 8 + t * 2;
                        const int lc = h * 64 + col;
                        const int gc = k0 + lc;
                        const int gr0 = q0 + rl, gr1 = gr0 + 8;
                        const float w0 = wsc[lc], w1 = wsc[lc + 1];
                        float v0 = acc[i][j].x * 0.03125f + w0;
                        float v1 = acc[i][j].y * 0.03125f + w1;
                        float v2 = acc[i][j].z * 0.03125f + w0;
                        float v3 = acc[i][j].w * 0.03125f + w1;
                        if (gc + 0 > gr0) v0 = -INFINITY;
                        if (gc + 1 > gr0) v1 = -INFINITY;
                        if (gc + 0 > gr1) v2 = -INFINITY;
                        if (gc + 1 > gr1) v3 = -INFINITY;
                        *(float2*)&sc[srow * 72 + col] = make_float2(v0, v1);
                        *(float2*)&sc[(srow + 8) * 72 + col] = make_float2(v2, v3);
                    }
                }
            }
            __syncthreads();
            if (tid < 128) {
                const int row = rh * 128 + tid;
                float tv[TOPK]; int ti[TOPK];
#pragma unroll
                for (int j = 0; j < TOPK; j++) { tv[j] = tval[row * 8 + j]; ti[j] = tidx[row * 8 + j]; }
                float vmin = tv[0]; int mpos = 0;
#pragma unroll
                for (int j = 1; j < TOPK; j++) if (tv[j] < vmin) { vmin = tv[j]; mpos = j; }
                const int cbase = k0 + h * 64;
                for (int cc = 0; cc < 64; cc++) {
                    const float vv = sc[tid * 72 + cc];
                    if (vv > vmin) {
                        tv[mpos] = vv; ti[mpos] = cbase + cc;
                        vmin = tv[0]; mpos = 0;
#pragma unroll
                        for (int j = 1; j < TOPK; j++) if (tv[j] < vmin) { vmin = tv[j]; mpos = j; }
                    }
                }
#pragma unroll
                for (int j = 0; j < TOPK; j++) { tval[row * 8 + j] = tv[j]; tidx[row * 8 + j] = ti[j]; }
            }
            __syncthreads();
        }
    }

    const size_t base = (((size_t)b * NSB + bidx) * 256 + tid) * TOPK;
#pragma unroll
    for (int j = 0; j < TOPK; j++) {
        pval[base + j] = tval[tid * 8 + j];
        pidx[base + j] = tidx[tid * 8 + j];
    }
}

// ------- merge top-12 (2x) -> exact rescore -> top-8 softmax -> gather -------
__global__ __launch_bounds__(128) void merge_rescore_gather(
    const float* __restrict__ pv, const int* __restrict__ pi,
    const float* __restrict__ Traw, const float* __restrict__ S,
    const float* __restrict__ w, const float* __restrict__ U,
    const float* __restrict__ bvo, float* __restrict__ out) {
    const int row = blockIdx.x;
    const int b = row >> 12, rr = row & 4095;
    const int qt = rr >> 7;
    const int sq = qt >> 1;
    const int rib = rr - sq * 256;
    const size_t sbase = ((size_t)b * NSB + (size_t)sq * (sq + 1)) * 256 + rib;

    __shared__ float trow[DIM];
    __shared__ float cval[NCAND];
    __shared__ int   cidx[NCAND];
    __shared__ float cex[NCAND];
    __shared__ float ps[TOPK];
    __shared__ int   ids[TOPK];

    const int tid = threadIdx.x;
    const int lane = tid & 31, wid = tid >> 5;

    // load T row to smem (256 float4 over 128 threads)
    {
        const float4* tr = (const float4*)(Traw + (size_t)row * DIM);
        ((float4*)trow)[tid] = tr[tid];
        ((float4*)trow)[tid + 128] = tr[tid + 128];
    }

    // warp 0: merge partial lists to top-NCAND by 2x value
    if (tid < 32) {
        float v[TOPK]; int id8[TOPK];
        if (lane <= qt) {
            const size_t base = (sbase + (size_t)lane * 256) * TOPK;
#pragma unroll
            for (int j = 0; j < TOPK; j++) { v[j] = pv[base + j]; id8[j] = pi[base + j]; }
        } else {
#pragma unroll
            for (int j = 0; j < TOPK; j++) { v[j] = -INFINITY; id8[j] = 0; }
        }
#pragma unroll
        for (int r = 0; r < NCAND; r++) {
            float lm = v[0]; int ls = 0;
#pragma unroll
            for (int j = 1; j < TOPK; j++) if (v[j] > lm) { lm = v[j]; ls = j; }
            float m = lm; int who = lane;
#pragma unroll
            for (int o = 16; o; o >>= 1) {
                float om = __shfl_xor_sync(0xffffffffu, m, o);
                int ow = __shfl_xor_sync(0xffffffffu, who, o);
                if (om > m || (om == m && ow < who)) { m = om; who = ow; }
            }
            int widx = 0;
#pragma unroll
            for (int j = 0; j < TOPK; j++) if (j == ls) widx = id8[j];
            const int gidx = __shfl_sync(0xffffffffu, widx, who);
            if (lane == 0) { cval[r] = m; cidx[r] = gidx; }
            if (lane == who) {
#pragma unroll
                for (int j = 0; j < TOPK; j++) if (j == ls) v[j] = -INFINITY;
            }
        }
    }
    __syncthreads();

    // rescore candidates exactly: each warp handles NCAND/4 candidates
    for (int c = wid; c < NCAND; c += 4) {
        const float v2 = cval[c];
        const int idx = cidx[c];
        float acc = 0.f;
        if (v2 != -INFINITY) {
            const float4* srow = (const float4*)(S + ((size_t)b * NSEQ + idx) * DIM);
            const float4* tr4 = (const float4*)trow;
            for (int i = lane; i < DIM / 4; i += 32) {
                float4 s = srow[i], tt = tr4[i];
                acc += tt.x * s.x + tt.y * s.y + tt.z * s.z + tt.w * s.w;
            }
        }
#pragma unroll
        for (int o = 16; o; o >>= 1) acc += __shfl_xor_sync(0xffffffffu, acc, o);
        if (lane == 0)
            cex[c] = (v2 != -INFINITY)
                         ? acc * 0.03125f + w[b * NSEQ + idx]
                         : -INFINITY;
    }
    __syncthreads();

    // thread 0: exact top-8 of NCAND + softmax
    if (tid == 0) {
        float ev[NCAND]; int ei[NCAND];
#pragma unroll
        for (int j = 0; j < NCAND; j++) { ev[j] = cex[j]; ei[j] = cidx[j]; }
        float tv[TOPK]; int ti[TOPK];
#pragma unroll
        for (int r = 0; r < TOPK; r++) {
            int m = 0; float best = ev[0];
#pragma unroll
            for (int j = 1; j < NCAND; j++) if (ev[j] > best) { best = ev[j]; m = j; }
            tv[r] = best; ti[r] = ei[m]; ev[m] = -INFINITY;
        }
        float mx = tv[0];
#pragma unroll
        for (int j = 1; j < TOPK; j++) mx = fmaxf(mx, tv[j]);
        float e[TOPK]; float ssum = 0.f;
#pragma unroll
        for (int j = 0; j < TOPK; j++) { e[j] = expf(tv[j] - mx); ssum += e[j]; }
        const float inv = 1.f / ssum;
#pragma unroll
        for (int j = 0; j < TOPK; j++) { ps[j] = e[j] * inv; ids[j] = ti[j]; }
    }
    __syncthreads();

    const float* ub = U + (size_t)b * NSEQ * DIM;
    const int c = tid * 8;
    float4 a0 = *(const float4*)(bvo + c);
    float4 a1 = *(const float4*)(bvo + c + 4);
#pragma unroll
    for (int j = 0; j < TOPK; j++) {
        const float4* vr = (const float4*)(ub + (size_t)ids[j] * DIM + c);
        const float pj = ps[j];
        float4 v0 = vr[0], v1 = vr[1];
        a0.x += pj * v0.x; a0.y += pj * v0.y; a0.z += pj * v0.z; a0.w += pj * v0.w;
        a1.x += pj * v1.x; a1.y += pj * v1.y; a1.z += pj * v1.z; a1.w += pj * v1.w;
    }
    float4* orow = (float4*)(out + (size_t)row * DIM + c);
    orow[0] = a0; orow[1] = a1;
}

// ---------------- launch -----------------------------------------------------
extern "C" void kernel_launch(void* const* d_in, const int* in_sizes, int n_in,
                              void* d_out, int out_size) {
    const float* S  = (const float*)d_in[0];
    const float* Wq = (const float*)d_in[1];
    const float* bq = (const float*)d_in[2];
    const float* Wk = (const float*)d_in[3];
    const float* bk = (const float*)d_in[4];  // row-const in softmax; drops out
    const float* Wv = (const float*)d_in[5];
    const float* bv = (const float*)d_in[6];
    const float* Wo = (const float*)d_in[7];
    const float* bo = (const float*)d_in[8];
    float* out = (float*)d_out;
    (void)bk;

    float *up, *trp, *pvp, *ahip, *alop;
    float *qhip, *qlop, *khip, *klop, *wthip, *wtlop;
    float *bvop, *yp, *wp;
    int *pip;
    cudaGetSymbolAddress((void**)&up, g_u);
    cudaGetSymbolAddress((void**)&trp, g_traw);
    cudaGetSymbolAddress((void**)&pvp, g_pval);
    cudaGetSymbolAddress((void**)&pip, g_pidx);
    cudaGetSymbolAddress((void**)&ahip, g_ahi);
    cudaGetSymbolAddress((void**)&alop, g_alo);
    cudaGetSymbolAddress((void**)&qhip, g_qhi);
    cudaGetSymbolAddress((void**)&qlop, g_qlo);
    cudaGetSymbolAddress((void**)&khip, g_khi);
    cudaGetSymbolAddress((void**)&klop, g_klo);
    cudaGetSymbolAddress((void**)&wthip, g_wthi);
    cudaGetSymbolAddress((void**)&wtlop, g_wtlo);
    cudaGetSymbolAddress((void**)&bvop, g_bvo);
    cudaGetSymbolAddress((void**)&yp, g_y);
    cudaGetSymbolAddress((void**)&wp, g_w);

    cudaFuncSetAttribute(gemm_prep_kernel,
                         cudaFuncAttributeMaxDynamicSharedMemorySize, GEMM_SMEM);
    cudaFuncSetAttribute(gemm_tu_kernel,
                         cudaFuncAttributeMaxDynamicSharedMemorySize, GEMM_SMEM);
    cudaFuncSetAttribute(scores_super_kernel,
                         cudaFuncAttributeMaxDynamicSharedMemorySize, SSC_SMEM);

    const int WPACK_GRID = (DIM / 8) * KS8 / 8;   // 2048
    const int APACK_1K = (DIM / 16) * KS8 / 8;    // 1024

    // operand packs for prep: A buffer = [Wv | Wq], B buffer = [Wo | Wk]
    split_pack_a<<<APACK_1K, 256>>>(Wv, (float4*)ahip, (float4*)alop);
    split_pack_a<<<APACK_1K, 256>>>(Wq,
        (float4*)ahip + (size_t)8192 * 32, (float4*)alop + (size_t)8192 * 32);
    split_pack_w<<<WPACK_GRID, 256>>>(Wo, (float2*)khip, (float2*)klop);
    split_pack_kb<<<WPACK_GRID, 256>>>(Wk,
        (float2*)khip + (size_t)16384 * 32, (float2*)klop + (size_t)16384 * 32);

    // bias folds
    bvo_kernel<<<DIM / 128, 128>>>(bv, Wo, bo, bvop);
    ydot_kernel<<<DIM / 8, 256>>>(Wk, bq, yp);
    wdot_kernel<<<MROWS / 8, 256>>>(S, yp, wp);

    // fused prep GEMMs (split-K x2) + partial-sum pack
    gemm_prep_kernel<<<dim3(8, 4, 4), 256, GEMM_SMEM>>>(ahip, alop, khip, klop, up);
    prep_pack_sum<<<4096, 256>>>(up, (float2*)wthip, (float2*)wtlop);

    // fused S pack: A-fmt + B-fmt in one pass
    split_pack_s<<<(MROWS / 16) * KS8 / 8, 256>>>(
        S, (float4*)ahip, (float4*)alop, (float2*)khip, (float2*)klop);

    // fused: T = S@G (3x, packed + raw), U = S@Wvo (2x, raw)
    gemm_tu_kernel<<<dim3(16, MROWS / 256), 256, GEMM_SMEM>>>(
        ahip, alop, wthip, wtlop, qhip, qlop, trp, up);

    // pass 1: 2x scores -> per-tile candidate top-8
    scores_super_kernel<<<dim3(NSB, BSZ), 256, SSC_SMEM>>>(
        qhip, qlop, khip, klop, wp, pvp, pip);
    // pass 2: merge top-12, exact rescore, softmax, gather
    merge_rescore_gather<<<MROWS, 128>>>(pvp, pip, trp, S, wp, up, bvop, out);
}

// round 15
// speedup vs baseline: 4.1655x; 1.1456x over previous
#include <cuda_runtime.h>
#include <math.h>
#include <stdint.h>

#define BSZ   4
#define NSEQ  4096
#define DIM   1024
#define TOPK  8
#define NCAND 16
#define MROWS (BSZ * NSEQ)
#define KS8   (DIM / 8)
#define NSB   272
#define WSZF  ((size_t)DIM * DIM)

typedef unsigned long long ULL;

// ---------------- scratch (__device__ globals; no allocation allowed) -------
__device__ __align__(128) float g_u[(size_t)MROWS * DIM];     // prep partials, then U
__device__ __align__(128) float g_traw[(size_t)MROWS * DIM];  // raw T (rescore)
__device__ float g_pval[(size_t)BSZ * NSB * 256 * TOPK];
__device__ int   g_pidx[(size_t)BSZ * NSB * 256 * TOPK];
__device__ float g_bvo[DIM];
__device__ float g_y[DIM];
__device__ float g_w[MROWS];
__device__ __align__(128) float g_ahi[(size_t)MROWS * DIM];
__device__ __align__(128) float g_alo[(size_t)MROWS * DIM];
__device__ __align__(128) float g_qhi[(size_t)MROWS * DIM];   // A-fmt Thi
__device__ __align__(128) float g_khi[(size_t)MROWS * DIM];   // B-fmt (Wo/Wk then S hi)
__device__ __align__(128) float g_klo[(size_t)MROWS * DIM];   // B-fmt lo (prep only)
__device__ __align__(128) float g_wthi[2][WSZF];              // slot0 G, slot1 Wvo
__device__ __align__(128) float g_wtlo[2][WSZF];

// ---------------- helpers -----------------------------------------------------
__device__ __forceinline__ uint32_t smem_u32(const void* p) {
    uint32_t a;
    asm("{ .reg .u64 t; cvta.to.shared.u64 t, %1; cvt.u32.u64 %0, t; }"
        : "=r"(a) : "l"(p));
    return a;
}
__device__ __forceinline__ float tf32r(float x) {
    uint32_t u;
    asm("cvt.rna.tf32.f32 %0, %1;" : "=r"(u) : "f"(x));
    return __uint_as_float(u);
}
__device__ __forceinline__ void cpasync16(uint32_t saddr, const void* g) {
    asm volatile("cp.async.cg.shared.global [%0], [%1], 16;"
                 :: "r"(saddr), "l"(g));
}
#define CP_COMMIT() asm volatile("cp.async.commit_group;" ::: "memory")
#define CP_WAIT_1() asm volatile("cp.async.wait_group 1;" ::: "memory")
#define CP_WAIT_0() asm volatile("cp.async.wait_group 0;" ::: "memory")

__device__ __forceinline__ void mma8(float4& c, const uint4& a, const uint2& b) {
    asm volatile(
        "mma.sync.aligned.m16n8k8.row.col.f32.tf32.tf32.f32 "
        "{%0,%1,%2,%3}, {%4,%5,%6,%7}, {%8,%9}, {%0,%1,%2,%3};"
        : "+f"(c.x), "+f"(c.y), "+f"(c.z), "+f"(c.w)
        : "r"(a.x), "r"(a.y), "r"(a.z), "r"(a.w), "r"(b.x), "r"(b.y));
}

// ---------------- split+pack A-format: X[M,K] row-major ---------------------
__global__ __launch_bounds__(256) void split_pack_a(
    const float* __restrict__ X, float4* __restrict__ Phi, float4* __restrict__ Plo) {
    const int atom = blockIdx.x * 8 + (threadIdx.x >> 5);
    const int lane = threadIdx.x & 31;
    const int mt = atom >> 7;
    const int ks = atom & 127;
    const int g = lane >> 2, t = lane & 3;
    const size_t r0 = (size_t)(mt * 16 + g) * DIM + ks * 8 + t;
    const size_t r1 = r0 + 8 * DIM;
    float x0 = X[r0], x1 = X[r1], x2 = X[r0 + 4], x3 = X[r1 + 4];
    float4 h, l;
    h.x = tf32r(x0); l.x = tf32r(x0 - h.x);
    h.y = tf32r(x1); l.y = tf32r(x1 - h.y);
    h.z = tf32r(x2); l.z = tf32r(x2 - h.z);
    h.w = tf32r(x3); l.w = tf32r(x3 - h.w);
    Phi[(size_t)atom * 32 + lane] = h;
    Plo[(size_t)atom * 32 + lane] = l;
}

// ---------------- split+pack W (B-format) ------------------------------------
__global__ __launch_bounds__(256) void split_pack_w(
    const float* __restrict__ W, float2* __restrict__ Phi, float2* __restrict__ Plo) {
    const int atom = blockIdx.x * 8 + (threadIdx.x >> 5);
    const int lane = threadIdx.x & 31;
    const int nt = atom >> 7;
    const int ks = atom & 127;
    const int g = lane >> 2, t = lane & 3;
    float x0 = W[(size_t)(ks * 8 + t) * DIM + nt * 8 + g];
    float x1 = W[(size_t)(ks * 8 + t + 4) * DIM + nt * 8 + g];
    float2 h, l;
    h.x = tf32r(x0); l.x = tf32r(x0 - h.x);
    h.y = tf32r(x1); l.y = tf32r(x1 - h.y);
    Phi[(size_t)atom * 32 + lane] = h;
    Plo[(size_t)atom * 32 + lane] = l;
}

// ---------------- split+pack row-major [N,K] -> B-format ---------------------
__global__ __launch_bounds__(256) void split_pack_kb(
    const float* __restrict__ X, float2* __restrict__ Phi, float2* __restrict__ Plo) {
    const int atom = blockIdx.x * 8 + (threadIdx.x >> 5);
    const int lane = threadIdx.x & 31;
    const int nt = atom >> 7;
    const int ks = atom & 127;
    const int g = lane >> 2, t = lane & 3;
    const size_t base = (size_t)(nt * 8 + g) * DIM + ks * 8 + t;
    float x0 = X[base];
    float x1 = X[base + 4];
    float2 h, l;
    h.x = tf32r(x0); l.x = tf32r(x0 - h.x);
    h.y = tf32r(x1); l.y = tf32r(x1 - h.y);
    Phi[(size_t)atom * 32 + lane] = h;
    Plo[(size_t)atom * 32 + lane] = l;
}

// ------- fused S pack: A-format hi/lo + B-format hi (B lo unused) ------------
__global__ __launch_bounds__(256) void split_pack_s(
    const float* __restrict__ X,
    float4* __restrict__ Ahi, float4* __restrict__ Alo,
    float2* __restrict__ Bhi) {
    const int atom = blockIdx.x * 8 + (threadIdx.x >> 5);
    const int lane = threadIdx.x & 31;
    const int mt = atom >> 7;
    const int ks = atom & 127;
    const int g = lane >> 2, t = lane & 3;
    const size_t r0 = (size_t)(mt * 16 + g) * DIM + ks * 8 + t;
    const size_t r1 = r0 + 8 * DIM;
    float x0 = X[r0], x1 = X[r1], x2 = X[r0 + 4], x3 = X[r1 + 4];
    float4 h, l;
    h.x = tf32r(x0); l.x = tf32r(x0 - h.x);
    h.y = tf32r(x1); l.y = tf32r(x1 - h.y);
    h.z = tf32r(x2); l.z = tf32r(x2 - h.z);
    h.w = tf32r(x3); l.w = tf32r(x3 - h.w);
    Ahi[(size_t)atom * 32 + lane] = h;
    Alo[(size_t)atom * 32 + lane] = l;
    const size_t b0 = ((size_t)(2 * mt) * KS8 + ks) * 32 + lane;
    const size_t b1 = b0 + (size_t)KS8 * 32;
    Bhi[b0] = make_float2(h.x, h.z);
    Bhi[b1] = make_float2(h.y, h.w);
}

// ---------------- bvo = bv @ Wo + bo ----------------------------------------
__global__ __launch_bounds__(128) void bvo_kernel(
    const float* __restrict__ bv, const float* __restrict__ Wo,
    const float* __restrict__ bo, float* __restrict__ bvo) {
    const int n = blockIdx.x * 128 + threadIdx.x;
    float acc = bo[n];
    for (int k = 0; k < DIM; k++) acc += bv[k] * Wo[(size_t)k * DIM + n];
    bvo[n] = acc;
}

// ---------------- y[d] = Wk[d,:] . bq ----------------------------------------
__global__ __launch_bounds__(256) void ydot_kernel(
    const float* __restrict__ Wk, const float* __restrict__ bq,
    float* __restrict__ y) {
    const int wid = threadIdx.x >> 5, lane = threadIdx.x & 31;
    const int row = blockIdx.x * 8 + wid;
    const float4* r4 = (const float4*)(Wk + (size_t)row * DIM);
    const float4* b4 = (const float4*)bq;
    float acc = 0.f;
    for (int i = lane; i < DIM / 4; i += 32) {
        float4 a = r4[i], b = b4[i];
        acc += a.x * b.x + a.y * b.y + a.z * b.z + a.w * b.w;
    }
#pragma unroll
    for (int o = 16; o; o >>= 1) acc += __shfl_xor_sync(0xffffffffu, acc, o);
    if (lane == 0) y[row] = acc;
}

// ---------------- w[m] = (S[m,:] . y) / 32 -----------------------------------
__global__ __launch_bounds__(256) void wdot_kernel(
    const float* __restrict__ S, const float* __restrict__ y,
    float* __restrict__ w) {
    const int wid = threadIdx.x >> 5, lane = threadIdx.x & 31;
    const int row = blockIdx.x * 8 + wid;
    const float4* r4 = (const float4*)(S + (size_t)row * DIM);
    const float4* y4 = (const float4*)y;
    float acc = 0.f;
    for (int i = lane; i < DIM / 4; i += 32) {
        float4 a = r4[i], b = y4[i];
        acc += a.x * b.x + a.y * b.y + a.z * b.z + a.w * b.w;
    }
#pragma unroll
    for (int o = 16; o; o >>= 1) acc += __shfl_xor_sync(0xffffffffu, acc, o);
    if (lane == 0) w[row] = acc * 0.03125f;
}

// ---------- shared TF32 mainloop (256x128 tile, BK=16), MODE in {1,2,3} -----
// MODE 3: hi*hi + hi*lo + lo*hi.  MODE 2: hi*hi + lo*hi.  MODE 1: hi*hi only.
#define GEMM_SMEM (3 * 12288 * 4)

template <int MODE>
__device__ __forceinline__ void mma_mainloop(
    float* sm, const float* __restrict__ Ahi, const float* __restrict__ Alo,
    const float* __restrict__ Bhi, const float* __restrict__ Blo,
    int br16, int bn16, int kc0, int iters, float4 (&acc)[4][8]) {
    const int tid = threadIdx.x;
    const int lane = tid & 31, wid = tid >> 5;
    const int wy = wid >> 1, wx = wid & 1;
    const uint32_t smb = smem_u32(sm);

    auto load_stage = [&](int kc, int s) {
        const uint32_t sb = smb + s * 49152;
#pragma unroll
        for (int j = 0; j < 4; j++) {
            const int cA = tid + j * 256;
            const int mtl = cA >> 6, off = cA & 63;
            const uint32_t so = sb + (uint32_t)(mtl * 256 + off * 4) * 4;
            const size_t go = ((size_t)(br16 + mtl) * KS8 + kc * 2) * 128 + off * 4;
            cpasync16(so, Ahi + go);
            if (MODE >= 2) cpasync16(so + 4096 * 4, Alo + go);
        }
#pragma unroll
        for (int j = 0; j < 2; j++) {
            const int cB = tid + j * 256;
            const int ntl = cB >> 5, off = cB & 31;
            const uint32_t so = sb + (uint32_t)(8192 + ntl * 128 + off * 4) * 4;
            const size_t go = ((size_t)(bn16 + ntl) * KS8 + kc * 2) * 64 + off * 4;
            cpasync16(so, Bhi + go);
            if (MODE >= 3) cpasync16(so + 2048 * 4, Blo + go);
        }
    };

    load_stage(kc0, 0); CP_COMMIT();
    load_stage(kc0 + 1, 1); CP_COMMIT();

#pragma unroll
    for (int i = 0; i < 4; i++)
#pragma unroll
        for (int j = 0; j < 8; j++) acc[i][j] = make_float4(0.f, 0.f, 0.f, 0.f);

    for (int c = 0; c < iters; c++) {
        if (c < iters - 2) { CP_WAIT_1(); } else { CP_WAIT_0(); }
        __syncthreads();
        if (c + 2 < iters) { load_stage(kc0 + c + 2, (c + 2) % 3); CP_COMMIT(); }
        const float* st = sm + (c % 3) * 12288;
#pragma unroll
        for (int ks = 0; ks < 2; ks++) {
            uint4 Ah[4], Al[4];
            uint2 Bh[8], Bl[8];
#pragma unroll
            for (int i = 0; i < 4; i++) {
                const float* p = st + ((wy * 4 + i) * 2 + ks) * 128 + lane * 4;
                Ah[i] = *(const uint4*)p;
                if (MODE >= 2) Al[i] = *(const uint4*)(p + 4096);
            }
#pragma unroll
            for (int j = 0; j < 8; j++) {
                const float* p = st + 8192 + ((wx * 8 + j) * 2 + ks) * 64 + lane * 2;
                Bh[j] = *(const uint2*)p;
                if (MODE >= 3) Bl[j] = *(const uint2*)(p + 2048);
            }
#pragma unroll
            for (int i = 0; i < 4; i++)
#pragma unroll
                for (int j = 0; j < 8; j++) {
                    mma8(acc[i][j], Ah[i], Bh[j]);
                    if (MODE >= 3) mma8(acc[i][j], Ah[i], Bl[j]);
                    if (MODE >= 2) mma8(acc[i][j], Al[i], Bh[j]);
                }
        }
    }
}

// --------- fused prep GEMMs: Wvo = Wv@Wo and G = Wq@Wk^T, split-K x2 --------
__global__ __launch_bounds__(256, 1) void gemm_prep_kernel(
    const float* __restrict__ Ahi, const float* __restrict__ Alo,
    const float* __restrict__ Bhi, const float* __restrict__ Blo,
    float* __restrict__ P) {
    extern __shared__ float sm[];
    const int wsel = blockIdx.z >> 1;
    const int khalf = blockIdx.z & 1;
    const int tid = threadIdx.x;
    const int lane = tid & 31, wid = tid >> 5;
    const int wy = wid >> 1, wx = wid & 1;
    const int g = lane >> 2, t = lane & 3;
    const int m0 = blockIdx.y * 256, n0 = blockIdx.x * 128;

    float4 acc[4][8];
    mma_mainloop<3>(sm, Ahi, Alo, Bhi, Blo,
                    wsel * 64 + blockIdx.y * 16, wsel * 128 + blockIdx.x * 16,
                    khalf * 32, 32, acc);

    float* out = P + (size_t)(wsel * 2 + khalf) * DIM * DIM;
#pragma unroll
    for (int i = 0; i < 4; i++) {
        const int r0 = m0 + wy * 64 + i * 16 + g;
#pragma unroll
        for (int j = 0; j < 8; j++) {
            const int col = n0 + wx * 64 + j * 8 + t * 2;
            *(float2*)(out + (size_t)r0 * DIM + col) =
                make_float2(acc[i][j].x, acc[i][j].y);
            *(float2*)(out + (size_t)(r0 + 8) * DIM + col) =
                make_float2(acc[i][j].z, acc[i][j].w);
        }
    }
}

// --------- sum split-K partials + pack B-format into weight slots ------------
__global__ __launch_bounds__(256) void prep_pack_sum(
    const float* __restrict__ P, float2* __restrict__ WHi, float2* __restrict__ WLo) {
    const int bx = blockIdx.x;
    const int w = bx >> 11;
    const float* p0 = P + (size_t)(w == 0 ? 2 : 0) * DIM * DIM;
    const float* p1 = p0 + (size_t)DIM * DIM;
    float2* dhi = WHi + (size_t)w * WSZF / 2;
    float2* dlo = WLo + (size_t)w * WSZF / 2;
    const int atom = (bx & 2047) * 8 + (threadIdx.x >> 5);
    const int lane = threadIdx.x & 31;
    const int nt = atom >> 7;
    const int ks = atom & 127;
    const int g = lane >> 2, t = lane & 3;
    const size_t i0 = (size_t)(ks * 8 + t) * DIM + nt * 8 + g;
    const size_t i1 = (size_t)(ks * 8 + t + 4) * DIM + nt * 8 + g;
    float x0 = p0[i0] + p1[i0];
    float x1 = p0[i1] + p1[i1];
    float2 h, l;
    h.x = tf32r(x0); l.x = tf32r(x0 - h.x);
    h.y = tf32r(x1); l.y = tf32r(x1 - h.y);
    dhi[(size_t)atom * 32 + lane] = h;
    dlo[(size_t)atom * 32 + lane] = l;
}

// Fused T/U projection. wsel 0 -> T = S@G (3x): packed A-fmt hi + raw.
// wsel 1 -> U = S@Wvo (2x): raw.
__global__ __launch_bounds__(256, 1) void gemm_tu_kernel(
    const float* __restrict__ Ahi, const float* __restrict__ Alo,
    const float* __restrict__ Whi, const float* __restrict__ Wlo,
    float* __restrict__ Thi, float* __restrict__ Traw, float* __restrict__ U) {
    extern __shared__ float sm[];
    const int wsel = blockIdx.x & 1;
    const int nxt = blockIdx.x >> 1;
    const int tid = threadIdx.x;
    const int lane = tid & 31, wid = tid >> 5;
    const int wy = wid >> 1, wx = wid & 1;
    const int g = lane >> 2, t = lane & 3;
    const int m0 = blockIdx.y * 256, n0 = nxt * 128;

    if (wsel == 1) {
        float4 acc[4][8];
        mma_mainloop<2>(sm, Ahi, Alo, Whi + WSZF, Wlo + WSZF,
                        blockIdx.y * 16, nxt * 16, 0, 64, acc);
#pragma unroll
        for (int i = 0; i < 4; i++) {
            const int r0 = m0 + wy * 64 + i * 16 + g;
#pragma unroll
            for (int j = 0; j < 8; j++) {
                const int col = n0 + wx * 64 + j * 8 + t * 2;
                *(float2*)(U + (size_t)r0 * DIM + col) =
                    make_float2(acc[i][j].x, acc[i][j].y);
                *(float2*)(U + (size_t)(r0 + 8) * DIM + col) =
                    make_float2(acc[i][j].z, acc[i][j].w);
            }
        }
        return;
    }

    float4 acc[4][8];
    mma_mainloop<3>(sm, Ahi, Alo, Whi, Wlo,
                    blockIdx.y * 16, nxt * 16, 0, 64, acc);

    // raw T write (for exact rescore)
#pragma unroll
    for (int i = 0; i < 4; i++) {
        const int r0 = m0 + wy * 64 + i * 16 + g;
#pragma unroll
        for (int j = 0; j < 8; j++) {
            const int col = n0 + wx * 64 + j * 8 + t * 2;
            *(float2*)(Traw + (size_t)r0 * DIM + col) =
                make_float2(acc[i][j].x, acc[i][j].y);
            *(float2*)(Traw + (size_t)(r0 + 8) * DIM + col) =
                make_float2(acc[i][j].z, acc[i][j].w);
        }
    }

    __syncthreads();  // pipeline smem free
#pragma unroll
    for (int i = 0; i < 4; i++) {
        const int r0 = wy * 64 + i * 16 + g;
#pragma unroll
        for (int j = 0; j < 8; j++) {
            const int col = wx * 64 + j * 8 + t * 2;
            *(float2*)&sm[r0 * 132 + col] = make_float2(acc[i][j].x, acc[i][j].y);
            *(float2*)&sm[(r0 + 8) * 132 + col] = make_float2(acc[i][j].z, acc[i][j].w);
        }
    }
    __syncthreads();

    // pack Thi (A-format hi only; scores pass is 1x)
    for (int a = wid; a < 256; a += 8) {
        const int amt = a >> 4, aks = a & 15;
        const float* bp = sm + (amt * 16 + g) * 132 + aks * 8 + t;
        float4 h;
        h.x = tf32r(bp[0]);
        h.y = tf32r(bp[8 * 132]);
        h.z = tf32r(bp[4]);
        h.w = tf32r(bp[8 * 132 + 4]);
        const size_t atom = (size_t)(blockIdx.y * 16 + amt) * KS8 + (nxt * 16 + aks);
        ((float4*)Thi)[atom * 32 + lane] = h;
    }
}

// ---------------- supertile 1x TF32 causal scores + candidate top-8 ---------
// Pass 1: scores ~= Thi.Shi/32 + w (1x). Candidates only; exact rescore later.
#define SSC_SMEM ((3 * 12288 + 128 * 72 + 256 * 8 + 256 * 8 + 128) * 4)

__global__ __launch_bounds__(256, 1) void scores_super_kernel(
    const float* __restrict__ Thi, const float* __restrict__ Shi,
    const float* __restrict__ w,
    float* __restrict__ pval, int* __restrict__ pidx) {
    extern __shared__ float sm[];
    float* sc = sm + 36864;
    float* tval = sm + 46080;
    int* tidx = (int*)(sm + 48128);
    float* wsc = sm + 50176;

    const int tid = threadIdx.x;
    const int lane = tid & 31, wid = tid >> 5;
    const int wy = wid >> 1, wx = wid & 1;
    const int g = lane >> 2, t = lane & 3;
    const int b = blockIdx.y;
    const int bidx = blockIdx.x;

    int sq = (int)((sqrtf(4.0f * (float)bidx + 1.0f) - 1.0f) * 0.5f);
    while ((sq + 1) * (sq + 2) <= bidx) sq++;
    while (sq * (sq + 1) > bidx) sq--;
    const int kt = bidx - sq * (sq + 1);
    const int q0 = sq * 256, k0 = kt * 128;

    for (int i = tid; i < 256 * TOPK; i += 256) {
        tval[i] = -INFINITY;
        tidx[i] = 0;
    }
    if (tid < 128) wsc[tid] = w[b * NSEQ + k0 + tid];

    float4 acc[4][8];
    mma_mainloop<1>(sm, Thi, (const float*)0, Shi, (const float*)0,
                    b * 256 + sq * 16, b * 512 + kt * 16, 0, 64, acc);

#pragma unroll
    for (int rh = 0; rh < 2; rh++) {
#pragma unroll
        for (int h = 0; h < 2; h++) {
            if ((wy >> 1) == rh && wx == h) {
#pragma unroll
                for (int i = 0; i < 4; i++) {
                    const int rl = wy * 64 + i * 16 + g;
                    const int srow = rl - rh * 128;
#pragma unroll
                    for (int j = 0; j < 8; j++) {
                        const int col = j * 8 + t * 2;
                        const int lc = h * 64 + col;
                        const int gc = k0 + lc;
                        const int gr0 = q0 + rl, gr1 = gr0 + 8;
                        const float w0 = wsc[lc], w1 = wsc[lc + 1];
                        float v0 = acc[i][j].x * 0.03125f + w0;
                        float v1 = acc[i][j].y * 0.03125f + w1;
                        float v2 = acc[i][j].z * 0.03125f + w0;
                        float v3 = acc[i][j].w * 0.03125f + w1;
                        if (gc + 0 > gr0) v0 = -INFINITY;
                        if (gc + 1 > gr0) v1 = -INFINITY;
                        if (gc + 0 > gr1) v2 = -INFINITY;
                        if (gc + 1 > gr1) v3 = -INFINITY;
                        *(float2*)&sc[srow * 72 + col] = make_float2(v0, v1);
                        *(float2*)&sc[(srow + 8) * 72 + col] = make_float2(v2, v3);
                    }
                }
            }
            __syncthreads();
            if (tid < 128) {
                const int row = rh * 128 + tid;
                float tv[TOPK]; int ti[TOPK];
#pragma unroll
                for (int j = 0; j < TOPK; j++) { tv[j] = tval[row * 8 + j]; ti[j] = tidx[row * 8 + j]; }
                float vmin = tv[0]; int mpos = 0;
#pragma unroll
                for (int j = 1; j < TOPK; j++) if (tv[j] < vmin) { vmin = tv[j]; mpos = j; }
                const int cbase = k0 + h * 64;
                for (int cc = 0; cc < 64; cc++) {
                    const float vv = sc[tid * 72 + cc];
                    if (vv > vmin) {
                        tv[mpos] = vv; ti[mpos] = cbase + cc;
                        vmin = tv[0]; mpos = 0;
#pragma unroll
                        for (int j = 1; j < TOPK; j++) if (tv[j] < vmin) { vmin = tv[j]; mpos = j; }
                    }
                }
#pragma unroll
                for (int j = 0; j < TOPK; j++) { tval[row * 8 + j] = tv[j]; tidx[row * 8 + j] = ti[j]; }
            }
            __syncthreads();
        }
    }

    const size_t base = (((size_t)b * NSB + bidx) * 256 + tid) * TOPK;
#pragma unroll
    for (int j = 0; j < TOPK; j++) {
        pval[base + j] = tval[tid * 8 + j];
        pidx[base + j] = tidx[tid * 8 + j];
    }
}

// ------- merge top-16 (1x) -> exact rescore -> top-8 softmax -> gather -------
__global__ __launch_bounds__(128) void merge_rescore_gather(
    const float* __restrict__ pv, const int* __restrict__ pi,
    const float* __restrict__ Traw, const float* __restrict__ S,
    const float* __restrict__ w, const float* __restrict__ U,
    const float* __restrict__ bvo, float* __restrict__ out) {
    const int row = blockIdx.x;
    const int b = row >> 12, rr = row & 4095;
    const int qt = rr >> 7;
    const int sq = qt >> 1;
    const int rib = rr - sq * 256;
    const size_t sbase = ((size_t)b * NSB + (size_t)sq * (sq + 1)) * 256 + rib;

    __shared__ float trow[DIM];
    __shared__ float cval[NCAND];
    __shared__ int   cidx[NCAND];
    __shared__ float cex[NCAND];
    __shared__ float ps[TOPK];
    __shared__ int   ids[TOPK];

    const int tid = threadIdx.x;
    const int lane = tid & 31, wid = tid >> 5;

    // load T row to smem
    {
        const float4* tr = (const float4*)(Traw + (size_t)row * DIM);
        ((float4*)trow)[tid] = tr[tid];
        ((float4*)trow)[tid + 128] = tr[tid + 128];
    }

    // warp 0: merge partial lists to top-NCAND by 1x value
    if (tid < 32) {
        float v[TOPK]; int id8[TOPK];
        if (lane <= qt) {
            const size_t base = (sbase + (size_t)lane * 256) * TOPK;
#pragma unroll
            for (int j = 0; j < TOPK; j++) { v[j] = pv[base + j]; id8[j] = pi[base + j]; }
        } else {
#pragma unroll
            for (int j = 0; j < TOPK; j++) { v[j] = -INFINITY; id8[j] = 0; }
        }
#pragma unroll
        for (int r = 0; r < NCAND; r++) {
            float lm = v[0]; int ls = 0;
#pragma unroll
            for (int j = 1; j < TOPK; j++) if (v[j] > lm) { lm = v[j]; ls = j; }
            float m = lm; int who = lane;
#pragma unroll
            for (int o = 16; o; o >>= 1) {
                float om = __shfl_xor_sync(0xffffffffu, m, o);
                int ow = __shfl_xor_sync(0xffffffffu, who, o);
                if (om > m || (om == m && ow < who)) { m = om; who = ow; }
            }
            int widx = 0;
#pragma unroll
            for (int j = 0; j < TOPK; j++) if (j == ls) widx = id8[j];
            const int gidx = __shfl_sync(0xffffffffu, widx, who);
            if (lane == 0) { cval[r] = m; cidx[r] = gidx; }
            if (lane == who) {
#pragma unroll
                for (int j = 0; j < TOPK; j++) if (j == ls) v[j] = -INFINITY;
            }
        }
    }
    __syncthreads();

    // rescore candidates exactly: each warp handles NCAND/4 candidates
    for (int c = wid; c < NCAND; c += 4) {
        const float v1 = cval[c];
        const int idx = cidx[c];
        float acc = 0.f;
        if (v1 != -INFINITY) {
            const float4* srow = (const float4*)(S + ((size_t)b * NSEQ + idx) * DIM);
            const float4* tr4 = (const float4*)trow;
            for (int i = lane; i < DIM / 4; i += 32) {
                float4 s = srow[i], tt = tr4[i];
                acc += tt.x * s.x + tt.y * s.y + tt.z * s.z + tt.w * s.w;
            }
        }
#pragma unroll
        for (int o = 16; o; o >>= 1) acc += __shfl_xor_sync(0xffffffffu, acc, o);
        if (lane == 0)
            cex[c] = (v1 != -INFINITY)
                         ? acc * 0.03125f + w[b * NSEQ + idx]
                         : -INFINITY;
    }
    __syncthreads();

    // thread 0: exact top-8 of NCAND + softmax
    if (tid == 0) {
        float ev[NCAND]; int ei[NCAND];
#pragma unroll
        for (int j = 0; j < NCAND; j++) { ev[j] = cex[j]; ei[j] = cidx[j]; }
        float tv[TOPK]; int ti[TOPK];
#pragma unroll
        for (int r = 0; r < TOPK; r++) {
            int m = 0; float best = ev[0];
#pragma unroll
            for (int j = 1; j < NCAND; j++) if (ev[j] > best) { best = ev[j]; m = j; }
            tv[r] = best; ti[r] = ei[m]; ev[m] = -INFINITY;
        }
        float mx = tv[0];
#pragma unroll
        for (int j = 1; j < TOPK; j++) mx = fmaxf(mx, tv[j]);
        float e[TOPK]; float ssum = 0.f;
#pragma unroll
        for (int j = 0; j < TOPK; j++) { e[j] = expf(tv[j] - mx); ssum += e[j]; }
        const float inv = 1.f / ssum;
#pragma unroll
        for (int j = 0; j < TOPK; j++) { ps[j] = e[j] * inv; ids[j] = ti[j]; }
    }
    __syncthreads();

    const float* ub = U + (size_t)b * NSEQ * DIM;
    const int c = tid * 8;
    float4 a0 = *(const float4*)(bvo + c);
    float4 a1 = *(const float4*)(bvo + c + 4);
#pragma unroll
    for (int j = 0; j < TOPK; j++) {
        const float4* vr = (const float4*)(ub + (size_t)ids[j] * DIM + c);
        const float pj = ps[j];
        float4 v0 = vr[0], v1 = vr[1];
        a0.x += pj * v0.x; a0.y += pj * v0.y; a0.z += pj * v0.z; a0.w += pj * v0.w;
        a1.x += pj * v1.x; a1.y += pj * v1.y; a1.z += pj * v1.z; a1.w += pj * v1.w;
    }
    float4* orow = (float4*)(out + (size_t)row * DIM + c);
    orow[0] = a0; orow[1] = a1;
}

// ---------------- launch -----------------------------------------------------
extern "C" void kernel_launch(void* const* d_in, const int* in_sizes, int n_in,
                              void* d_out, int out_size) {
    const float* S  = (const float*)d_in[0];
    const float* Wq = (const float*)d_in[1];
    const float* bq = (const float*)d_in[2];
    const float* Wk = (const float*)d_in[3];
    const float* bk = (const float*)d_in[4];  // row-const in softmax; drops out
    const float* Wv = (const float*)d_in[5];
    const float* bv = (const float*)d_in[6];
    const float* Wo = (const float*)d_in[7];
    const float* bo = (const float*)d_in[8];
    float* out = (float*)d_out;
    (void)bk;

    float *up, *trp, *pvp, *ahip, *alop;
    float *qhip, *khip, *klop, *wthip, *wtlop;
    float *bvop, *yp, *wp;
    int *pip;
    cudaGetSymbolAddress((void**)&up, g_u);
    cudaGetSymbolAddress((void**)&trp, g_traw);
    cudaGetSymbolAddress((void**)&pvp, g_pval);
    cudaGetSymbolAddress((void**)&pip, g_pidx);
    cudaGetSymbolAddress((void**)&ahip, g_ahi);
    cudaGetSymbolAddress((void**)&alop, g_alo);
    cudaGetSymbolAddress((void**)&qhip, g_qhi);
    cudaGetSymbolAddress((void**)&khip, g_khi);
    cudaGetSymbolAddress((void**)&klop, g_klo);
    cudaGetSymbolAddress((void**)&wthip, g_wthi);
    cudaGetSymbolAddress((void**)&wtlop, g_wtlo);
    cudaGetSymbolAddress((void**)&bvop, g_bvo);
    cudaGetSymbolAddress((void**)&yp, g_y);
    cudaGetSymbolAddress((void**)&wp, g_w);

    cudaFuncSetAttribute(gemm_prep_kernel,
                         cudaFuncAttributeMaxDynamicSharedMemorySize, GEMM_SMEM);
    cudaFuncSetAttribute(gemm_tu_kernel,
                         cudaFuncAttributeMaxDynamicSharedMemorySize, GEMM_SMEM);
    cudaFuncSetAttribute(scores_super_kernel,
                         cudaFuncAttributeMaxDynamicSharedMemorySize, SSC_SMEM);

    const int WPACK_GRID = (DIM / 8) * KS8 / 8;   // 2048
    const int APACK_1K = (DIM / 16) * KS8 / 8;    // 1024

    // operand packs for prep: A buffer = [Wv | Wq], B buffer = [Wo | Wk]
    split_pack_a<<<APACK_1K, 256>>>(Wv, (float4*)ahip, (float4*)alop);
    split_pack_a<<<APACK_1K, 256>>>(Wq,
        (float4*)ahip + (size_t)8192 * 32, (float4*)alop + (size_t)8192 * 32);
    split_pack_w<<<WPACK_GRID, 256>>>(Wo, (float2*)khip, (float2*)klop);
    split_pack_kb<<<WPACK_GRID, 256>>>(Wk,
        (float2*)khip + (size_t)16384 * 32, (float2*)klop + (size_t)16384 * 32);

    // bias folds
    bvo_kernel<<<DIM / 128, 128>>>(bv, Wo, bo, bvop);
    ydot_kernel<<<DIM / 8, 256>>>(Wk, bq, yp);
    wdot_kernel<<<MROWS / 8, 256>>>(S, yp, wp);

    // fused prep GEMMs (split-K x2) + partial-sum pack
    gemm_prep_kernel<<<dim3(8, 4, 4), 256, GEMM_SMEM>>>(ahip, alop, khip, klop, up);
    prep_pack_sum<<<4096, 256>>>(up, (float2*)wthip, (float2*)wtlop);

    // fused S pack: A-fmt hi/lo + B-fmt hi
    split_pack_s<<<(MROWS / 16) * KS8 / 8, 256>>>(
        S, (float4*)ahip, (float4*)alop, (float2*)khip);

    // fused: T = S@G (3x, Thi packed + raw), U = S@Wvo (2x, raw)
    gemm_tu_kernel<<<dim3(16, MROWS / 256), 256, GEMM_SMEM>>>(
        ahip, alop, wthip, wtlop, qhip, trp, up);

    // pass 1: 1x scores -> per-tile candidate top-8
    scores_super_kernel<<<dim3(NSB, BSZ), 256, SSC_SMEM>>>(
        qhip, khip, wp, pvp, pip);
    // pass 2: merge top-16, exact rescore, softmax, gather
    merge_rescore_gather<<<MROWS, 128>>>(pvp, pip, trp, S, wp, up, bvop, out);
}

// round 16
// speedup vs baseline: 4.5390x; 1.0897x over previous
#include <cuda_runtime.h>
#include <math.h>
#include <stdint.h>

#define BSZ   4
#define NSEQ  4096
#define DIM   1024
#define TOPK  8
#define NCAND 16
#define MROWS (BSZ * NSEQ)
#define KS8   (DIM / 8)
#define NSB   272
#define WSZF  ((size_t)DIM * DIM)

typedef unsigned long long ULL;

// ---------------- scratch (__device__ globals; no allocation allowed) -------
__device__ __align__(128) float g_u[(size_t)MROWS * DIM];     // prep partials, then U
__device__ __align__(128) float g_traw[(size_t)MROWS * DIM];  // raw T (rescore)
__device__ float g_pval[(size_t)BSZ * NSB * 256 * TOPK];
__device__ int   g_pidx[(size_t)BSZ * NSB * 256 * TOPK];
__device__ float g_bvo[DIM];
__device__ float g_y[DIM];
__device__ float g_w[MROWS];
__device__ __align__(128) float g_ahi[(size_t)MROWS * DIM];
__device__ __align__(128) float g_alo[(size_t)MROWS * DIM];
__device__ __align__(128) float g_qhi[(size_t)MROWS * DIM];   // A-fmt Thi
__device__ __align__(128) float g_khi[(size_t)MROWS * DIM];   // B-fmt (Wo/Wk then S hi)
__device__ __align__(128) float g_klo[(size_t)MROWS * DIM];   // B-fmt lo (prep only)
__device__ __align__(128) float g_wthi[2][WSZF];              // slot0 G, slot1 Wvo
__device__ __align__(128) float g_wtlo[2][WSZF];

// ---------------- helpers -----------------------------------------------------
__device__ __forceinline__ uint32_t smem_u32(const void* p) {
    uint32_t a;
    asm("{ .reg .u64 t; cvta.to.shared.u64 t, %1; cvt.u32.u64 %0, t; }"
        : "=r"(a) : "l"(p));
    return a;
}
__device__ __forceinline__ float tf32r(float x) {
    uint32_t u;
    asm("cvt.rna.tf32.f32 %0, %1;" : "=r"(u) : "f"(x));
    return __uint_as_float(u);
}
__device__ __forceinline__ void cpasync16(uint32_t saddr, const void* g) {
    asm volatile("cp.async.cg.shared.global [%0], [%1], 16;"
                 :: "r"(saddr), "l"(g));
}
#define CP_COMMIT() asm volatile("cp.async.commit_group;" ::: "memory")
#define CP_WAIT_1() asm volatile("cp.async.wait_group 1;" ::: "memory")
#define CP_WAIT_0() asm volatile("cp.async.wait_group 0;" ::: "memory")

__device__ __forceinline__ void mma8(float4& c, const uint4& a, const uint2& b) {
    asm volatile(
        "mma.sync.aligned.m16n8k8.row.col.f32.tf32.tf32.f32 "
        "{%0,%1,%2,%3}, {%4,%5,%6,%7}, {%8,%9}, {%0,%1,%2,%3};"
        : "+f"(c.x), "+f"(c.y), "+f"(c.z), "+f"(c.w)
        : "r"(a.x), "r"(a.y), "r"(a.z), "r"(a.w), "r"(b.x), "r"(b.y));
}

// ---------------- split+pack A-format: X[M,K] row-major ---------------------
__global__ __launch_bounds__(256) void split_pack_a(
    const float* __restrict__ X, float4* __restrict__ Phi, float4* __restrict__ Plo) {
    const int atom = blockIdx.x * 8 + (threadIdx.x >> 5);
    const int lane = threadIdx.x & 31;
    const int mt = atom >> 7;
    const int ks = atom & 127;
    const int g = lane >> 2, t = lane & 3;
    const size_t r0 = (size_t)(mt * 16 + g) * DIM + ks * 8 + t;
    const size_t r1 = r0 + 8 * DIM;
    float x0 = X[r0], x1 = X[r1], x2 = X[r0 + 4], x3 = X[r1 + 4];
    float4 h, l;
    h.x = tf32r(x0); l.x = tf32r(x0 - h.x);
    h.y = tf32r(x1); l.y = tf32r(x1 - h.y);
    h.z = tf32r(x2); l.z = tf32r(x2 - h.z);
    h.w = tf32r(x3); l.w = tf32r(x3 - h.w);
    Phi[(size_t)atom * 32 + lane] = h;
    Plo[(size_t)atom * 32 + lane] = l;
}

// ---------------- split+pack W (B-format) ------------------------------------
__global__ __launch_bounds__(256) void split_pack_w(
    const float* __restrict__ W, float2* __restrict__ Phi, float2* __restrict__ Plo) {
    const int atom = blockIdx.x * 8 + (threadIdx.x >> 5);
    const int lane = threadIdx.x & 31;
    const int nt = atom >> 7;
    const int ks = atom & 127;
    const int g = lane >> 2, t = lane & 3;
    float x0 = W[(size_t)(ks * 8 + t) * DIM + nt * 8 + g];
    float x1 = W[(size_t)(ks * 8 + t + 4) * DIM + nt * 8 + g];
    float2 h, l;
    h.x = tf32r(x0); l.x = tf32r(x0 - h.x);
    h.y = tf32r(x1); l.y = tf32r(x1 - h.y);
    Phi[(size_t)atom * 32 + lane] = h;
    Plo[(size_t)atom * 32 + lane] = l;
}

// ---------------- split+pack row-major [N,K] -> B-format ---------------------
__global__ __launch_bounds__(256) void split_pack_kb(
    const float* __restrict__ X, float2* __restrict__ Phi, float2* __restrict__ Plo) {
    const int atom = blockIdx.x * 8 + (threadIdx.x >> 5);
    const int lane = threadIdx.x & 31;
    const int nt = atom >> 7;
    const int ks = atom & 127;
    const int g = lane >> 2, t = lane & 3;
    const size_t base = (size_t)(nt * 8 + g) * DIM + ks * 8 + t;
    float x0 = X[base];
    float x1 = X[base + 4];
    float2 h, l;
    h.x = tf32r(x0); l.x = tf32r(x0 - h.x);
    h.y = tf32r(x1); l.y = tf32r(x1 - h.y);
    Phi[(size_t)atom * 32 + lane] = h;
    Plo[(size_t)atom * 32 + lane] = l;
}

// ------- fused S pack: A-format hi/lo + B-format hi (B lo unused) ------------
__global__ __launch_bounds__(256) void split_pack_s(
    const float* __restrict__ X,
    float4* __restrict__ Ahi, float4* __restrict__ Alo,
    float2* __restrict__ Bhi) {
    const int atom = blockIdx.x * 8 + (threadIdx.x >> 5);
    const int lane = threadIdx.x & 31;
    const int mt = atom >> 7;
    const int ks = atom & 127;
    const int g = lane >> 2, t = lane & 3;
    const size_t r0 = (size_t)(mt * 16 + g) * DIM + ks * 8 + t;
    const size_t r1 = r0 + 8 * DIM;
    float x0 = X[r0], x1 = X[r1], x2 = X[r0 + 4], x3 = X[r1 + 4];
    float4 h, l;
    h.x = tf32r(x0); l.x = tf32r(x0 - h.x);
    h.y = tf32r(x1); l.y = tf32r(x1 - h.y);
    h.z = tf32r(x2); l.z = tf32r(x2 - h.z);
    h.w = tf32r(x3); l.w = tf32r(x3 - h.w);
    Ahi[(size_t)atom * 32 + lane] = h;
    Alo[(size_t)atom * 32 + lane] = l;
    const size_t b0 = ((size_t)(2 * mt) * KS8 + ks) * 32 + lane;
    const size_t b1 = b0 + (size_t)KS8 * 32;
    Bhi[b0] = make_float2(h.x, h.z);
    Bhi[b1] = make_float2(h.y, h.w);
}

// ---------------- bvo = bv @ Wo + bo ----------------------------------------
__global__ __launch_bounds__(128) void bvo_kernel(
    const float* __restrict__ bv, const float* __restrict__ Wo,
    const float* __restrict__ bo, float* __restrict__ bvo) {
    const int n = blockIdx.x * 128 + threadIdx.x;
    float acc = bo[n];
    for (int k = 0; k < DIM; k++) acc += bv[k] * Wo[(size_t)k * DIM + n];
    bvo[n] = acc;
}

// ---------------- y[d] = Wk[d,:] . bq ----------------------------------------
__global__ __launch_bounds__(256) void ydot_kernel(
    const float* __restrict__ Wk, const float* __restrict__ bq,
    float* __restrict__ y) {
    const int wid = threadIdx.x >> 5, lane = threadIdx.x & 31;
    const int row = blockIdx.x * 8 + wid;
    const float4* r4 = (const float4*)(Wk + (size_t)row * DIM);
    const float4* b4 = (const float4*)bq;
    float acc = 0.f;
    for (int i = lane; i < DIM / 4; i += 32) {
        float4 a = r4[i], b = b4[i];
        acc += a.x * b.x + a.y * b.y + a.z * b.z + a.w * b.w;
    }
#pragma unroll
    for (int o = 16; o; o >>= 1) acc += __shfl_xor_sync(0xffffffffu, acc, o);
    if (lane == 0) y[row] = acc;
}

// ---------------- w[m] = (S[m,:] . y) / 32 -----------------------------------
__global__ __launch_bounds__(256) void wdot_kernel(
    const float* __restrict__ S, const float* __restrict__ y,
    float* __restrict__ w) {
    const int wid = threadIdx.x >> 5, lane = threadIdx.x & 31;
    const int row = blockIdx.x * 8 + wid;
    const float4* r4 = (const float4*)(S + (size_t)row * DIM);
    const float4* y4 = (const float4*)y;
    float acc = 0.f;
    for (int i = lane; i < DIM / 4; i += 32) {
        float4 a = r4[i], b = y4[i];
        acc += a.x * b.x + a.y * b.y + a.z * b.z + a.w * b.w;
    }
#pragma unroll
    for (int o = 16; o; o >>= 1) acc += __shfl_xor_sync(0xffffffffu, acc, o);
    if (lane == 0) w[row] = acc * 0.03125f;
}

// ---------- shared TF32 mainloop (256x128 tile, BK=16), MODE in {1,2,3} -----
// MODE 3: hi*hi + hi*lo + lo*hi.  MODE 2: hi*hi + lo*hi.  MODE 1: hi*hi only.
#define GEMM_SMEM (3 * 12288 * 4)

template <int MODE>
__device__ __forceinline__ void mma_mainloop(
    float* sm, const float* __restrict__ Ahi, const float* __restrict__ Alo,
    const float* __restrict__ Bhi, const float* __restrict__ Blo,
    int br16, int bn16, int kc0, int iters, float4 (&acc)[4][8]) {
    const int tid = threadIdx.x;
    const int lane = tid & 31, wid = tid >> 5;
    const int wy = wid >> 1, wx = wid & 1;
    const uint32_t smb = smem_u32(sm);

    auto load_stage = [&](int kc, int s) {
        const uint32_t sb = smb + s * 49152;
#pragma unroll
        for (int j = 0; j < 4; j++) {
            const int cA = tid + j * 256;
            const int mtl = cA >> 6, off = cA & 63;
            const uint32_t so = sb + (uint32_t)(mtl * 256 + off * 4) * 4;
            const size_t go = ((size_t)(br16 + mtl) * KS8 + kc * 2) * 128 + off * 4;
            cpasync16(so, Ahi + go);
            if (MODE >= 2) cpasync16(so + 4096 * 4, Alo + go);
        }
#pragma unroll
        for (int j = 0; j < 2; j++) {
            const int cB = tid + j * 256;
            const int ntl = cB >> 5, off = cB & 31;
            const uint32_t so = sb + (uint32_t)(8192 + ntl * 128 + off * 4) * 4;
            const size_t go = ((size_t)(bn16 + ntl) * KS8 + kc * 2) * 64 + off * 4;
            cpasync16(so, Bhi + go);
            if (MODE >= 3) cpasync16(so + 2048 * 4, Blo + go);
        }
    };

    load_stage(kc0, 0); CP_COMMIT();
    load_stage(kc0 + 1, 1); CP_COMMIT();

#pragma unroll
    for (int i = 0; i < 4; i++)
#pragma unroll
        for (int j = 0; j < 8; j++) acc[i][j] = make_float4(0.f, 0.f, 0.f, 0.f);

    for (int c = 0; c < iters; c++) {
        if (c < iters - 2) { CP_WAIT_1(); } else { CP_WAIT_0(); }
        __syncthreads();
        if (c + 2 < iters) { load_stage(kc0 + c + 2, (c + 2) % 3); CP_COMMIT(); }
        const float* st = sm + (c % 3) * 12288;
#pragma unroll
        for (int ks = 0; ks < 2; ks++) {
            uint4 Ah[4], Al[4];
            uint2 Bh[8], Bl[8];
#pragma unroll
            for (int i = 0; i < 4; i++) {
                const float* p = st + ((wy * 4 + i) * 2 + ks) * 128 + lane * 4;
                Ah[i] = *(const uint4*)p;
                if (MODE >= 2) Al[i] = *(const uint4*)(p + 4096);
            }
#pragma unroll
            for (int j = 0; j < 8; j++) {
                const float* p = st + 8192 + ((wx * 8 + j) * 2 + ks) * 64 + lane * 2;
                Bh[j] = *(const uint2*)p;
                if (MODE >= 3) Bl[j] = *(const uint2*)(p + 2048);
            }
#pragma unroll
            for (int i = 0; i < 4; i++)
#pragma unroll
                for (int j = 0; j < 8; j++) {
                    mma8(acc[i][j], Ah[i], Bh[j]);
                    if (MODE >= 3) mma8(acc[i][j], Ah[i], Bl[j]);
                    if (MODE >= 2) mma8(acc[i][j], Al[i], Bh[j]);
                }
        }
    }
}

// --------- fused prep GEMMs: Wvo = Wv@Wo and G = Wq@Wk^T, split-K x2 --------
__global__ __launch_bounds__(256, 1) void gemm_prep_kernel(
    const float* __restrict__ Ahi, const float* __restrict__ Alo,
    const float* __restrict__ Bhi, const float* __restrict__ Blo,
    float* __restrict__ P) {
    extern __shared__ float sm[];
    const int wsel = blockIdx.z >> 1;
    const int khalf = blockIdx.z & 1;
    const int tid = threadIdx.x;
    const int lane = tid & 31, wid = tid >> 5;
    const int wy = wid >> 1, wx = wid & 1;
    const int g = lane >> 2, t = lane & 3;
    const int m0 = blockIdx.y * 256, n0 = blockIdx.x * 128;

    float4 acc[4][8];
    mma_mainloop<3>(sm, Ahi, Alo, Bhi, Blo,
                    wsel * 64 + blockIdx.y * 16, wsel * 128 + blockIdx.x * 16,
                    khalf * 32, 32, acc);

    float* out = P + (size_t)(wsel * 2 + khalf) * DIM * DIM;
#pragma unroll
    for (int i = 0; i < 4; i++) {
        const int r0 = m0 + wy * 64 + i * 16 + g;
#pragma unroll
        for (int j = 0; j < 8; j++) {
            const int col = n0 + wx * 64 + j * 8 + t * 2;
            *(float2*)(out + (size_t)r0 * DIM + col) =
                make_float2(acc[i][j].x, acc[i][j].y);
            *(float2*)(out + (size_t)(r0 + 8) * DIM + col) =
                make_float2(acc[i][j].z, acc[i][j].w);
        }
    }
}

// --------- sum split-K partials + pack B-format into weight slots ------------
__global__ __launch_bounds__(256) void prep_pack_sum(
    const float* __restrict__ P, float2* __restrict__ WHi, float2* __restrict__ WLo) {
    const int bx = blockIdx.x;
    const int w = bx >> 11;
    const float* p0 = P + (size_t)(w == 0 ? 2 : 0) * DIM * DIM;
    const float* p1 = p0 + (size_t)DIM * DIM;
    float2* dhi = WHi + (size_t)w * WSZF / 2;
    float2* dlo = WLo + (size_t)w * WSZF / 2;
    const int atom = (bx & 2047) * 8 + (threadIdx.x >> 5);
    const int lane = threadIdx.x & 31;
    const int nt = atom >> 7;
    const int ks = atom & 127;
    const int g = lane >> 2, t = lane & 3;
    const size_t i0 = (size_t)(ks * 8 + t) * DIM + nt * 8 + g;
    const size_t i1 = (size_t)(ks * 8 + t + 4) * DIM + nt * 8 + g;
    float x0 = p0[i0] + p1[i0];
    float x1 = p0[i1] + p1[i1];
    float2 h, l;
    h.x = tf32r(x0); l.x = tf32r(x0 - h.x);
    h.y = tf32r(x1); l.y = tf32r(x1 - h.y);
    dhi[(size_t)atom * 32 + lane] = h;
    dlo[(size_t)atom * 32 + lane] = l;
}

// Fused T/U projection. wsel 0 -> T = S@G (3x): packed A-fmt hi + raw.
// wsel 1 -> U = S@Wvo (1x: value path; error budget verified R13/R15).
__global__ __launch_bounds__(256, 1) void gemm_tu_kernel(
    const float* __restrict__ Ahi, const float* __restrict__ Alo,
    const float* __restrict__ Whi, const float* __restrict__ Wlo,
    float* __restrict__ Thi, float* __restrict__ Traw, float* __restrict__ U) {
    extern __shared__ float sm[];
    const int wsel = blockIdx.x & 1;
    const int nxt = blockIdx.x >> 1;
    const int tid = threadIdx.x;
    const int lane = tid & 31, wid = tid >> 5;
    const int wy = wid >> 1, wx = wid & 1;
    const int g = lane >> 2, t = lane & 3;
    const int m0 = blockIdx.y * 256, n0 = nxt * 128;

    if (wsel == 1) {
        float4 acc[4][8];
        mma_mainloop<1>(sm, Ahi, (const float*)0, Whi + WSZF, (const float*)0,
                        blockIdx.y * 16, nxt * 16, 0, 64, acc);
#pragma unroll
        for (int i = 0; i < 4; i++) {
            const int r0 = m0 + wy * 64 + i * 16 + g;
#pragma unroll
            for (int j = 0; j < 8; j++) {
                const int col = n0 + wx * 64 + j * 8 + t * 2;
                *(float2*)(U + (size_t)r0 * DIM + col) =
                    make_float2(acc[i][j].x, acc[i][j].y);
                *(float2*)(U + (size_t)(r0 + 8) * DIM + col) =
                    make_float2(acc[i][j].z, acc[i][j].w);
            }
        }
        return;
    }

    float4 acc[4][8];
    mma_mainloop<3>(sm, Ahi, Alo, Whi, Wlo,
                    blockIdx.y * 16, nxt * 16, 0, 64, acc);

    // raw T write (for exact rescore)
#pragma unroll
    for (int i = 0; i < 4; i++) {
        const int r0 = m0 + wy * 64 + i * 16 + g;
#pragma unroll
        for (int j = 0; j < 8; j++) {
            const int col = n0 + wx * 64 + j * 8 + t * 2;
            *(float2*)(Traw + (size_t)r0 * DIM + col) =
                make_float2(acc[i][j].x, acc[i][j].y);
            *(float2*)(Traw + (size_t)(r0 + 8) * DIM + col) =
                make_float2(acc[i][j].z, acc[i][j].w);
        }
    }

    __syncthreads();  // pipeline smem free
#pragma unroll
    for (int i = 0; i < 4; i++) {
        const int r0 = wy * 64 + i * 16 + g;
#pragma unroll
        for (int j = 0; j < 8; j++) {
            const int col = wx * 64 + j * 8 + t * 2;
            *(float2*)&sm[r0 * 132 + col] = make_float2(acc[i][j].x, acc[i][j].y);
            *(float2*)&sm[(r0 + 8) * 132 + col] = make_float2(acc[i][j].z, acc[i][j].w);
        }
    }
    __syncthreads();

    // pack Thi (A-format hi only; scores pass is 1x)
    for (int a = wid; a < 256; a += 8) {
        const int amt = a >> 4, aks = a & 15;
        const float* bp = sm + (amt * 16 + g) * 132 + aks * 8 + t;
        float4 h;
        h.x = tf32r(bp[0]);
        h.y = tf32r(bp[8 * 132]);
        h.z = tf32r(bp[4]);
        h.w = tf32r(bp[8 * 132 + 4]);
        const size_t atom = (size_t)(blockIdx.y * 16 + amt) * KS8 + (nxt * 16 + aks);
        ((float4*)Thi)[atom * 32 + lane] = h;
    }
}

// ---------------- supertile 1x TF32 causal scores + candidate top-8 ---------
#define SSC_SMEM ((3 * 12288 + 128 * 72 + 256 * 8 + 256 * 8 + 128) * 4)

__global__ __launch_bounds__(256, 1) void scores_super_kernel(
    const float* __restrict__ Thi, const float* __restrict__ Shi,
    const float* __restrict__ w,
    float* __restrict__ pval, int* __restrict__ pidx) {
    extern __shared__ float sm[];
    float* sc = sm + 36864;
    float* tval = sm + 46080;
    int* tidx = (int*)(sm + 48128);
    float* wsc = sm + 50176;

    const int tid = threadIdx.x;
    const int lane = tid & 31, wid = tid >> 5;
    const int wy = wid >> 1, wx = wid & 1;
    const int g = lane >> 2, t = lane & 3;
    const int b = blockIdx.y;
    const int bidx = blockIdx.x;

    int sq = (int)((sqrtf(4.0f * (float)bidx + 1.0f) - 1.0f) * 0.5f);
    while ((sq + 1) * (sq + 2) <= bidx) sq++;
    while (sq * (sq + 1) > bidx) sq--;
    const int kt = bidx - sq * (sq + 1);
    const int q0 = sq * 256, k0 = kt * 128;

    for (int i = tid; i < 256 * TOPK; i += 256) {
        tval[i] = -INFINITY;
        tidx[i] = 0;
    }
    if (tid < 128) wsc[tid] = w[b * NSEQ + k0 + tid];

    float4 acc[4][8];
    mma_mainloop<1>(sm, Thi, (const float*)0, Shi, (const float*)0,
                    b * 256 + sq * 16, b * 512 + kt * 16, 0, 64, acc);

#pragma unroll
    for (int rh = 0; rh < 2; rh++) {
#pragma unroll
        for (int h = 0; h < 2; h++) {
            if ((wy >> 1) == rh && wx == h) {
#pragma unroll
                for (int i = 0; i < 4; i++) {
                    const int rl = wy * 64 + i * 16 + g;
                    const int srow = rl - rh * 128;
#pragma unroll
                    for (int j = 0; j < 8; j++) {
                        const int col = j * 8 + t * 2;
                        const int lc = h * 64 + col;
                        const int gc = k0 + lc;
                        const int gr0 = q0 + rl, gr1 = gr0 + 8;
                        const float w0 = wsc[lc], w1 = wsc[lc + 1];
                        float v0 = acc[i][j].x * 0.03125f + w0;
                        float v1 = acc[i][j].y * 0.03125f + w1;
                        float v2 = acc[i][j].z * 0.03125f + w0;
                        float v3 = acc[i][j].w * 0.03125f + w1;
                        if (gc + 0 > gr0) v0 = -INFINITY;
                        if (gc + 1 > gr0) v1 = -INFINITY;
                        if (gc + 0 > gr1) v2 = -INFINITY;
                        if (gc + 1 > gr1) v3 = -INFINITY;
                        *(float2*)&sc[srow * 72 + col] = make_float2(v0, v1);
                        *(float2*)&sc[(srow + 8) * 72 + col] = make_float2(v2, v3);
                    }
                }
            }
            __syncthreads();
            if (tid < 128) {
                const int row = rh * 128 + tid;
                float tv[TOPK]; int ti[TOPK];
#pragma unroll
                for (int j = 0; j < TOPK; j++) { tv[j] = tval[row * 8 + j]; ti[j] = tidx[row * 8 + j]; }
                float vmin = tv[0]; int mpos = 0;
#pragma unroll
                for (int j = 1; j < TOPK; j++) if (tv[j] < vmin) { vmin = tv[j]; mpos = j; }
                const int cbase = k0 + h * 64;
                for (int cc = 0; cc < 64; cc++) {
                    const float vv = sc[tid * 72 + cc];
                    if (vv > vmin) {
                        tv[mpos] = vv; ti[mpos] = cbase + cc;
                        vmin = tv[0]; mpos = 0;
#pragma unroll
                        for (int j = 1; j < TOPK; j++) if (tv[j] < vmin) { vmin = tv[j]; mpos = j; }
                    }
                }
#pragma unroll
                for (int j = 0; j < TOPK; j++) { tval[row * 8 + j] = tv[j]; tidx[row * 8 + j] = ti[j]; }
            }
            __syncthreads();
        }
    }

    const size_t base = (((size_t)b * NSB + bidx) * 256 + tid) * TOPK;
#pragma unroll
    for (int j = 0; j < TOPK; j++) {
        pval[base + j] = tval[tid * 8 + j];
        pidx[base + j] = tidx[tid * 8 + j];
    }
}

// ------- merge top-16 (1x) -> exact rescore -> top-8 softmax -> gather -------
__global__ __launch_bounds__(128) void merge_rescore_gather(
    const float* __restrict__ pv, const int* __restrict__ pi,
    const float* __restrict__ Traw, const float* __restrict__ S,
    const float* __restrict__ w, const float* __restrict__ U,
    const float* __restrict__ bvo, float* __restrict__ out) {
    const int row = blockIdx.x;
    const int b = row >> 12, rr = row & 4095;
    const int qt = rr >> 7;
    const int sq = qt >> 1;
    const int rib = rr - sq * 256;
    const size_t sbase = ((size_t)b * NSB + (size_t)sq * (sq + 1)) * 256 + rib;

    __shared__ float trow[DIM];
    __shared__ float cval[NCAND];
    __shared__ int   cidx[NCAND];
    __shared__ float cex[NCAND];
    __shared__ float ps[TOPK];
    __shared__ int   ids[TOPK];

    const int tid = threadIdx.x;
    const int lane = tid & 31, wid = tid >> 5;

    // load T row to smem
    {
        const float4* tr = (const float4*)(Traw + (size_t)row * DIM);
        ((float4*)trow)[tid] = tr[tid];
        ((float4*)trow)[tid + 128] = tr[tid + 128];
    }

    // warp 0: merge partial lists to top-NCAND by 1x value
    if (tid < 32) {
        float v[TOPK]; int id8[TOPK];
        if (lane <= qt) {
            const size_t base = (sbase + (size_t)lane * 256) * TOPK;
#pragma unroll
            for (int j = 0; j < TOPK; j++) { v[j] = pv[base + j]; id8[j] = pi[base + j]; }
        } else {
#pragma unroll
            for (int j = 0; j < TOPK; j++) { v[j] = -INFINITY; id8[j] = 0; }
        }
#pragma unroll
        for (int r = 0; r < NCAND; r++) {
            float lm = v[0]; int ls = 0;
#pragma unroll
            for (int j = 1; j < TOPK; j++) if (v[j] > lm) { lm = v[j]; ls = j; }
            float m = lm; int who = lane;
#pragma unroll
            for (int o = 16; o; o >>= 1) {
                float om = __shfl_xor_sync(0xffffffffu, m, o);
                int ow = __shfl_xor_sync(0xffffffffu, who, o);
                if (om > m || (om == m && ow < who)) { m = om; who = ow; }
            }
            int widx = 0;
#pragma unroll
            for (int j = 0; j < TOPK; j++) if (j == ls) widx = id8[j];
            const int gidx = __shfl_sync(0xffffffffu, widx, who);
            if (lane == 0) { cval[r] = m; cidx[r] = gidx; }
            if (lane == who) {
#pragma unroll
                for (int j = 0; j < TOPK; j++) if (j == ls) v[j] = -INFINITY;
            }
        }
    }
    __syncthreads();

    // rescore candidates exactly: each warp handles NCAND/4 candidates
    for (int c = wid; c < NCAND; c += 4) {
        const float v1 = cval[c];
        const int idx = cidx[c];
        float acc = 0.f;
        if (v1 != -INFINITY) {
            const float4* srow = (const float4*)(S + ((size_t)b * NSEQ + idx) * DIM);
            const float4* tr4 = (const float4*)trow;
            for (int i = lane; i < DIM / 4; i += 32) {
                float4 s = srow[i], tt = tr4[i];
                acc += tt.x * s.x + tt.y * s.y + tt.z * s.z + tt.w * s.w;
            }
        }
#pragma unroll
        for (int o = 16; o; o >>= 1) acc += __shfl_xor_sync(0xffffffffu, acc, o);
        if (lane == 0)
            cex[c] = (v1 != -INFINITY)
                         ? acc * 0.03125f + w[b * NSEQ + idx]
                         : -INFINITY;
    }
    __syncthreads();

    // thread 0: exact top-8 of NCAND + softmax
    if (tid == 0) {
        float ev[NCAND]; int ei[NCAND];
#pragma unroll
        for (int j = 0; j < NCAND; j++) { ev[j] = cex[j]; ei[j] = cidx[j]; }
        float tv[TOPK]; int ti[TOPK];
#pragma unroll
        for (int r = 0; r < TOPK; r++) {
            int m = 0; float best = ev[0];
#pragma unroll
            for (int j = 1; j < NCAND; j++) if (ev[j] > best) { best = ev[j]; m = j; }
            tv[r] = best; ti[r] = ei[m]; ev[m] = -INFINITY;
        }
        float mx = tv[0];
#pragma unroll
        for (int j = 1; j < TOPK; j++) mx = fmaxf(mx, tv[j]);
        float e[TOPK]; float ssum = 0.f;
#pragma unroll
        for (int j = 0; j < TOPK; j++) { e[j] = expf(tv[j] - mx); ssum += e[j]; }
        const float inv = 1.f / ssum;
#pragma unroll
        for (int j = 0; j < TOPK; j++) { ps[j] = e[j] * inv; ids[j] = ti[j]; }
    }
    __syncthreads();

    const float* ub = U + (size_t)b * NSEQ * DIM;
    const int c = tid * 8;
    float4 a0 = *(const float4*)(bvo + c);
    float4 a1 = *(const float4*)(bvo + c + 4);
#pragma unroll
    for (int j = 0; j < TOPK; j++) {
        const float4* vr = (const float4*)(ub + (size_t)ids[j] * DIM + c);
        const float pj = ps[j];
        float4 v0 = vr[0], v1 = vr[1];
        a0.x += pj * v0.x; a0.y += pj * v0.y; a0.z += pj * v0.z; a0.w += pj * v0.w;
        a1.x += pj * v1.x; a1.y += pj * v1.y; a1.z += pj * v1.z; a1.w += pj * v1.w;
    }
    float4* orow = (float4*)(out + (size_t)row * DIM + c);
    orow[0] = a0; orow[1] = a1;
}

// ---------------- launch -----------------------------------------------------
extern "C" void kernel_launch(void* const* d_in, const int* in_sizes, int n_in,
                              void* d_out, int out_size) {
    const float* S  = (const float*)d_in[0];
    const float* Wq = (const float*)d_in[1];
    const float* bq = (const float*)d_in[2];
    const float* Wk = (const float*)d_in[3];
    const float* bk = (const float*)d_in[4];  // row-const in softmax; drops out
    const float* Wv = (const float*)d_in[5];
    const float* bv = (const float*)d_in[6];
    const float* Wo = (const float*)d_in[7];
    const float* bo = (const float*)d_in[8];
    float* out = (float*)d_out;
    (void)bk;

    float *up, *trp, *pvp, *ahip, *alop;
    float *qhip, *khip, *klop, *wthip, *wtlop;
    float *bvop, *yp, *wp;
    int *pip;
    cudaGetSymbolAddress((void**)&up, g_u);
    cudaGetSymbolAddress((void**)&trp, g_traw);
    cudaGetSymbolAddress((void**)&pvp, g_pval);
    cudaGetSymbolAddress((void**)&pip, g_pidx);
    cudaGetSymbolAddress((void**)&ahip, g_ahi);
    cudaGetSymbolAddress((void**)&alop, g_alo);
    cudaGetSymbolAddress((void**)&qhip, g_qhi);
    cudaGetSymbolAddress((void**)&khip, g_khi);
    cudaGetSymbolAddress((void**)&klop, g_klo);
    cudaGetSymbolAddress((void**)&wthip, g_wthi);
    cudaGetSymbolAddress((void**)&wtlop, g_wtlo);
    cudaGetSymbolAddress((void**)&bvop, g_bvo);
    cudaGetSymbolAddress((void**)&yp, g_y);
    cudaGetSymbolAddress((void**)&wp, g_w);

    cudaFuncSetAttribute(gemm_prep_kernel,
                         cudaFuncAttributeMaxDynamicSharedMemorySize, GEMM_SMEM);
    cudaFuncSetAttribute(gemm_tu_kernel,
                         cudaFuncAttributeMaxDynamicSharedMemorySize, GEMM_SMEM);
    cudaFuncSetAttribute(scores_super_kernel,
                         cudaFuncAttributeMaxDynamicSharedMemorySize, SSC_SMEM);

    const int WPACK_GRID = (DIM / 8) * KS8 / 8;   // 2048
    const int APACK_1K = (DIM / 16) * KS8 / 8;    // 1024

    // operand packs for prep: A buffer = [Wv | Wq], B buffer = [Wo | Wk]
    split_pack_a<<<APACK_1K, 256>>>(Wv, (float4*)ahip, (float4*)alop);
    split_pack_a<<<APACK_1K, 256>>>(Wq,
        (float4*)ahip + (size_t)8192 * 32, (float4*)alop + (size_t)8192 * 32);
    split_pack_w<<<WPACK_GRID, 256>>>(Wo, (float2*)khip, (float2*)klop);
    split_pack_kb<<<WPACK_GRID, 256>>>(Wk,
        (float2*)khip + (size_t)16384 * 32, (float2*)klop + (size_t)16384 * 32);

    // bias folds
    bvo_kernel<<<DIM / 128, 128>>>(bv, Wo, bo, bvop);
    ydot_kernel<<<DIM / 8, 256>>>(Wk, bq, yp);
    wdot_kernel<<<MROWS / 8, 256>>>(S, yp, wp);

    // fused prep GEMMs (split-K x2) + partial-sum pack
    gemm_prep_kernel<<<dim3(8, 4, 4), 256, GEMM_SMEM>>>(ahip, alop, khip, klop, up);
    prep_pack_sum<<<4096, 256>>>(up, (float2*)wthip, (float2*)wtlop);

    // fused S pack: A-fmt hi/lo + B-fmt hi
    split_pack_s<<<(MROWS / 16) * KS8 / 8, 256>>>(
        S, (float4*)ahip, (float4*)alop, (float2*)khip);

    // fused: T = S@G (3x, Thi packed + raw), U = S@Wvo (1x, raw)
    gemm_tu_kernel<<<dim3(16, MROWS / 256), 256, GEMM_SMEM>>>(
        ahip, alop, wthip, wtlop, qhip, trp, up);

    // pass 1: 1x scores -> per-tile candidate top-8
    scores_super_kernel<<<dim3(NSB, BSZ), 256, SSC_SMEM>>>(
        qhip, khip, wp, pvp, pip);
    // pass 2: merge top-16, exact rescore, softmax, gather
    merge_rescore_gather<<<MROWS, 128>>>(pvp, pip, trp, S, wp, up, bvop, out);
}